// round 11
// baseline (speedup 1.0000x reference)
#include <cuda_runtime.h>
#include <math.h>
#include <stdint.h>

// ---------------- problem constants ----------------
constexpr int SEQ  = 4096;
constexpr int DM   = 1024;
constexpr int ODIM = 1024;
constexpr int KW   = 256;
constexpr int STR  = 16;
constexpr int NH   = 16;
constexpr int DH   = 64;
constexpr int NWIN = (SEQ - KW) / STR;   // 240
constexpr int ROWS = NWIN * KW;          // 61440

typedef unsigned long long ull;

// packed fp32x2 helpers
#define PACK2(o, lo, hi)   asm("mov.b64 %0, {%1,%2};" : "=l"(o) : "f"(lo), "f"(hi))
#define UNPACK2(lo, hi, i) asm("mov.b64 {%0,%1}, %2;" : "=f"(lo), "=f"(hi) : "l"(i))
#define FMA2(d, a, b, c)   asm("fma.rn.f32x2 %0, %1, %2, %3;" : "=l"(d) : "l"(a), "l"(b), "l"(c))
#define MUL2(d, a, b)      asm("mul.rn.f32x2 %0, %1, %2;" : "=l"(d) : "l"(a), "l"(b))

__device__ __forceinline__ uint32_t smaddr(const void* p) {
    return (uint32_t)__cvta_generic_to_shared(p);
}

#define CP_ASYNC16(sm_u32, gptr) \
    asm volatile("cp.async.cg.shared.global [%0], [%1], 16;" :: "r"(sm_u32), "l"(gptr))
#define CP_COMMIT() asm volatile("cp.async.commit_group;")
#define CP_WAIT0()  asm volatile("cp.async.wait_group 0;")
#define CP_WAIT1()  asm volatile("cp.async.wait_group 1;")

#define LDSM4(r0, r1, r2, r3, addr) \
    asm volatile("ldmatrix.sync.aligned.m8n8.x4.shared.b16 {%0,%1,%2,%3}, [%4];" \
        : "=r"(r0), "=r"(r1), "=r"(r2), "=r"(r3) : "r"(addr))

#define MMA_TF32(c, a, b) \
    asm volatile("mma.sync.aligned.m16n8k8.row.col.f32.tf32.tf32.f32 " \
        "{%0,%1,%2,%3},{%4,%5,%6,%7},{%8,%9},{%0,%1,%2,%3};" \
        : "+f"((c)[0]), "+f"((c)[1]), "+f"((c)[2]), "+f"((c)[3]) \
        : "r"((a)[0]), "r"((a)[1]), "r"((a)[2]), "r"((a)[3]), "r"((b)[0]), "r"((b)[1]))

// release/acquire flag ops (L2-scope ordering; no CCTL.IVALL)
__device__ __forceinline__ void flag_release(unsigned* f) {
    unsigned old;
    asm volatile("atom.release.gpu.global.add.u32 %0, [%1], 1;" : "=r"(old) : "l"(f) : "memory");
}
__device__ __forceinline__ unsigned flag_acquire(unsigned* f) {
    unsigned v;
    asm volatile("ld.acquire.gpu.global.u32 %0, [%1];" : "=r"(v) : "l"(f) : "memory");
    return v;
}

// ---------------- scratch ----------------
__device__ float g_qkv1[SEQ * 3 * DM];
__device__ float g_attn1[ROWS * DM];
__device__ float g_x[ROWS * ODIM];
__device__ float g_q2[ROWS * ODIM];
__device__ float g_kv[2 * KW * 2 * ODIM];   // double-buffered by step parity
__device__ float g_st[2 * KW * ODIM];       // double-buffered by step parity
__device__ float g_wt[DM * DM];
__device__ float g_wt2[DM * DM];
__device__ float g_wcomb[DM * DM];
__device__ float g_bcomb[DM];
__device__ float g_wkv[2 * ODIM * DM];
__device__ float g_bkv[2 * ODIM];
__device__ float g_zb[DM];

// persistent-kernel sync state (monotonic; replay-safe)
__device__ unsigned g_bar_arrive  = 0;
__device__ unsigned g_bar_release = 0;
__device__ unsigned g_flagA[32];            // per kv column-stripe: +4 per step
__device__ unsigned g_flagBQ[128];          // per (qt,h) st sub-block: +1 per step, [qt*16+h]

// ================= TF32 tensor-core GEMM, 128x128 tiles, 3-stage cp.async =========
constexpr int TF_BK = 32;
constexpr int TF_LD = TF_BK + 4;                       // 36 floats
constexpr int TF_BUF = (128 + 128) * TF_LD;            // floats per stage
constexpr int TF_SMEM = 3 * TF_BUF * (int)sizeof(float);  // 110592 B

template<bool RELU>
__global__ __launch_bounds__(256, 2)
void gemm_tf32(const float* __restrict__ A, const float* __restrict__ W,
               const float* __restrict__ bias, float* __restrict__ C,
               int M, int N, int K)
{
    extern __shared__ float smem[];
    const int tid    = threadIdx.x;
    const int lane   = tid & 31;
    const int warp   = tid >> 5;
    const int warp_m = (warp & 1) * 64;
    const int warp_n = (warp >> 1) * 32;
    const int bm     = blockIdx.y * 128;
    const int bn     = blockIdx.x * 128;

    const int ar = (lane & 7) + ((lane >> 3) & 1) * 8;
    const int ac = (lane >> 4) * 4;
    const int br = (lane & 7) + (lane >> 4) * 8;
    const int bc = ((lane >> 3) & 1) * 4;

    float c[4][4][4];
    #pragma unroll
    for (int i = 0; i < 4; i++)
        #pragma unroll
        for (int j = 0; j < 4; j++)
            #pragma unroll
            for (int r = 0; r < 4; r++) c[i][j][r] = 0.f;

    const int lr = tid >> 3;
    const int lc = tid & 7;

    auto issue = [&](int t) {
        const size_t ko = (size_t)t * TF_BK + lc * 4;
        float* As = smem + (t % 3) * TF_BUF;
        float* Bs = As + 128 * TF_LD;
        #pragma unroll
        for (int i = 0; i < 4; i++) {
            int r = lr + i * 32;
            CP_ASYNC16(smaddr(&As[r * TF_LD + lc * 4]), &A[(size_t)(bm + r) * K + ko]);
            CP_ASYNC16(smaddr(&Bs[r * TF_LD + lc * 4]), &W[(size_t)(bn + r) * K + ko]);
        }
        CP_COMMIT();
    };

    const int nk = K / TF_BK;
    issue(0);
    if (nk > 1) issue(1);

    for (int t = 0; t < nk; t++) {
        if (t == nk - 1) { CP_WAIT0(); } else { CP_WAIT1(); }
        __syncthreads();
        if (t + 2 < nk) issue(t + 2);

        const float* bufp = smem + (t % 3) * TF_BUF;
        const uint32_t a_base = smaddr(bufp + (warp_m + ar) * TF_LD + ac);
        const uint32_t b_base = smaddr(bufp + 128 * TF_LD + (warp_n + br) * TF_LD + bc);

        #pragma unroll
        for (int ks = 0; ks < 4; ks++) {
            uint32_t a[4][4], b[4][2];
            #pragma unroll
            for (int mt = 0; mt < 4; mt++)
                LDSM4(a[mt][0], a[mt][1], a[mt][2], a[mt][3],
                      a_base + (uint32_t)((mt * 16 * TF_LD + ks * 8) * 4));
            #pragma unroll
            for (int np = 0; np < 2; np++)
                LDSM4(b[2*np][0], b[2*np][1], b[2*np+1][0], b[2*np+1][1],
                      b_base + (uint32_t)((np * 16 * TF_LD + ks * 8) * 4));
            #pragma unroll
            for (int mt = 0; mt < 4; mt++)
                #pragma unroll
                for (int nt = 0; nt < 4; nt++)
                    MMA_TF32(c[mt][nt], a[mt], b[nt]);
        }
    }

    const int g  = lane >> 2;
    const int tg = lane & 3;
    #pragma unroll
    for (int mt = 0; mt < 4; mt++) {
        int row0 = bm + warp_m + mt * 16 + g;
        #pragma unroll
        for (int nt = 0; nt < 4; nt++) {
            int col = bn + warp_n + nt * 8 + tg * 2;
            float2 bb = *(const float2*)&bias[col];
            float2 o0, o1;
            o0.x = c[mt][nt][0] + bb.x;  o0.y = c[mt][nt][1] + bb.y;
            o1.x = c[mt][nt][2] + bb.x;  o1.y = c[mt][nt][3] + bb.y;
            if (RELU) {
                o0.x = fmaxf(o0.x, 0.f); o0.y = fmaxf(o0.y, 0.f);
                o1.x = fmaxf(o1.x, 0.f); o1.y = fmaxf(o1.y, 0.f);
            }
            *(float2*)&C[(size_t)row0 * N + col]       = o0;
            *(float2*)&C[(size_t)(row0 + 8) * N + col] = o1;
        }
    }
}

// ================= exact FFMA2 SGEMM (final projection only) =================
template<int BM, int BN, int BK, int TM, int TN>
__global__ __launch_bounds__((BM/TM)*(BN/TN))
void gemm_bias(const float* __restrict__ A, const float* __restrict__ W,
               const float* __restrict__ bias, float* __restrict__ C,
               int M, int N, int K)
{
    constexpr int THREADS = (BM/TM)*(BN/TN);
    __shared__ __align__(16) float As[BK][BM];
    __shared__ __align__(16) float Bs[BK][BN];
    const int tid  = threadIdx.x;
    const int bm   = blockIdx.y * BM;
    const int bn   = blockIdx.x * BN;
    const int tcol = tid % (BN/TN);
    const int trow = tid / (BN/TN);

    ull acc2[TM][TN/2];
    #pragma unroll
    for (int i = 0; i < TM; i++)
        #pragma unroll
        for (int j = 0; j < TN/2; j++) acc2[i][j] = 0ull;

    constexpr int AF4 = BM * (BK/4);
    constexpr int BF4 = BN * (BK/4);

    for (int k0 = 0; k0 < K; k0 += BK) {
        #pragma unroll
        for (int i = tid; i < AF4; i += THREADS) {
            int r  = i / (BK/4);
            int c4 = i % (BK/4);
            float4 v = *(const float4*)&A[(size_t)(bm + r) * K + k0 + c4*4];
            As[c4*4+0][r] = v.x; As[c4*4+1][r] = v.y;
            As[c4*4+2][r] = v.z; As[c4*4+3][r] = v.w;
        }
        #pragma unroll
        for (int i = tid; i < BF4; i += THREADS) {
            int r  = i / (BK/4);
            int c4 = i % (BK/4);
            float4 v = *(const float4*)&W[(size_t)(bn + r) * K + k0 + c4*4];
            Bs[c4*4+0][r] = v.x; Bs[c4*4+1][r] = v.y;
            Bs[c4*4+2][r] = v.z; Bs[c4*4+3][r] = v.w;
        }
        __syncthreads();

        #pragma unroll
        for (int k = 0; k < BK; k++) {
            float ra[TM];
            #pragma unroll
            for (int i = 0; i < TM; i += 4) {
                float4 v = *(const float4*)&As[k][trow*TM + i];
                ra[i] = v.x; ra[i+1] = v.y; ra[i+2] = v.z; ra[i+3] = v.w;
            }
            ull ras[TM];
            #pragma unroll
            for (int i = 0; i < TM; i++) PACK2(ras[i], ra[i], ra[i]);

            ull rb2[TN/2];
            #pragma unroll
            for (int j4 = 0; j4 < TN/4; j4++) {
                ulonglong2 v = *(const ulonglong2*)&Bs[k][tcol*TN + j4*4];
                rb2[2*j4]   = v.x;
                rb2[2*j4+1] = v.y;
            }
            #pragma unroll
            for (int i = 0; i < TM; i++)
                #pragma unroll
                for (int j = 0; j < TN/2; j++)
                    FMA2(acc2[i][j], ras[i], rb2[j], acc2[i][j]);
        }
        __syncthreads();
    }

    #pragma unroll
    for (int i = 0; i < TM; i++) {
        size_t row = (size_t)(bm + trow*TM + i);
        float oc[TN];
        #pragma unroll
        for (int j = 0; j < TN/2; j++) UNPACK2(oc[2*j], oc[2*j+1], acc2[i][j]);
        #pragma unroll
        for (int j = 0; j < TN; j += 4) {
            int col = bn + tcol*TN + j;
            float4 b4 = *(const float4*)&bias[col];
            float4 o;
            o.x = oc[j+0] + b4.x;
            o.y = oc[j+1] + b4.y;
            o.z = oc[j+2] + b4.z;
            o.w = oc[j+3] + b4.w;
            *(float4*)&C[row * N + col] = o;
        }
    }
}

// ---------------- prep: transposes + zero + bias folds in ONE launch ----------------
__global__ __launch_bounds__(256)
void prep_kernel(const float* __restrict__ w_out1, const float* __restrict__ w_out2,
                 const float* __restrict__ w_lin,  const float* __restrict__ b_out1,
                 const float* __restrict__ b_lin,  const float* __restrict__ wkv2,
                 const float* __restrict__ b_out2, const float* __restrict__ bkv2,
                 float* __restrict__ wt, float* __restrict__ wt2, float* __restrict__ zb,
                 float* __restrict__ bcomb, float* __restrict__ bkv)
{
    const int b   = blockIdx.x;
    const int tid = threadIdx.x;

    if (b < 2048) {
        const float* in = (b < 1024) ? w_out1 : w_out2;
        float* out      = (b < 1024) ? wt : wt2;
        const int bb = b & 1023;
        const int bx = bb & 31, by = bb >> 5;
        __shared__ float tile[32][33];
        const int tx = tid & 31, ty = tid >> 5;
        #pragma unroll
        for (int j = 0; j < 32; j += 8)
            tile[ty + j][tx] = in[(size_t)(by*32 + ty + j) * DM + bx*32 + tx];
        __syncthreads();
        #pragma unroll
        for (int j = 0; j < 32; j += 8)
            out[(size_t)(bx*32 + ty + j) * DM + by*32 + tx] = tile[tx][ty + j];
    } else if (b < 2052) {
        zb[(b - 2048) * 256 + tid] = 0.f;
    } else {
        int bb = b - 2052;
        const float *W, *b1, *b2;
        float* out;
        if (bb < 128) { W = w_lin; b1 = b_out1; b2 = b_lin; out = bcomb; }
        else          { bb -= 128; W = wkv2; b1 = b_out2; b2 = bkv2; out = bkv; }
        const int n = bb * 8 + (tid >> 5);
        const int lane = tid & 31;
        float s = 0.f;
        for (int j = lane; j < DM; j += 32) s = fmaf(W[(size_t)n * DM + j], b1[j], s);
        #pragma unroll
        for (int o = 16; o; o >>= 1) s += __shfl_xor_sync(0xffffffffu, s, o);
        if (lane == 0) out[n] = s + b2[n];
    }
}

// ---------------- flash-style attention (stage 2 bulk; packed f32x2) ----------------
constexpr int ATTN_SMEM = (2 * KW * DH + 2 * 256) * (int)sizeof(float); // 133120 B

__global__ __launch_bounds__(256)
void attn_kernel(const float* __restrict__ qbase, long long q_ws, int q_rs,
                 const float* __restrict__ kbase, long long k_ws, int k_rs,
                 const float* __restrict__ vbase, long long v_ws, int v_rs,
                 float* __restrict__ obase,       long long o_ws, int o_rs,
                 float scale)
{
    extern __shared__ float sm[];
    float* Ks   = sm;
    float* Vs   = sm + KW * DH;
    float* mbuf = sm + 2 * KW * DH;
    float* lbuf = mbuf + 256;

    const int h  = blockIdx.x;
    const int qt = blockIdx.y;
    const int w  = blockIdx.z;
    const int tid = threadIdx.x;

    const float* Kp = kbase + (size_t)w * k_ws + h * DH;
    const float* Vp = vbase + (size_t)w * v_ws + h * DH;

    for (int idx = tid; idx < KW * (DH/4); idx += 256) {
        int r  = idx >> 4;
        int c4 = idx & 15;
        CP_ASYNC16(smaddr(Ks + r * DH + c4*4), Kp + (size_t)r * k_rs + c4*4);
        CP_ASYNC16(smaddr(Vs + r * DH + c4*4), Vp + (size_t)r * v_rs + c4*4);
    }
    CP_COMMIT();

    const int q = tid & 63;
    const int c = tid >> 6;
    const int qrow = qt * 64 + q;

    const float* Qr = qbase + (size_t)w * q_ws + (size_t)qrow * q_rs + h * DH;
    ull qp[DH/2];
    #pragma unroll
    for (int d4 = 0; d4 < 16; d4++) {
        ulonglong2 v = *(const ulonglong2*)(Qr + d4*4);
        qp[2*d4]   = v.x;
        qp[2*d4+1] = v.y;
    }

    CP_WAIT0();
    __syncthreads();

    float m = -1e30f, l = 0.f;
    ull accp[DH/2];
    #pragma unroll
    for (int t = 0; t < DH/2; t++) accp[t] = 0ull;

    const int k0 = c * 64;
    for (int kk = 0; kk < 64; kk++) {
        const float* Krow = Ks + (k0 + kk) * DH;
        ull s0 = 0ull, s1 = 0ull, s2 = 0ull, s3 = 0ull;
        #pragma unroll
        for (int d4 = 0; d4 < 16; d4 += 2) {
            ulonglong2 a = *(const ulonglong2*)(Krow + d4*4);
            ulonglong2 b = *(const ulonglong2*)(Krow + d4*4 + 4);
            FMA2(s0, qp[2*d4+0], a.x, s0);
            FMA2(s1, qp[2*d4+1], a.y, s1);
            FMA2(s2, qp[2*d4+2], b.x, s2);
            FMA2(s3, qp[2*d4+3], b.y, s3);
        }
        float a0,a1,b0,b1,c0,c1,d0,d1;
        UNPACK2(a0,a1,s0); UNPACK2(b0,b1,s1); UNPACK2(c0,c1,s2); UNPACK2(d0,d1,s3);
        float s = ((a0+a1)+(b0+b1)) + ((c0+c1)+(d0+d1));
        s *= scale;

        if (s > m) {
            float corr = __expf(m - s);
            l *= corr;
            ull cp; PACK2(cp, corr, corr);
            #pragma unroll
            for (int t = 0; t < DH/2; t++) MUL2(accp[t], accp[t], cp);
            m = s;
        }
        float p = __expf(s - m);
        l += p;
        ull pp; PACK2(pp, p, p);
        const float* Vrow = Vs + (k0 + kk) * DH;
        #pragma unroll
        for (int d4 = 0; d4 < 16; d4 += 2) {
            ulonglong2 a = *(const ulonglong2*)(Vrow + d4*4);
            ulonglong2 b = *(const ulonglong2*)(Vrow + d4*4 + 4);
            FMA2(accp[2*d4+0], pp, a.x, accp[2*d4+0]);
            FMA2(accp[2*d4+1], pp, a.y, accp[2*d4+1]);
            FMA2(accp[2*d4+2], pp, b.x, accp[2*d4+2]);
            FMA2(accp[2*d4+3], pp, b.y, accp[2*d4+3]);
        }
    }
    __syncthreads();

    float* accbuf = Ks;
    mbuf[tid] = m;
    lbuf[tid] = l;
    #pragma unroll
    for (int d4 = 0; d4 < 16; d4++)
        *(ulonglong2*)(accbuf + (size_t)tid * DH + d4*4) =
            make_ulonglong2(accp[2*d4], accp[2*d4+1]);
    __syncthreads();

    float m0 = mbuf[q], m1 = mbuf[64+q], m2 = mbuf[128+q], m3 = mbuf[192+q];
    float mg = fmaxf(fmaxf(m0, m1), fmaxf(m2, m3));
    float e0 = __expf(m0 - mg), e1 = __expf(m1 - mg);
    float e2 = __expf(m2 - mg), e3 = __expf(m3 - mg);
    float lg = lbuf[q]*e0 + lbuf[64+q]*e1 + lbuf[128+q]*e2 + lbuf[192+q]*e3;
    float inv = 1.f / lg;

    float* Or = obase + (size_t)w * o_ws + (size_t)qrow * o_rs + h * DH;
    #pragma unroll
    for (int d = c*16; d < c*16 + 16; d++) {
        float o = accbuf[(size_t)(0*64+q)*DH + d] * e0
                + accbuf[(size_t)(1*64+q)*DH + d] * e1
                + accbuf[(size_t)(2*64+q)*DH + d] * e2
                + accbuf[(size_t)(3*64+q)*DH + d] * e3;
        Or[d] = o * inv;
    }
}

// ================= persistent recurrence kernel (streamed flag-sync) =================
constexpr int REC_NB   = 128;
constexpr int RA_BK  = 128;
constexpr int RA_LD  = RA_BK + 4;                   // 132 floats
constexpr int RA_BUF = (64 + 64) * RA_LD;           // 16896 floats per stage
constexpr int REC_SMEM = 3 * RA_BUF * (int)sizeof(float);   // 202752 B

__device__ __forceinline__ void grid_bar(unsigned base, unsigned bar_id)
{
    __syncthreads();
    if (threadIdx.x == 0) {
        __threadfence();
        unsigned a = atomicAdd(&g_bar_arrive, 1u);
        if ((a & (REC_NB - 1u)) == (REC_NB - 1u)) {
            atomicAdd(&g_bar_release, 1u);
        } else {
            while (*(volatile unsigned*)&g_bar_release - base < bar_id) { }
        }
        __threadfence();
    }
    __syncthreads();
}

__global__ __launch_bounds__(256)
void recurrence_kernel(const float* __restrict__ x,
                       const float* __restrict__ q2,
                       const float* __restrict__ wkv2, const float* __restrict__ bkv2,
                       const float* __restrict__ wkvF, const float* __restrict__ bkvF,
                       float* __restrict__ kv, float* __restrict__ st)
{
    extern __shared__ float sm[];
    const int tid = threadIdx.x;
    const int bid = blockIdx.x;

    __shared__ unsigned s_base;
    if (tid == 0) s_base = *(volatile unsigned*)&g_bar_release;
    __syncthreads();
    const unsigned base = s_base;

    // zero flags behind the (replay-safe) global barrier
    if (bid == 0) {
        if (tid < 128)              g_flagBQ[tid]      = 0;
        else if (tid < 160)         g_flagA[tid - 128] = 0;
    }
    grid_bar(base, 1);

    const int lane = tid & 31, warp = tid >> 5;
    const int g = lane >> 2, tg = lane & 3;
    const int warp_m = (warp & 1) * 32;
    const int warp_n = (warp >> 1) * 16;
    const int tm = bid >> 5;            // 0..3   A: M-tile (64 rows)
    const int tn = bid & 31;            // 0..31  A: N-stripe of kv (64 cols)
    const int lr3 = tid >> 5;           // 0..7   (cp.async row)
    const int lc3 = tid & 31;           // 0..31  (cp.async float4 col)

    const int ar = (lane & 7) + ((lane >> 3) & 1) * 8;
    const int ac = (lane >> 4) * 4;
    const int br = (lane & 7) + (lane >> 4) * 8;
    const int bc = ((lane >> 3) & 1) * 4;

    const int h  = bid >> 3;            // 0..15  B: head
    const int qt = bid & 7;             // 0..7   B: q row-block (32 rows)
    const int q  = tid & 31;
    const int ck = tid >> 5;

    for (int i = 1; i < NWIN; i++) {
        float* kvb          = kv + (size_t)(i & 1) * KW * 2 * ODIM;
        float* stb          = st + (size_t)(i & 1) * KW * ODIM;
        const float* stprev = st + (size_t)((i - 1) & 1) * KW * ODIM;

        // ================= Phase A: KV projection (BK=128, streamed k-block waits) ====
        {
            const float* A  = (i == 1) ? x    : stprev;
            const float* W  = (i == 1) ? wkv2 : wkvF;
            const float* bb = (i == 1) ? bkv2 : bkvF;

            float cacc[2][2][4];
            #pragma unroll
            for (int mt = 0; mt < 2; mt++)
                #pragma unroll
                for (int nt = 0; nt < 2; nt++)
                    #pragma unroll
                    for (int r = 0; r < 4; r++) cacc[mt][nt][r] = 0.f;

            // wait for st heads 2t,2t+1 (rows 2tm,2tm+1) of step i-1; lane0 polls per warp
            auto waitK = [&](int t) {
                if (i > 1) {
                    if (lane == 0) {
                        const unsigned tgt = (unsigned)(i - 1);
                        const int h0 = 2 * t;
                        while (flag_acquire(&g_flagBQ[(2*tm)*16   + h0])     < tgt) { }
                        while (flag_acquire(&g_flagBQ[(2*tm)*16   + h0 + 1]) < tgt) { }
                        while (flag_acquire(&g_flagBQ[(2*tm+1)*16 + h0])     < tgt) { }
                        while (flag_acquire(&g_flagBQ[(2*tm+1)*16 + h0 + 1]) < tgt) { }
                    }
                    __syncwarp();
                }
            };
            auto issue = [&](int t) {
                size_t ko = (size_t)t * RA_BK + lc3 * 4;
                float* As = sm + (t % 3) * RA_BUF;
                float* Bs = As + 64 * RA_LD;
                #pragma unroll
                for (int p = 0; p < 8; p++) {
                    int r = lr3 + p * 8;
                    CP_ASYNC16(smaddr(&As[r * RA_LD + lc3*4]), &A[(size_t)(tm*64 + r) * 1024 + ko]);
                    CP_ASYNC16(smaddr(&Bs[r * RA_LD + lc3*4]), &W[(size_t)(tn*64 + r) * 1024 + ko]);
                }
                CP_COMMIT();
            };

            waitK(0); issue(0);
            waitK(1); issue(1);
            for (int t = 0; t < 8; t++) {
                if (t == 7) { CP_WAIT0(); } else { CP_WAIT1(); }
                __syncthreads();
                if (t + 2 < 8) { waitK(t + 2); issue(t + 2); }

                const float* bufp = sm + (t % 3) * RA_BUF;
                const uint32_t a_base = smaddr(bufp + (warp_m + ar) * RA_LD + ac);
                const uint32_t b_base = smaddr(bufp + 64 * RA_LD + (warp_n + br) * RA_LD + bc);

                #pragma unroll
                for (int ks = 0; ks < 16; ks++) {
                    uint32_t a[2][4], b[2][2];
                    #pragma unroll
                    for (int mt = 0; mt < 2; mt++)
                        LDSM4(a[mt][0], a[mt][1], a[mt][2], a[mt][3],
                              a_base + (uint32_t)((mt * 16 * RA_LD + ks * 8) * 4));
                    LDSM4(b[0][0], b[0][1], b[1][0], b[1][1],
                          b_base + (uint32_t)((ks * 8) * 4));
                    #pragma unroll
                    for (int mt = 0; mt < 2; mt++)
                        #pragma unroll
                        for (int nt = 0; nt < 2; nt++)
                            MMA_TF32(cacc[mt][nt], a[mt], b[nt]);
                }
            }

            #pragma unroll
            for (int mt = 0; mt < 2; mt++) {
                int row0 = tm*64 + warp_m + mt*16 + g;
                #pragma unroll
                for (int nt = 0; nt < 2; nt++) {
                    int col = tn*64 + warp_n + nt*8 + tg*2;
                    float2 bb2 = *(const float2*)&bb[col];
                    float2 o0, o1;
                    o0.x = cacc[mt][nt][0] + bb2.x;  o0.y = cacc[mt][nt][1] + bb2.y;
                    o1.x = cacc[mt][nt][2] + bb2.x;  o1.y = cacc[mt][nt][3] + bb2.y;
                    *(float2*)&kvb[(size_t)row0 * 2048 + col]       = o0;
                    *(float2*)&kvb[(size_t)(row0 + 8) * 2048 + col] = o1;
                }
            }
            __syncthreads();
            if (tid == 0) flag_release(&g_flagA[tn]);
        }

        // ================= Phase B: attention =================
        {
            if (tid == 0) {
                unsigned tgt = 4u * (unsigned)i;
                while (flag_acquire(&g_flagA[h])      < tgt) { }
                while (flag_acquire(&g_flagA[16 + h]) < tgt) { }
            }
            __syncthreads();

            float* Ks   = sm;
            float* Vs   = sm + 16384;
            float* mbuf = sm + 32768;
            float* lbuf = mbuf + 256;

            const float* Kp = kvb + h * DH;
            const float* Vp = kvb + 1024 + h * DH;
            for (int idx = tid; idx < 256 * 16; idx += 256) {
                int r  = idx >> 4;
                int c4 = idx & 15;
                CP_ASYNC16(smaddr(Ks + r*64 + c4*4), Kp + (size_t)r*2048 + c4*4);
                CP_ASYNC16(smaddr(Vs + r*64 + c4*4), Vp + (size_t)r*2048 + c4*4);
            }
            CP_COMMIT();

            const float* Qr = q2 + (size_t)i * KW * ODIM + (size_t)(qt*32 + q) * 1024 + h * DH;
            ull qp[32];
            #pragma unroll
            for (int d4 = 0; d4 < 16; d4++) {
                ulonglong2 v = *(const ulonglong2*)(Qr + d4*4);
                qp[2*d4]   = v.x;
                qp[2*d4+1] = v.y;
            }

            CP_WAIT0();
            __syncthreads();

            float m = -1e30f, l = 0.f;
            ull accp[32];
            #pragma unroll
            for (int t = 0; t < 32; t++) accp[t] = 0ull;

            const int k0 = ck * 32;
            for (int kk = 0; kk < 32; kk++) {
                const float* Krow = Ks + (k0 + kk) * 64;
                ull s0 = 0ull, s1 = 0ull, s2 = 0ull, s3 = 0ull;
                #pragma unroll
                for (int d4 = 0; d4 < 16; d4 += 2) {
                    ulonglong2 a = *(const ulonglong2*)(Krow + d4*4);
                    ulonglong2 b = *(const ulonglong2*)(Krow + d4*4 + 4);
                    FMA2(s0, qp[2*d4+0], a.x, s0);
                    FMA2(s1, qp[2*d4+1], a.y, s1);
                    FMA2(s2, qp[2*d4+2], b.x, s2);
                    FMA2(s3, qp[2*d4+3], b.y, s3);
                }
                float a0,a1,b0,b1,c0,c1,d0,d1;
                UNPACK2(a0,a1,s0); UNPACK2(b0,b1,s1); UNPACK2(c0,c1,s2); UNPACK2(d0,d1,s3);
                float s = ((a0+a1)+(b0+b1)) + ((c0+c1)+(d0+d1));
                s *= 0.125f;

                if (s > m) {
                    float corr = __expf(m - s);
                    l *= corr;
                    ull cp; PACK2(cp, corr, corr);
                    #pragma unroll
                    for (int t = 0; t < 32; t++) MUL2(accp[t], accp[t], cp);
                    m = s;
                }
                float p = __expf(s - m);
                l += p;
                ull pp; PACK2(pp, p, p);
                const float* Vrow = Vs + (k0 + kk) * 64;
                #pragma unroll
                for (int d4 = 0; d4 < 16; d4 += 2) {
                    ulonglong2 a = *(const ulonglong2*)(Vrow + d4*4);
                    ulonglong2 b = *(const ulonglong2*)(Vrow + d4*4 + 4);
                    FMA2(accp[2*d4+0], pp, a.x, accp[2*d4+0]);
                    FMA2(accp[2*d4+1], pp, a.y, accp[2*d4+1]);
                    FMA2(accp[2*d4+2], pp, b.x, accp[2*d4+2]);
                    FMA2(accp[2*d4+3], pp, b.y, accp[2*d4+3]);
                }
            }
            __syncthreads();

            float* accbuf = sm;
            mbuf[tid] = m;
            lbuf[tid] = l;
            #pragma unroll
            for (int t = 0; t < 32; t++) {
                float f0, f1;
                UNPACK2(f0, f1, accp[t]);
                accbuf[tid*65 + 2*t]     = f0;
                accbuf[tid*65 + 2*t + 1] = f1;
            }
            __syncthreads();

            float mv[8], ev[8];
            float mg = -1e30f;
            #pragma unroll
            for (int cc = 0; cc < 8; cc++) { mv[cc] = mbuf[cc*32 + q]; mg = fmaxf(mg, mv[cc]); }
            float lg = 0.f;
            #pragma unroll
            for (int cc = 0; cc < 8; cc++) { ev[cc] = __expf(mv[cc] - mg); lg += lbuf[cc*32 + q] * ev[cc]; }
            float inv = 1.f / lg;

            float* Orow = stb + (size_t)(qt*32 + q) * 1024 + h * DH;
            #pragma unroll
            for (int j = 0; j < 8; j++) {
                int d = ck*8 + j;
                float o = 0.f;
                #pragma unroll
                for (int cc = 0; cc < 8; cc++)
                    o += accbuf[(cc*32 + q)*65 + d] * ev[cc];
                Orow[d] = o * inv;
            }
            __syncthreads();
            if (tid == 0) flag_release(&g_flagBQ[qt*16 + h]);
        }
    }
}

// ---------------- host ----------------
extern "C" void kernel_launch(void* const* d_in, const int* in_sizes, int n_in,
                              void* d_out, int out_size)
{
    const float* path   = (const float*)d_in[0];
    const float* w_in1  = (const float*)d_in[1];
    const float* b_in1  = (const float*)d_in[2];
    const float* w_out1 = (const float*)d_in[3];
    const float* b_out1 = (const float*)d_in[4];
    const float* w_lin  = (const float*)d_in[5];
    const float* b_lin  = (const float*)d_in[6];
    const float* w_in2  = (const float*)d_in[7];
    const float* b_in2  = (const float*)d_in[8];
    const float* w_out2 = (const float*)d_in[9];
    const float* b_out2 = (const float*)d_in[10];

    float *qkv1, *attn1, *x, *q2, *kv, *st, *wt, *wt2, *wcomb, *bcomb, *wkv, *bkv, *zb;
    cudaGetSymbolAddress((void**)&qkv1,  g_qkv1);
    cudaGetSymbolAddress((void**)&attn1, g_attn1);
    cudaGetSymbolAddress((void**)&x,     g_x);
    cudaGetSymbolAddress((void**)&q2,    g_q2);
    cudaGetSymbolAddress((void**)&kv,    g_kv);
    cudaGetSymbolAddress((void**)&st,    g_st);
    cudaGetSymbolAddress((void**)&wt,    g_wt);
    cudaGetSymbolAddress((void**)&wt2,   g_wt2);
    cudaGetSymbolAddress((void**)&wcomb, g_wcomb);
    cudaGetSymbolAddress((void**)&bcomb, g_bcomb);
    cudaGetSymbolAddress((void**)&wkv,   g_wkv);
    cudaGetSymbolAddress((void**)&bkv,   g_bkv);
    cudaGetSymbolAddress((void**)&zb,    g_zb);

    cudaFuncSetAttribute(attn_kernel,        cudaFuncAttributeMaxDynamicSharedMemorySize, ATTN_SMEM);
    cudaFuncSetAttribute(gemm_tf32<false>,   cudaFuncAttributeMaxDynamicSharedMemorySize, TF_SMEM);
    cudaFuncSetAttribute(gemm_tf32<true>,    cudaFuncAttributeMaxDynamicSharedMemorySize, TF_SMEM);
    cudaFuncSetAttribute(recurrence_kernel,  cudaFuncAttributeMaxDynamicSharedMemorySize, REC_SMEM);
    cudaFuncSetAttribute(gemm_tf32<false>,   cudaFuncAttributePreferredSharedMemoryCarveout, 100);
    cudaFuncSetAttribute(gemm_tf32<true>,    cudaFuncAttributePreferredSharedMemoryCarveout, 100);

    auto g64  = gemm_bias<64,64,16,4,4>;
    auto t32  = gemm_tf32<false>;
    auto t32r = gemm_tf32<true>;

    const float* wkv2 = w_in2 + (size_t)ODIM * ODIM;
    const float* bkv2 = b_in2 + ODIM;

    // launch 0: all prologue prep in one kernel
    prep_kernel<<<2052 + 128 + 256, 256>>>(w_out1, w_out2, w_lin, b_out1, b_lin,
                                           wkv2, b_out2, bkv2, wt, wt2, zb, bcomb, bkv);
    // launches 1-2: weight folds (tf32)
    t32<<<dim3(DM/128, DM/128), 256, TF_SMEM>>>(w_lin, wt, zb, wcomb, DM, DM, DM);
    t32<<<dim3(DM/128, 2*ODIM/128), 256, TF_SMEM>>>(wkv2, wt2, zb, wkv, 2*ODIM, DM, DM);

    // launch 3: stage 1 QKV of every path row
    t32<<<dim3(3*DM/128, SEQ/128), 256, TF_SMEM>>>(path, w_in1, b_in1, qkv1, SEQ, 3*DM, DM);

    // launch 4: stage 2 batched window self-attention (exact fp32)
    attn_kernel<<<dim3(NH, KW/64, NWIN), 256, ATTN_SMEM>>>(
        qkv1,        (long long)STR * 3*DM, 3*DM,
        qkv1 + DM,   (long long)STR * 3*DM, 3*DM,
        qkv1 + 2*DM, (long long)STR * 3*DM, 3*DM,
        attn1,       (long long)KW * DM,    DM,
        0.125f);

    // launch 5: stage 3 fused outproj1 + linear + relu (tf32)  <-- ncu -s 5 target
    t32r<<<dim3(ODIM/128, ROWS/128), 256, TF_SMEM>>>(attn1, wcomb, bcomb, x, ROWS, ODIM, DM);

    // launch 6: stage 4a bulk Q2 projections (tf32)
    t32<<<dim3(ODIM/128, ROWS/128), 256, TF_SMEM>>>(x, w_in2, b_in2, q2, ROWS, ODIM, ODIM);

    // launch 7: persistent recurrence with streamed fine-grained flags
    recurrence_kernel<<<REC_NB, 256, REC_SMEM>>>(x, q2, wkv2, bkv2, wkv, bkv, kv, st);

    // launch 8: final out-projection (exact fp32 -> d_out); last step wrote st[(NWIN-1)&1]
    g64<<<dim3(ODIM/64, KW/64), 256>>>(st + (size_t)((NWIN-1)&1) * KW * ODIM,
                                       w_out2, b_out2, (float*)d_out, KW, ODIM, ODIM);
}

// round 12
// speedup vs baseline: 1.1726x; 1.1726x over previous
#include <cuda_runtime.h>
#include <cuda_fp16.h>
#include <math.h>
#include <stdint.h>

// ---------------- problem constants ----------------
constexpr int SEQ  = 4096;
constexpr int DM   = 1024;
constexpr int ODIM = 1024;
constexpr int KW   = 256;
constexpr int STR  = 16;
constexpr int NH   = 16;
constexpr int DH   = 64;
constexpr int NWIN = (SEQ - KW) / STR;   // 240
constexpr int ROWS = NWIN * KW;          // 61440

typedef unsigned long long ull;

// packed fp32x2 helpers
#define PACK2(o, lo, hi)   asm("mov.b64 %0, {%1,%2};" : "=l"(o) : "f"(lo), "f"(hi))
#define UNPACK2(lo, hi, i) asm("mov.b64 {%0,%1}, %2;" : "=f"(lo), "=f"(hi) : "l"(i))
#define FMA2(d, a, b, c)   asm("fma.rn.f32x2 %0, %1, %2, %3;" : "=l"(d) : "l"(a), "l"(b), "l"(c))
#define MUL2(d, a, b)      asm("mul.rn.f32x2 %0, %1, %2;" : "=l"(d) : "l"(a), "l"(b))

__device__ __forceinline__ uint32_t smaddr(const void* p) {
    return (uint32_t)__cvta_generic_to_shared(p);
}

#define CP_ASYNC16(sm_u32, gptr) \
    asm volatile("cp.async.cg.shared.global [%0], [%1], 16;" :: "r"(sm_u32), "l"(gptr))
#define CP_COMMIT() asm volatile("cp.async.commit_group;")
#define CP_WAIT0()  asm volatile("cp.async.wait_group 0;")
#define CP_WAIT1()  asm volatile("cp.async.wait_group 1;")

#define LDSM4(r0, r1, r2, r3, addr) \
    asm volatile("ldmatrix.sync.aligned.m8n8.x4.shared.b16 {%0,%1,%2,%3}, [%4];" \
        : "=r"(r0), "=r"(r1), "=r"(r2), "=r"(r3) : "r"(addr))

#define MMA_TF32(c, a, b) \
    asm volatile("mma.sync.aligned.m16n8k8.row.col.f32.tf32.tf32.f32 " \
        "{%0,%1,%2,%3},{%4,%5,%6,%7},{%8,%9},{%0,%1,%2,%3};" \
        : "+f"((c)[0]), "+f"((c)[1]), "+f"((c)[2]), "+f"((c)[3]) \
        : "r"((a)[0]), "r"((a)[1]), "r"((a)[2]), "r"((a)[3]), "r"((b)[0]), "r"((b)[1]))

#define MMA_F16(c, a, b) \
    asm volatile("mma.sync.aligned.m16n8k16.row.col.f32.f16.f16.f32 " \
        "{%0,%1,%2,%3},{%4,%5,%6,%7},{%8,%9},{%0,%1,%2,%3};" \
        : "+f"((c)[0]), "+f"((c)[1]), "+f"((c)[2]), "+f"((c)[3]) \
        : "r"((a)[0]), "r"((a)[1]), "r"((a)[2]), "r"((a)[3]), "r"((b)[0]), "r"((b)[1]))

// release/acquire flag ops (L2-scope ordering; no CCTL.IVALL)
__device__ __forceinline__ void flag_release(unsigned* f) {
    unsigned old;
    asm volatile("atom.release.gpu.global.add.u32 %0, [%1], 1;" : "=r"(old) : "l"(f) : "memory");
}
__device__ __forceinline__ unsigned flag_acquire(unsigned* f) {
    unsigned v;
    asm volatile("ld.acquire.gpu.global.u32 %0, [%1];" : "=r"(v) : "l"(f) : "memory");
    return v;
}

// ---------------- scratch ----------------
__device__ float  g_qkv1[SEQ * 3 * DM];
__device__ __half g_attn1h[ROWS * DM];      // stage2 output, fp16 (stage3's only input)
__device__ float  g_x[ROWS * ODIM];         // fp32 (recurrence i==1)
__device__ __half g_x16[ROWS * ODIM];       // fp16 shadow (stage4a input)
__device__ float  g_q2[ROWS * ODIM];
__device__ float  g_kv[2 * KW * 2 * ODIM];  // double-buffered by step parity
__device__ float  g_st[2 * KW * ODIM];      // double-buffered by step parity
__device__ float  g_wt[DM * DM];
__device__ float  g_wt2[DM * DM];
__device__ float  g_wcomb[DM * DM];
__device__ __half g_wcomb16[DM * DM];
__device__ __half g_win2q16[ODIM * DM];
__device__ float  g_bcomb[DM];
__device__ float  g_wkv[2 * ODIM * DM];
__device__ float  g_bkv[2 * ODIM];
__device__ float  g_zb[DM];

// persistent-kernel sync state (monotonic; replay-safe)
__device__ unsigned g_bar_arrive  = 0;
__device__ unsigned g_bar_release = 0;
__device__ unsigned g_flagA[32];            // per kv column-stripe: +4 per step
__device__ unsigned g_flagB[8];             // per st row-block:     +16 per step

// ================= TF32 tensor-core GEMM, 128x128 tiles, 3-stage cp.async =========
constexpr int TF_BK = 32;
constexpr int TF_LD = TF_BK + 4;                       // 36 floats
constexpr int TF_BUF = (128 + 128) * TF_LD;            // floats per stage
constexpr int TF_SMEM = 3 * TF_BUF * (int)sizeof(float);  // 110592 B

template<bool RELU>
__global__ __launch_bounds__(256, 2)
void gemm_tf32(const float* __restrict__ A, const float* __restrict__ W,
               const float* __restrict__ bias, float* __restrict__ C,
               int M, int N, int K)
{
    extern __shared__ float smem[];
    const int tid    = threadIdx.x;
    const int lane   = tid & 31;
    const int warp   = tid >> 5;
    const int warp_m = (warp & 1) * 64;
    const int warp_n = (warp >> 1) * 32;
    const int bm     = blockIdx.y * 128;
    const int bn     = blockIdx.x * 128;

    const int ar = (lane & 7) + ((lane >> 3) & 1) * 8;
    const int ac = (lane >> 4) * 4;
    const int br = (lane & 7) + (lane >> 4) * 8;
    const int bc = ((lane >> 3) & 1) * 4;

    float c[4][4][4];
    #pragma unroll
    for (int i = 0; i < 4; i++)
        #pragma unroll
        for (int j = 0; j < 4; j++)
            #pragma unroll
            for (int r = 0; r < 4; r++) c[i][j][r] = 0.f;

    const int lr = tid >> 3;
    const int lc = tid & 7;

    auto issue = [&](int t) {
        const size_t ko = (size_t)t * TF_BK + lc * 4;
        float* As = smem + (t % 3) * TF_BUF;
        float* Bs = As + 128 * TF_LD;
        #pragma unroll
        for (int i = 0; i < 4; i++) {
            int r = lr + i * 32;
            CP_ASYNC16(smaddr(&As[r * TF_LD + lc * 4]), &A[(size_t)(bm + r) * K + ko]);
            CP_ASYNC16(smaddr(&Bs[r * TF_LD + lc * 4]), &W[(size_t)(bn + r) * K + ko]);
        }
        CP_COMMIT();
    };

    const int nk = K / TF_BK;
    issue(0);
    if (nk > 1) issue(1);

    for (int t = 0; t < nk; t++) {
        if (t == nk - 1) { CP_WAIT0(); } else { CP_WAIT1(); }
        __syncthreads();
        if (t + 2 < nk) issue(t + 2);

        const float* bufp = smem + (t % 3) * TF_BUF;
        const uint32_t a_base = smaddr(bufp + (warp_m + ar) * TF_LD + ac);
        const uint32_t b_base = smaddr(bufp + 128 * TF_LD + (warp_n + br) * TF_LD + bc);

        #pragma unroll
        for (int ks = 0; ks < 4; ks++) {
            uint32_t a[4][4], b[4][2];
            #pragma unroll
            for (int mt = 0; mt < 4; mt++)
                LDSM4(a[mt][0], a[mt][1], a[mt][2], a[mt][3],
                      a_base + (uint32_t)((mt * 16 * TF_LD + ks * 8) * 4));
            #pragma unroll
            for (int np = 0; np < 2; np++)
                LDSM4(b[2*np][0], b[2*np][1], b[2*np+1][0], b[2*np+1][1],
                      b_base + (uint32_t)((np * 16 * TF_LD + ks * 8) * 4));
            #pragma unroll
            for (int mt = 0; mt < 4; mt++)
                #pragma unroll
                for (int nt = 0; nt < 4; nt++)
                    MMA_TF32(c[mt][nt], a[mt], b[nt]);
        }
    }

    const int g  = lane >> 2;
    const int tg = lane & 3;
    #pragma unroll
    for (int mt = 0; mt < 4; mt++) {
        int row0 = bm + warp_m + mt * 16 + g;
        #pragma unroll
        for (int nt = 0; nt < 4; nt++) {
            int col = bn + warp_n + nt * 8 + tg * 2;
            float2 bb = *(const float2*)&bias[col];
            float2 o0, o1;
            o0.x = c[mt][nt][0] + bb.x;  o0.y = c[mt][nt][1] + bb.y;
            o1.x = c[mt][nt][2] + bb.x;  o1.y = c[mt][nt][3] + bb.y;
            if (RELU) {
                o0.x = fmaxf(o0.x, 0.f); o0.y = fmaxf(o0.y, 0.f);
                o1.x = fmaxf(o1.x, 0.f); o1.y = fmaxf(o1.y, 0.f);
            }
            *(float2*)&C[(size_t)row0 * N + col]       = o0;
            *(float2*)&C[(size_t)(row0 + 8) * N + col] = o1;
        }
    }
}

// ================= FP16 tensor-core GEMM, 128x128 tiles, 3-stage cp.async =========
// A[M,K], W[N,K] fp16; fp32 accumulate; optional fp16 shadow output.
constexpr int H_BK  = 32;                    // halfs per k-tile
constexpr int H_LD  = H_BK + 8;              // 40 halfs = 80 B padded stride (conflict-free LDSM)
constexpr int H_BUF = (128 + 128) * H_LD;    // halfs per stage
constexpr int H_SMEM = 3 * H_BUF * 2;        // 61440 B

template<bool RELU>
__global__ __launch_bounds__(256, 2)
void gemm_fp16(const __half* __restrict__ A, const __half* __restrict__ W,
               const float* __restrict__ bias, float* __restrict__ C,
               __half* __restrict__ C16, int M, int N, int K)
{
    extern __shared__ __half smh[];
    const int tid    = threadIdx.x;
    const int lane   = tid & 31;
    const int warp   = tid >> 5;
    const int warp_m = (warp & 1) * 64;
    const int warp_n = (warp >> 1) * 32;
    const int bm     = blockIdx.y * 128;
    const int bn     = blockIdx.x * 128;

    // ldmatrix b16 fragment address components (units: halfs)
    const int ar = (lane & 7) + ((lane >> 3) & 1) * 8;
    const int ac = (lane >> 4) * 8;
    const int br = (lane & 7) + (lane >> 4) * 8;
    const int bc = ((lane >> 3) & 1) * 8;

    float c[4][4][4];
    #pragma unroll
    for (int i = 0; i < 4; i++)
        #pragma unroll
        for (int j = 0; j < 4; j++)
            #pragma unroll
            for (int r = 0; r < 4; r++) c[i][j][r] = 0.f;

    // cp.async: per operand tile 128 rows x 4 chunks of 8 halfs (16B); 2 chunks/thread
    const int cr = tid >> 1;        // row 0..127
    const int cc = (tid & 1) * 2;   // chunk pair base

    auto issue = [&](int t) {
        const size_t ko = (size_t)t * H_BK;
        __half* As = smh + (t % 3) * H_BUF;
        __half* Bs = As + 128 * H_LD;
        #pragma unroll
        for (int j = 0; j < 2; j++) {
            int ch = cc + j;
            CP_ASYNC16(smaddr(&As[cr * H_LD + ch * 8]), &A[(size_t)(bm + cr) * K + ko + ch * 8]);
            CP_ASYNC16(smaddr(&Bs[cr * H_LD + ch * 8]), &W[(size_t)(bn + cr) * K + ko + ch * 8]);
        }
        CP_COMMIT();
    };

    const int nk = K / H_BK;
    issue(0);
    if (nk > 1) issue(1);

    for (int t = 0; t < nk; t++) {
        if (t == nk - 1) { CP_WAIT0(); } else { CP_WAIT1(); }
        __syncthreads();
        if (t + 2 < nk) issue(t + 2);

        const __half* bufp = smh + (t % 3) * H_BUF;
        const uint32_t a_base = smaddr(bufp + (warp_m + ar) * H_LD + ac);
        const uint32_t b_base = smaddr(bufp + 128 * H_LD + (warp_n + br) * H_LD + bc);

        #pragma unroll
        for (int ks = 0; ks < 2; ks++) {      // two k16 chunks per 32-half tile
            uint32_t a[4][4], b[4][2];
            #pragma unroll
            for (int mt = 0; mt < 4; mt++)
                LDSM4(a[mt][0], a[mt][1], a[mt][2], a[mt][3],
                      a_base + (uint32_t)((mt * 16 * H_LD + ks * 16) * 2));
            #pragma unroll
            for (int np = 0; np < 2; np++)
                LDSM4(b[2*np][0], b[2*np][1], b[2*np+1][0], b[2*np+1][1],
                      b_base + (uint32_t)((np * 16 * H_LD + ks * 16) * 2));
            #pragma unroll
            for (int mt = 0; mt < 4; mt++)
                #pragma unroll
                for (int nt = 0; nt < 4; nt++)
                    MMA_F16(c[mt][nt], a[mt], b[nt]);
        }
    }

    const int g  = lane >> 2;
    const int tg = lane & 3;
    #pragma unroll
    for (int mt = 0; mt < 4; mt++) {
        int row0 = bm + warp_m + mt * 16 + g;
        #pragma unroll
        for (int nt = 0; nt < 4; nt++) {
            int col = bn + warp_n + nt * 8 + tg * 2;
            float2 bb = *(const float2*)&bias[col];
            float2 o0, o1;
            o0.x = c[mt][nt][0] + bb.x;  o0.y = c[mt][nt][1] + bb.y;
            o1.x = c[mt][nt][2] + bb.x;  o1.y = c[mt][nt][3] + bb.y;
            if (RELU) {
                o0.x = fmaxf(o0.x, 0.f); o0.y = fmaxf(o0.y, 0.f);
                o1.x = fmaxf(o1.x, 0.f); o1.y = fmaxf(o1.y, 0.f);
            }
            *(float2*)&C[(size_t)row0 * N + col]       = o0;
            *(float2*)&C[(size_t)(row0 + 8) * N + col] = o1;
            if (C16) {
                __half2 h0 = __floats2half2_rn(o0.x, o0.y);
                __half2 h1 = __floats2half2_rn(o1.x, o1.y);
                *(__half2*)&C16[(size_t)row0 * N + col]       = h0;
                *(__half2*)&C16[(size_t)(row0 + 8) * N + col] = h1;
            }
        }
    }
}

// ================= exact FFMA2 SGEMM (final projection only) =================
template<int BM, int BN, int BK, int TM, int TN>
__global__ __launch_bounds__((BM/TM)*(BN/TN))
void gemm_bias(const float* __restrict__ A, const float* __restrict__ W,
               const float* __restrict__ bias, float* __restrict__ C,
               int M, int N, int K)
{
    constexpr int THREADS = (BM/TM)*(BN/TN);
    __shared__ __align__(16) float As[BK][BM];
    __shared__ __align__(16) float Bs[BK][BN];
    const int tid  = threadIdx.x;
    const int bm   = blockIdx.y * BM;
    const int bn   = blockIdx.x * BN;
    const int tcol = tid % (BN/TN);
    const int trow = tid / (BN/TN);

    ull acc2[TM][TN/2];
    #pragma unroll
    for (int i = 0; i < TM; i++)
        #pragma unroll
        for (int j = 0; j < TN/2; j++) acc2[i][j] = 0ull;

    constexpr int AF4 = BM * (BK/4);
    constexpr int BF4 = BN * (BK/4);

    for (int k0 = 0; k0 < K; k0 += BK) {
        #pragma unroll
        for (int i = tid; i < AF4; i += THREADS) {
            int r  = i / (BK/4);
            int c4 = i % (BK/4);
            float4 v = *(const float4*)&A[(size_t)(bm + r) * K + k0 + c4*4];
            As[c4*4+0][r] = v.x; As[c4*4+1][r] = v.y;
            As[c4*4+2][r] = v.z; As[c4*4+3][r] = v.w;
        }
        #pragma unroll
        for (int i = tid; i < BF4; i += THREADS) {
            int r  = i / (BK/4);
            int c4 = i % (BK/4);
            float4 v = *(const float4*)&W[(size_t)(bn + r) * K + k0 + c4*4];
            Bs[c4*4+0][r] = v.x; Bs[c4*4+1][r] = v.y;
            Bs[c4*4+2][r] = v.z; Bs[c4*4+3][r] = v.w;
        }
        __syncthreads();

        #pragma unroll
        for (int k = 0; k < BK; k++) {
            float ra[TM];
            #pragma unroll
            for (int i = 0; i < TM; i += 4) {
                float4 v = *(const float4*)&As[k][trow*TM + i];
                ra[i] = v.x; ra[i+1] = v.y; ra[i+2] = v.z; ra[i+3] = v.w;
            }
            ull ras[TM];
            #pragma unroll
            for (int i = 0; i < TM; i++) PACK2(ras[i], ra[i], ra[i]);

            ull rb2[TN/2];
            #pragma unroll
            for (int j4 = 0; j4 < TN/4; j4++) {
                ulonglong2 v = *(const ulonglong2*)&Bs[k][tcol*TN + j4*4];
                rb2[2*j4]   = v.x;
                rb2[2*j4+1] = v.y;
            }
            #pragma unroll
            for (int i = 0; i < TM; i++)
                #pragma unroll
                for (int j = 0; j < TN/2; j++)
                    FMA2(acc2[i][j], ras[i], rb2[j], acc2[i][j]);
        }
        __syncthreads();
    }

    #pragma unroll
    for (int i = 0; i < TM; i++) {
        size_t row = (size_t)(bm + trow*TM + i);
        float oc[TN];
        #pragma unroll
        for (int j = 0; j < TN/2; j++) UNPACK2(oc[2*j], oc[2*j+1], acc2[i][j]);
        #pragma unroll
        for (int j = 0; j < TN; j += 4) {
            int col = bn + tcol*TN + j;
            float4 b4 = *(const float4*)&bias[col];
            float4 o;
            o.x = oc[j+0] + b4.x;
            o.y = oc[j+1] + b4.y;
            o.z = oc[j+2] + b4.z;
            o.w = oc[j+3] + b4.w;
            *(float4*)&C[row * N + col] = o;
        }
    }
}

// ---------------- prep: transposes + zero + bias folds in ONE launch ----------------
__global__ __launch_bounds__(256)
void prep_kernel(const float* __restrict__ w_out1, const float* __restrict__ w_out2,
                 const float* __restrict__ w_lin,  const float* __restrict__ b_out1,
                 const float* __restrict__ b_lin,  const float* __restrict__ wkv2,
                 const float* __restrict__ b_out2, const float* __restrict__ bkv2,
                 float* __restrict__ wt, float* __restrict__ wt2, float* __restrict__ zb,
                 float* __restrict__ bcomb, float* __restrict__ bkv)
{
    const int b   = blockIdx.x;
    const int tid = threadIdx.x;

    if (b < 2048) {
        const float* in = (b < 1024) ? w_out1 : w_out2;
        float* out      = (b < 1024) ? wt : wt2;
        const int bb = b & 1023;
        const int bx = bb & 31, by = bb >> 5;
        __shared__ float tile[32][33];
        const int tx = tid & 31, ty = tid >> 5;
        #pragma unroll
        for (int j = 0; j < 32; j += 8)
            tile[ty + j][tx] = in[(size_t)(by*32 + ty + j) * DM + bx*32 + tx];
        __syncthreads();
        #pragma unroll
        for (int j = 0; j < 32; j += 8)
            out[(size_t)(bx*32 + ty + j) * DM + by*32 + tx] = tile[tx][ty + j];
    } else if (b < 2052) {
        zb[(b - 2048) * 256 + tid] = 0.f;
    } else {
        int bb = b - 2052;
        const float *W, *b1, *b2;
        float* out;
        if (bb < 128) { W = w_lin; b1 = b_out1; b2 = b_lin; out = bcomb; }
        else          { bb -= 128; W = wkv2; b1 = b_out2; b2 = bkv2; out = bkv; }
        const int n = bb * 8 + (tid >> 5);
        const int lane = tid & 31;
        float s = 0.f;
        for (int j = lane; j < DM; j += 32) s = fmaf(W[(size_t)n * DM + j], b1[j], s);
        #pragma unroll
        for (int o = 16; o; o >>= 1) s += __shfl_xor_sync(0xffffffffu, s, o);
        if (lane == 0) out[n] = s + b2[n];
    }
}

// f32 -> f16 convert (grid-stride, float4 granularity)
__global__ void f2h_kernel(const float* __restrict__ in, __half* __restrict__ out, int n)
{
    int i = (blockIdx.x * blockDim.x + threadIdx.x) * 4;
    if (i < n) {
        float4 v = *(const float4*)&in[i];
        __half2 h0 = __floats2half2_rn(v.x, v.y);
        __half2 h1 = __floats2half2_rn(v.z, v.w);
        *(__half2*)&out[i]     = h0;
        *(__half2*)&out[i + 2] = h1;
    }
}

// ---------------- flash-style attention (stage 2; fp16 output) ----------------
constexpr int ATTN_SMEM = (2 * KW * DH + 2 * 256) * (int)sizeof(float); // 133120 B

__global__ __launch_bounds__(256)
void attn_kernel(const float* __restrict__ qbase, long long q_ws, int q_rs,
                 const float* __restrict__ kbase, long long k_ws, int k_rs,
                 const float* __restrict__ vbase, long long v_ws, int v_rs,
                 __half* __restrict__ obase,      long long o_ws, int o_rs,
                 float scale)
{
    extern __shared__ float sm[];
    float* Ks   = sm;
    float* Vs   = sm + KW * DH;
    float* mbuf = sm + 2 * KW * DH;
    float* lbuf = mbuf + 256;

    const int h  = blockIdx.x;
    const int qt = blockIdx.y;
    const int w  = blockIdx.z;
    const int tid = threadIdx.x;

    const float* Kp = kbase + (size_t)w * k_ws + h * DH;
    const float* Vp = vbase + (size_t)w * v_ws + h * DH;

    for (int idx = tid; idx < KW * (DH/4); idx += 256) {
        int r  = idx >> 4;
        int c4 = idx & 15;
        CP_ASYNC16(smaddr(Ks + r * DH + c4*4), Kp + (size_t)r * k_rs + c4*4);
        CP_ASYNC16(smaddr(Vs + r * DH + c4*4), Vp + (size_t)r * v_rs + c4*4);
    }
    CP_COMMIT();

    const int q = tid & 63;
    const int c = tid >> 6;
    const int qrow = qt * 64 + q;

    const float* Qr = qbase + (size_t)w * q_ws + (size_t)qrow * q_rs + h * DH;
    ull qp[DH/2];
    #pragma unroll
    for (int d4 = 0; d4 < 16; d4++) {
        ulonglong2 v = *(const ulonglong2*)(Qr + d4*4);
        qp[2*d4]   = v.x;
        qp[2*d4+1] = v.y;
    }

    CP_WAIT0();
    __syncthreads();

    float m = -1e30f, l = 0.f;
    ull accp[DH/2];
    #pragma unroll
    for (int t = 0; t < DH/2; t++) accp[t] = 0ull;

    const int k0 = c * 64;
    for (int kk = 0; kk < 64; kk++) {
        const float* Krow = Ks + (k0 + kk) * DH;
        ull s0 = 0ull, s1 = 0ull, s2 = 0ull, s3 = 0ull;
        #pragma unroll
        for (int d4 = 0; d4 < 16; d4 += 2) {
            ulonglong2 a = *(const ulonglong2*)(Krow + d4*4);
            ulonglong2 b = *(const ulonglong2*)(Krow + d4*4 + 4);
            FMA2(s0, qp[2*d4+0], a.x, s0);
            FMA2(s1, qp[2*d4+1], a.y, s1);
            FMA2(s2, qp[2*d4+2], b.x, s2);
            FMA2(s3, qp[2*d4+3], b.y, s3);
        }
        float a0,a1,b0,b1,c0,c1,d0,d1;
        UNPACK2(a0,a1,s0); UNPACK2(b0,b1,s1); UNPACK2(c0,c1,s2); UNPACK2(d0,d1,s3);
        float s = ((a0+a1)+(b0+b1)) + ((c0+c1)+(d0+d1));
        s *= scale;

        if (s > m) {
            float corr = __expf(m - s);
            l *= corr;
            ull cp; PACK2(cp, corr, corr);
            #pragma unroll
            for (int t = 0; t < DH/2; t++) MUL2(accp[t], accp[t], cp);
            m = s;
        }
        float p = __expf(s - m);
        l += p;
        ull pp; PACK2(pp, p, p);
        const float* Vrow = Vs + (k0 + kk) * DH;
        #pragma unroll
        for (int d4 = 0; d4 < 16; d4 += 2) {
            ulonglong2 a = *(const ulonglong2*)(Vrow + d4*4);
            ulonglong2 b = *(const ulonglong2*)(Vrow + d4*4 + 4);
            FMA2(accp[2*d4+0], pp, a.x, accp[2*d4+0]);
            FMA2(accp[2*d4+1], pp, a.y, accp[2*d4+1]);
            FMA2(accp[2*d4+2], pp, b.x, accp[2*d4+2]);
            FMA2(accp[2*d4+3], pp, b.y, accp[2*d4+3]);
        }
    }
    __syncthreads();

    float* accbuf = Ks;
    mbuf[tid] = m;
    lbuf[tid] = l;
    #pragma unroll
    for (int d4 = 0; d4 < 16; d4++)
        *(ulonglong2*)(accbuf + (size_t)tid * DH + d4*4) =
            make_ulonglong2(accp[2*d4], accp[2*d4+1]);
    __syncthreads();

    float m0 = mbuf[q], m1 = mbuf[64+q], m2 = mbuf[128+q], m3 = mbuf[192+q];
    float mg = fmaxf(fmaxf(m0, m1), fmaxf(m2, m3));
    float e0 = __expf(m0 - mg), e1 = __expf(m1 - mg);
    float e2 = __expf(m2 - mg), e3 = __expf(m3 - mg);
    float lg = lbuf[q]*e0 + lbuf[64+q]*e1 + lbuf[128+q]*e2 + lbuf[192+q]*e3;
    float inv = 1.f / lg;

    __half* Or = obase + (size_t)w * o_ws + (size_t)qrow * o_rs + h * DH;
    #pragma unroll
    for (int d = c*16; d < c*16 + 16; d += 2) {
        float oa = accbuf[(size_t)(0*64+q)*DH + d] * e0
                 + accbuf[(size_t)(1*64+q)*DH + d] * e1
                 + accbuf[(size_t)(2*64+q)*DH + d] * e2
                 + accbuf[(size_t)(3*64+q)*DH + d] * e3;
        float ob = accbuf[(size_t)(0*64+q)*DH + d+1] * e0
                 + accbuf[(size_t)(1*64+q)*DH + d+1] * e1
                 + accbuf[(size_t)(2*64+q)*DH + d+1] * e2
                 + accbuf[(size_t)(3*64+q)*DH + d+1] * e3;
        *(__half2*)&Or[d] = __floats2half2_rn(oa * inv, ob * inv);
    }
}

// ================= persistent recurrence kernel (R10: flag-synced, BK=64 phase A) ==
constexpr int REC_NB   = 128;
constexpr int REC_SMEM = (32768 + 512) * (int)sizeof(float);   // 133120 B
constexpr int RA_BK  = 64;
constexpr int RA_LD  = RA_BK + 4;                              // 68 floats
constexpr int RA_BUF = (64 + 64) * RA_LD;                      // 8704 floats per stage

__device__ __forceinline__ void grid_bar(unsigned base, unsigned bar_id)
{
    __syncthreads();
    if (threadIdx.x == 0) {
        __threadfence();
        unsigned a = atomicAdd(&g_bar_arrive, 1u);
        if ((a & (REC_NB - 1u)) == (REC_NB - 1u)) {
            atomicAdd(&g_bar_release, 1u);
        } else {
            while (*(volatile unsigned*)&g_bar_release - base < bar_id) { }
        }
        __threadfence();
    }
    __syncthreads();
}

__global__ __launch_bounds__(256)
void recurrence_kernel(const float* __restrict__ x,
                       const float* __restrict__ q2,
                       const float* __restrict__ wkv2, const float* __restrict__ bkv2,
                       const float* __restrict__ wkvF, const float* __restrict__ bkvF,
                       float* __restrict__ kv, float* __restrict__ st)
{
    extern __shared__ float sm[];
    const int tid = threadIdx.x;
    const int bid = blockIdx.x;

    __shared__ unsigned s_base;
    if (tid == 0) s_base = *(volatile unsigned*)&g_bar_release;
    __syncthreads();
    const unsigned base = s_base;

    if (bid == 0) {
        if (tid < 32)              g_flagA[tid]      = 0;
        else if (tid < 40)         g_flagB[tid - 32] = 0;
    }
    grid_bar(base, 1);

    const int lane = tid & 31, warp = tid >> 5;
    const int g = lane >> 2, tg = lane & 3;
    const int warp_m = (warp & 1) * 32;
    const int warp_n = (warp >> 1) * 16;
    const int tm = bid >> 5;            // 0..3   A: M-tile
    const int tn = bid & 31;            // 0..31  A: N-stripe of kv
    const int lr2 = tid >> 4;           // 0..15
    const int lc2 = tid & 15;           // 0..15

    const int ar = (lane & 7) + ((lane >> 3) & 1) * 8;
    const int ac = (lane >> 4) * 4;
    const int br = (lane & 7) + (lane >> 4) * 8;
    const int bc = ((lane >> 3) & 1) * 4;

    const int h  = bid >> 3;            // 0..15  B: head
    const int qt = bid & 7;             // 0..7   B: q row-block
    const int q  = tid & 31;
    const int ck = tid >> 5;

    for (int i = 1; i < NWIN; i++) {
        float* kvb          = kv + (size_t)(i & 1) * KW * 2 * ODIM;
        float* stb          = st + (size_t)(i & 1) * KW * ODIM;
        const float* stprev = st + (size_t)((i - 1) & 1) * KW * ODIM;

        // ================= Phase A: KV projection (BK=64, 3-stage) =================
        {
            if (i > 1 && tid == 0) {
                unsigned tgt = 16u * (unsigned)(i - 1);
                while (flag_acquire(&g_flagB[2*tm])     < tgt) { }
                while (flag_acquire(&g_flagB[2*tm + 1]) < tgt) { }
            }
            __syncthreads();

            const float* A  = (i == 1) ? x    : stprev;
            const float* W  = (i == 1) ? wkv2 : wkvF;
            const float* bb = (i == 1) ? bkv2 : bkvF;

            float cacc[2][2][4];
            #pragma unroll
            for (int mt = 0; mt < 2; mt++)
                #pragma unroll
                for (int nt = 0; nt < 2; nt++)
                    #pragma unroll
                    for (int r = 0; r < 4; r++) cacc[mt][nt][r] = 0.f;

            auto issue = [&](int t) {
                size_t ko = (size_t)t * RA_BK + lc2 * 4;
                float* As = sm + (t % 3) * RA_BUF;
                float* Bs = As + 64 * RA_LD;
                #pragma unroll
                for (int p = 0; p < 4; p++) {
                    int r = lr2 + p * 16;
                    CP_ASYNC16(smaddr(&As[r * RA_LD + lc2*4]), &A[(size_t)(tm*64 + r) * 1024 + ko]);
                    CP_ASYNC16(smaddr(&Bs[r * RA_LD + lc2*4]), &W[(size_t)(tn*64 + r) * 1024 + ko]);
                }
                CP_COMMIT();
            };

            issue(0);
            issue(1);
            for (int t = 0; t < 16; t++) {
                if (t == 15) { CP_WAIT0(); } else { CP_WAIT1(); }
                __syncthreads();
                if (t + 2 < 16) issue(t + 2);

                const float* bufp = sm + (t % 3) * RA_BUF;
                const uint32_t a_base = smaddr(bufp + (warp_m + ar) * RA_LD + ac);
                const uint32_t b_base = smaddr(bufp + 64 * RA_LD + (warp_n + br) * RA_LD + bc);

                #pragma unroll
                for (int ks = 0; ks < 8; ks++) {
                    uint32_t a[2][4], b[2][2];
                    #pragma unroll
                    for (int mt = 0; mt < 2; mt++)
                        LDSM4(a[mt][0], a[mt][1], a[mt][2], a[mt][3],
                              a_base + (uint32_t)((mt * 16 * RA_LD + ks * 8) * 4));
                    LDSM4(b[0][0], b[0][1], b[1][0], b[1][1],
                          b_base + (uint32_t)((ks * 8) * 4));
                    #pragma unroll
                    for (int mt = 0; mt < 2; mt++)
                        #pragma unroll
                        for (int nt = 0; nt < 2; nt++)
                            MMA_TF32(cacc[mt][nt], a[mt], b[nt]);
                }
            }

            #pragma unroll
            for (int mt = 0; mt < 2; mt++) {
                int row0 = tm*64 + warp_m + mt*16 + g;
                #pragma unroll
                for (int nt = 0; nt < 2; nt++) {
                    int col = tn*64 + warp_n + nt*8 + tg*2;
                    float2 bb2 = *(const float2*)&bb[col];
                    float2 o0, o1;
                    o0.x = cacc[mt][nt][0] + bb2.x;  o0.y = cacc[mt][nt][1] + bb2.y;
                    o1.x = cacc[mt][nt][2] + bb2.x;  o1.y = cacc[mt][nt][3] + bb2.y;
                    *(float2*)&kvb[(size_t)row0 * 2048 + col]       = o0;
                    *(float2*)&kvb[(size_t)(row0 + 8) * 2048 + col] = o1;
                }
            }
            __syncthreads();
            if (tid == 0) flag_release(&g_flagA[tn]);
        }

        // ================= Phase B: attention =================
        {
            if (tid == 0) {
                unsigned tgt = 4u * (unsigned)i;
                while (flag_acquire(&g_flagA[h])      < tgt) { }
                while (flag_acquire(&g_flagA[16 + h]) < tgt) { }
            }
            __syncthreads();

            float* Ks   = sm;
            float* Vs   = sm + 16384;
            float* mbuf = sm + 32768;
            float* lbuf = mbuf + 256;

            const float* Kp = kvb + h * DH;
            const float* Vp = kvb + 1024 + h * DH;
            for (int idx = tid; idx < 256 * 16; idx += 256) {
                int r  = idx >> 4;
                int c4 = idx & 15;
                CP_ASYNC16(smaddr(Ks + r*64 + c4*4), Kp + (size_t)r*2048 + c4*4);
                CP_ASYNC16(smaddr(Vs + r*64 + c4*4), Vp + (size_t)r*2048 + c4*4);
            }
            CP_COMMIT();

            const float* Qr = q2 + (size_t)i * KW * ODIM + (size_t)(qt*32 + q) * 1024 + h * DH;
            ull qp[32];
            #pragma unroll
            for (int d4 = 0; d4 < 16; d4++) {
                ulonglong2 v = *(const ulonglong2*)(Qr + d4*4);
                qp[2*d4]   = v.x;
                qp[2*d4+1] = v.y;
            }

            CP_WAIT0();
            __syncthreads();

            float m = -1e30f, l = 0.f;
            ull accp[32];
            #pragma unroll
            for (int t = 0; t < 32; t++) accp[t] = 0ull;

            const int k0 = ck * 32;
            for (int kk = 0; kk < 32; kk++) {
                const float* Krow = Ks + (k0 + kk) * 64;
                ull s0 = 0ull, s1 = 0ull, s2 = 0ull, s3 = 0ull;
                #pragma unroll
                for (int d4 = 0; d4 < 16; d4 += 2) {
                    ulonglong2 a = *(const ulonglong2*)(Krow + d4*4);
                    ulonglong2 b = *(const ulonglong2*)(Krow + d4*4 + 4);
                    FMA2(s0, qp[2*d4+0], a.x, s0);
                    FMA2(s1, qp[2*d4+1], a.y, s1);
                    FMA2(s2, qp[2*d4+2], b.x, s2);
                    FMA2(s3, qp[2*d4+3], b.y, s3);
                }
                float a0,a1,b0,b1,c0,c1,d0,d1;
                UNPACK2(a0,a1,s0); UNPACK2(b0,b1,s1); UNPACK2(c0,c1,s2); UNPACK2(d0,d1,s3);
                float s = ((a0+a1)+(b0+b1)) + ((c0+c1)+(d0+d1));
                s *= 0.125f;

                if (s > m) {
                    float corr = __expf(m - s);
                    l *= corr;
                    ull cp; PACK2(cp, corr, corr);
                    #pragma unroll
                    for (int t = 0; t < 32; t++) MUL2(accp[t], accp[t], cp);
                    m = s;
                }
                float p = __expf(s - m);
                l += p;
                ull pp; PACK2(pp, p, p);
                const float* Vrow = Vs + (k0 + kk) * 64;
                #pragma unroll
                for (int d4 = 0; d4 < 16; d4 += 2) {
                    ulonglong2 a = *(const ulonglong2*)(Vrow + d4*4);
                    ulonglong2 b = *(const ulonglong2*)(Vrow + d4*4 + 4);
                    FMA2(accp[2*d4+0], pp, a.x, accp[2*d4+0]);
                    FMA2(accp[2*d4+1], pp, a.y, accp[2*d4+1]);
                    FMA2(accp[2*d4+2], pp, b.x, accp[2*d4+2]);
                    FMA2(accp[2*d4+3], pp, b.y, accp[2*d4+3]);
                }
            }
            __syncthreads();

            float* accbuf = sm;
            mbuf[tid] = m;
            lbuf[tid] = l;
            #pragma unroll
            for (int t = 0; t < 32; t++) {
                float f0, f1;
                UNPACK2(f0, f1, accp[t]);
                accbuf[tid*65 + 2*t]     = f0;
                accbuf[tid*65 + 2*t + 1] = f1;
            }
            __syncthreads();

            float mv[8], ev[8];
            float mg = -1e30f;
            #pragma unroll
            for (int cc = 0; cc < 8; cc++) { mv[cc] = mbuf[cc*32 + q]; mg = fmaxf(mg, mv[cc]); }
            float lg = 0.f;
            #pragma unroll
            for (int cc = 0; cc < 8; cc++) { ev[cc] = __expf(mv[cc] - mg); lg += lbuf[cc*32 + q] * ev[cc]; }
            float inv = 1.f / lg;

            float* Orow = stb + (size_t)(qt*32 + q) * 1024 + h * DH;
            #pragma unroll
            for (int j = 0; j < 8; j++) {
                int d = ck*8 + j;
                float o = 0.f;
                #pragma unroll
                for (int cc = 0; cc < 8; cc++)
                    o += accbuf[(cc*32 + q)*65 + d] * ev[cc];
                Orow[d] = o * inv;
            }
            __syncthreads();
            if (tid == 0) flag_release(&g_flagB[qt]);
        }
    }
}

// ---------------- host ----------------
extern "C" void kernel_launch(void* const* d_in, const int* in_sizes, int n_in,
                              void* d_out, int out_size)
{
    const float* path   = (const float*)d_in[0];
    const float* w_in1  = (const float*)d_in[1];
    const float* b_in1  = (const float*)d_in[2];
    const float* w_out1 = (const float*)d_in[3];
    const float* b_out1 = (const float*)d_in[4];
    const float* w_lin  = (const float*)d_in[5];
    const float* b_lin  = (const float*)d_in[6];
    const float* w_in2  = (const float*)d_in[7];
    const float* b_in2  = (const float*)d_in[8];
    const float* w_out2 = (const float*)d_in[9];
    const float* b_out2 = (const float*)d_in[10];

    float *qkv1, *x, *q2, *kv, *st, *wt, *wt2, *wcomb, *bcomb, *wkv, *bkv, *zb;
    __half *attn1h, *x16, *wcomb16, *win2q16;
    cudaGetSymbolAddress((void**)&qkv1,    g_qkv1);
    cudaGetSymbolAddress((void**)&attn1h,  g_attn1h);
    cudaGetSymbolAddress((void**)&x,       g_x);
    cudaGetSymbolAddress((void**)&x16,     g_x16);
    cudaGetSymbolAddress((void**)&q2,      g_q2);
    cudaGetSymbolAddress((void**)&kv,      g_kv);
    cudaGetSymbolAddress((void**)&st,      g_st);
    cudaGetSymbolAddress((void**)&wt,      g_wt);
    cudaGetSymbolAddress((void**)&wt2,     g_wt2);
    cudaGetSymbolAddress((void**)&wcomb,   g_wcomb);
    cudaGetSymbolAddress((void**)&wcomb16, g_wcomb16);
    cudaGetSymbolAddress((void**)&win2q16, g_win2q16);
    cudaGetSymbolAddress((void**)&bcomb,   g_bcomb);
    cudaGetSymbolAddress((void**)&wkv,     g_wkv);
    cudaGetSymbolAddress((void**)&bkv,     g_bkv);
    cudaGetSymbolAddress((void**)&zb,      g_zb);

    cudaFuncSetAttribute(attn_kernel,        cudaFuncAttributeMaxDynamicSharedMemorySize, ATTN_SMEM);
    cudaFuncSetAttribute(gemm_tf32<false>,   cudaFuncAttributeMaxDynamicSharedMemorySize, TF_SMEM);
    cudaFuncSetAttribute(gemm_fp16<false>,   cudaFuncAttributeMaxDynamicSharedMemorySize, H_SMEM);
    cudaFuncSetAttribute(gemm_fp16<true>,    cudaFuncAttributeMaxDynamicSharedMemorySize, H_SMEM);
    cudaFuncSetAttribute(recurrence_kernel,  cudaFuncAttributeMaxDynamicSharedMemorySize, REC_SMEM);
    cudaFuncSetAttribute(gemm_tf32<false>,   cudaFuncAttributePreferredSharedMemoryCarveout, 100);
    cudaFuncSetAttribute(gemm_fp16<false>,   cudaFuncAttributePreferredSharedMemoryCarveout, 100);
    cudaFuncSetAttribute(gemm_fp16<true>,    cudaFuncAttributePreferredSharedMemoryCarveout, 100);

    auto g64  = gemm_bias<64,64,16,4,4>;
    auto t32  = gemm_tf32<false>;
    auto h16  = gemm_fp16<false>;
    auto h16r = gemm_fp16<true>;

    const float* wkv2 = w_in2 + (size_t)ODIM * ODIM;
    const float* bkv2 = b_in2 + ODIM;

    // prologue prep
    prep_kernel<<<2052 + 128 + 256, 256>>>(w_out1, w_out2, w_lin, b_out1, b_lin,
                                           wkv2, b_out2, bkv2, wt, wt2, zb, bcomb, bkv);
    // weight folds (tf32)
    t32<<<dim3(DM/128, DM/128), 256, TF_SMEM>>>(w_lin, wt, zb, wcomb, DM, DM, DM);
    t32<<<dim3(DM/128, 2*ODIM/128), 256, TF_SMEM>>>(wkv2, wt2, zb, wkv, 2*ODIM, DM, DM);

    // fp16 weight shadows
    f2h_kernel<<<DM*DM/1024, 256>>>(wcomb, wcomb16, DM*DM);
    f2h_kernel<<<ODIM*DM/1024, 256>>>(w_in2, win2q16, ODIM*DM);

    // stage 1: QKV of every path row (tf32)
    t32<<<dim3(3*DM/128, SEQ/128), 256, TF_SMEM>>>(path, w_in1, b_in1, qkv1, SEQ, 3*DM, DM);

    // stage 2: batched window self-attention (fp32 math, fp16 output)
    attn_kernel<<<dim3(NH, KW/64, NWIN), 256, ATTN_SMEM>>>(
        qkv1,        (long long)STR * 3*DM, 3*DM,
        qkv1 + DM,   (long long)STR * 3*DM, 3*DM,
        qkv1 + 2*DM, (long long)STR * 3*DM, 3*DM,
        attn1h,      (long long)KW * DM,    DM,
        0.125f);

    // stage 3: fused outproj1 + linear + relu (fp16 MMA) -> x fp32 + x16
    h16r<<<dim3(ODIM/128, ROWS/128), 256, H_SMEM>>>(attn1h, wcomb16, bcomb, x, x16, ROWS, ODIM, DM);

    // stage 4a: bulk Q2 projections (fp16 MMA) -> q2 fp32
    h16<<<dim3(ODIM/128, ROWS/128), 256, H_SMEM>>>(x16, win2q16, b_in2, q2, ((__half*)0), ROWS, ODIM, ODIM);

    // stage 4b: persistent flag-synced recurrence (R10)
    recurrence_kernel<<<REC_NB, 256, REC_SMEM>>>(x, q2, wkv2, bkv2, wkv, bkv, kv, st);

    // final out-projection (exact fp32 -> d_out); last step wrote st[(NWIN-1)&1]
    g64<<<dim3(ODIM/64, KW/64), 256>>>(st + (size_t)((NWIN-1)&1) * KW * ODIM,
                                       w_out2, b_out2, (float*)d_out, KW, ODIM, ODIM);
}

// round 13
// speedup vs baseline: 1.2835x; 1.0946x over previous
#include <cuda_runtime.h>
#include <cuda_fp16.h>
#include <math.h>
#include <stdint.h>

// ---------------- problem constants ----------------
constexpr int SEQ  = 4096;
constexpr int DM   = 1024;
constexpr int ODIM = 1024;
constexpr int KW   = 256;
constexpr int STR  = 16;
constexpr int NH   = 16;
constexpr int DH   = 64;
constexpr int NWIN = (SEQ - KW) / STR;   // 240
constexpr int ROWS = NWIN * KW;          // 61440

typedef unsigned long long ull;

// packed fp32x2 helpers
#define PACK2(o, lo, hi)   asm("mov.b64 %0, {%1,%2};" : "=l"(o) : "f"(lo), "f"(hi))
#define UNPACK2(lo, hi, i) asm("mov.b64 {%0,%1}, %2;" : "=f"(lo), "=f"(hi) : "l"(i))
#define FMA2(d, a, b, c)   asm("fma.rn.f32x2 %0, %1, %2, %3;" : "=l"(d) : "l"(a), "l"(b), "l"(c))
#define MUL2(d, a, b)      asm("mul.rn.f32x2 %0, %1, %2;" : "=l"(d) : "l"(a), "l"(b))

__device__ __forceinline__ uint32_t smaddr(const void* p) {
    return (uint32_t)__cvta_generic_to_shared(p);
}

#define CP_ASYNC16(sm_u32, gptr) \
    asm volatile("cp.async.cg.shared.global [%0], [%1], 16;" :: "r"(sm_u32), "l"(gptr))
#define CP_COMMIT() asm volatile("cp.async.commit_group;")
#define CP_WAIT0()  asm volatile("cp.async.wait_group 0;")
#define CP_WAIT1()  asm volatile("cp.async.wait_group 1;")

#define LDSM4(r0, r1, r2, r3, addr) \
    asm volatile("ldmatrix.sync.aligned.m8n8.x4.shared.b16 {%0,%1,%2,%3}, [%4];" \
        : "=r"(r0), "=r"(r1), "=r"(r2), "=r"(r3) : "r"(addr))

#define MMA_TF32(c, a, b) \
    asm volatile("mma.sync.aligned.m16n8k8.row.col.f32.tf32.tf32.f32 " \
        "{%0,%1,%2,%3},{%4,%5,%6,%7},{%8,%9},{%0,%1,%2,%3};" \
        : "+f"((c)[0]), "+f"((c)[1]), "+f"((c)[2]), "+f"((c)[3]) \
        : "r"((a)[0]), "r"((a)[1]), "r"((a)[2]), "r"((a)[3]), "r"((b)[0]), "r"((b)[1]))

#define MMA_F16(c, a, b) \
    asm volatile("mma.sync.aligned.m16n8k16.row.col.f32.f16.f16.f32 " \
        "{%0,%1,%2,%3},{%4,%5,%6,%7},{%8,%9},{%0,%1,%2,%3};" \
        : "+f"((c)[0]), "+f"((c)[1]), "+f"((c)[2]), "+f"((c)[3]) \
        : "r"((a)[0]), "r"((a)[1]), "r"((a)[2]), "r"((a)[3]), "r"((b)[0]), "r"((b)[1]))

// release/acquire flag ops (L2-scope ordering; no CCTL.IVALL)
__device__ __forceinline__ void flag_release(unsigned* f) {
    unsigned old;
    asm volatile("atom.release.gpu.global.add.u32 %0, [%1], 1;" : "=r"(old) : "l"(f) : "memory");
}
__device__ __forceinline__ unsigned flag_acquire(unsigned* f) {
    unsigned v;
    asm volatile("ld.acquire.gpu.global.u32 %0, [%1];" : "=r"(v) : "l"(f) : "memory");
    return v;
}

// ---------------- scratch ----------------
__device__ float  g_qkv1[SEQ * 3 * DM];
__device__ __half g_attn1h[ROWS * DM];
__device__ float  g_x[ROWS * ODIM];
__device__ __half g_x16[ROWS * ODIM];
__device__ float  g_q2[ROWS * ODIM];
__device__ float  g_kv[2 * KW * 2 * ODIM];   // double-buffered by step parity
__device__ float  g_st[2 * KW * ODIM];       // fp32 state (final projection)
__device__ __half g_st16[2 * KW * ODIM];     // fp16 shadow (phase A input)
__device__ float  g_wt[DM * DM];
__device__ float  g_wt2[DM * DM];
__device__ float  g_wcomb[DM * DM];
__device__ __half g_wcomb16[DM * DM];
__device__ __half g_win2q16[ODIM * DM];
__device__ float  g_bcomb[DM];
__device__ float  g_wkv[2 * ODIM * DM];
__device__ __half g_wkvh[2 * ODIM * DM];     // fp16 folded KV weights
__device__ __half g_wkv2h[2 * ODIM * DM];    // fp16 original KV weights (i==1)
__device__ float  g_bkv[2 * ODIM];
__device__ float  g_zb[DM];

// persistent-kernel sync state (monotonic; replay-safe)
__device__ unsigned g_bar_arrive  = 0;
__device__ unsigned g_bar_release = 0;
__device__ unsigned g_flagA[32];
__device__ unsigned g_flagB[8];

// ================= TF32 tensor-core GEMM, 128x128 tiles, 3-stage cp.async =========
constexpr int TF_BK = 32;
constexpr int TF_LD = TF_BK + 4;
constexpr int TF_BUF = (128 + 128) * TF_LD;
constexpr int TF_SMEM = 3 * TF_BUF * (int)sizeof(float);  // 110592 B

template<bool RELU>
__global__ __launch_bounds__(256, 2)
void gemm_tf32(const float* __restrict__ A, const float* __restrict__ W,
               const float* __restrict__ bias, float* __restrict__ C,
               int M, int N, int K)
{
    extern __shared__ float smem[];
    const int tid    = threadIdx.x;
    const int lane   = tid & 31;
    const int warp   = tid >> 5;
    const int warp_m = (warp & 1) * 64;
    const int warp_n = (warp >> 1) * 32;
    const int bm     = blockIdx.y * 128;
    const int bn     = blockIdx.x * 128;

    const int ar = (lane & 7) + ((lane >> 3) & 1) * 8;
    const int ac = (lane >> 4) * 4;
    const int br = (lane & 7) + (lane >> 4) * 8;
    const int bc = ((lane >> 3) & 1) * 4;

    float c[4][4][4];
    #pragma unroll
    for (int i = 0; i < 4; i++)
        #pragma unroll
        for (int j = 0; j < 4; j++)
            #pragma unroll
            for (int r = 0; r < 4; r++) c[i][j][r] = 0.f;

    const int lr = tid >> 3;
    const int lc = tid & 7;

    auto issue = [&](int t) {
        const size_t ko = (size_t)t * TF_BK + lc * 4;
        float* As = smem + (t % 3) * TF_BUF;
        float* Bs = As + 128 * TF_LD;
        #pragma unroll
        for (int i = 0; i < 4; i++) {
            int r = lr + i * 32;
            CP_ASYNC16(smaddr(&As[r * TF_LD + lc * 4]), &A[(size_t)(bm + r) * K + ko]);
            CP_ASYNC16(smaddr(&Bs[r * TF_LD + lc * 4]), &W[(size_t)(bn + r) * K + ko]);
        }
        CP_COMMIT();
    };

    const int nk = K / TF_BK;
    issue(0);
    if (nk > 1) issue(1);

    for (int t = 0; t < nk; t++) {
        if (t == nk - 1) { CP_WAIT0(); } else { CP_WAIT1(); }
        __syncthreads();
        if (t + 2 < nk) issue(t + 2);

        const float* bufp = smem + (t % 3) * TF_BUF;
        const uint32_t a_base = smaddr(bufp + (warp_m + ar) * TF_LD + ac);
        const uint32_t b_base = smaddr(bufp + 128 * TF_LD + (warp_n + br) * TF_LD + bc);

        #pragma unroll
        for (int ks = 0; ks < 4; ks++) {
            uint32_t a[4][4], b[4][2];
            #pragma unroll
            for (int mt = 0; mt < 4; mt++)
                LDSM4(a[mt][0], a[mt][1], a[mt][2], a[mt][3],
                      a_base + (uint32_t)((mt * 16 * TF_LD + ks * 8) * 4));
            #pragma unroll
            for (int np = 0; np < 2; np++)
                LDSM4(b[2*np][0], b[2*np][1], b[2*np+1][0], b[2*np+1][1],
                      b_base + (uint32_t)((np * 16 * TF_LD + ks * 8) * 4));
            #pragma unroll
            for (int mt = 0; mt < 4; mt++)
                #pragma unroll
                for (int nt = 0; nt < 4; nt++)
                    MMA_TF32(c[mt][nt], a[mt], b[nt]);
        }
    }

    const int g  = lane >> 2;
    const int tg = lane & 3;
    #pragma unroll
    for (int mt = 0; mt < 4; mt++) {
        int row0 = bm + warp_m + mt * 16 + g;
        #pragma unroll
        for (int nt = 0; nt < 4; nt++) {
            int col = bn + warp_n + nt * 8 + tg * 2;
            float2 bb = *(const float2*)&bias[col];
            float2 o0, o1;
            o0.x = c[mt][nt][0] + bb.x;  o0.y = c[mt][nt][1] + bb.y;
            o1.x = c[mt][nt][2] + bb.x;  o1.y = c[mt][nt][3] + bb.y;
            if (RELU) {
                o0.x = fmaxf(o0.x, 0.f); o0.y = fmaxf(o0.y, 0.f);
                o1.x = fmaxf(o1.x, 0.f); o1.y = fmaxf(o1.y, 0.f);
            }
            *(float2*)&C[(size_t)row0 * N + col]       = o0;
            *(float2*)&C[(size_t)(row0 + 8) * N + col] = o1;
        }
    }
}

// ================= FP16 tensor-core GEMM, 128x128 tiles, 3-stage cp.async =========
constexpr int H_BK  = 32;
constexpr int H_LD  = H_BK + 8;              // 40 halfs = 80 B padded stride
constexpr int H_BUF = (128 + 128) * H_LD;
constexpr int H_SMEM = 3 * H_BUF * 2;        // 61440 B

template<bool RELU>
__global__ __launch_bounds__(256, 2)
void gemm_fp16(const __half* __restrict__ A, const __half* __restrict__ W,
               const float* __restrict__ bias, float* __restrict__ C,
               __half* __restrict__ C16, int M, int N, int K)
{
    extern __shared__ __half smh[];
    const int tid    = threadIdx.x;
    const int lane   = tid & 31;
    const int warp   = tid >> 5;
    const int warp_m = (warp & 1) * 64;
    const int warp_n = (warp >> 1) * 32;
    const int bm     = blockIdx.y * 128;
    const int bn     = blockIdx.x * 128;

    const int ar = (lane & 7) + ((lane >> 3) & 1) * 8;
    const int ac = (lane >> 4) * 8;
    const int br = (lane & 7) + (lane >> 4) * 8;
    const int bc = ((lane >> 3) & 1) * 8;

    float c[4][4][4];
    #pragma unroll
    for (int i = 0; i < 4; i++)
        #pragma unroll
        for (int j = 0; j < 4; j++)
            #pragma unroll
            for (int r = 0; r < 4; r++) c[i][j][r] = 0.f;

    const int cr = tid >> 1;
    const int cc = (tid & 1) * 2;

    auto issue = [&](int t) {
        const size_t ko = (size_t)t * H_BK;
        __half* As = smh + (t % 3) * H_BUF;
        __half* Bs = As + 128 * H_LD;
        #pragma unroll
        for (int j = 0; j < 2; j++) {
            int ch = cc + j;
            CP_ASYNC16(smaddr(&As[cr * H_LD + ch * 8]), &A[(size_t)(bm + cr) * K + ko + ch * 8]);
            CP_ASYNC16(smaddr(&Bs[cr * H_LD + ch * 8]), &W[(size_t)(bn + cr) * K + ko + ch * 8]);
        }
        CP_COMMIT();
    };

    const int nk = K / H_BK;
    issue(0);
    if (nk > 1) issue(1);

    for (int t = 0; t < nk; t++) {
        if (t == nk - 1) { CP_WAIT0(); } else { CP_WAIT1(); }
        __syncthreads();
        if (t + 2 < nk) issue(t + 2);

        const __half* bufp = smh + (t % 3) * H_BUF;
        const uint32_t a_base = smaddr(bufp + (warp_m + ar) * H_LD + ac);
        const uint32_t b_base = smaddr(bufp + 128 * H_LD + (warp_n + br) * H_LD + bc);

        #pragma unroll
        for (int ks = 0; ks < 2; ks++) {
            uint32_t a[4][4], b[4][2];
            #pragma unroll
            for (int mt = 0; mt < 4; mt++)
                LDSM4(a[mt][0], a[mt][1], a[mt][2], a[mt][3],
                      a_base + (uint32_t)((mt * 16 * H_LD + ks * 16) * 2));
            #pragma unroll
            for (int np = 0; np < 2; np++)
                LDSM4(b[2*np][0], b[2*np][1], b[2*np+1][0], b[2*np+1][1],
                      b_base + (uint32_t)((np * 16 * H_LD + ks * 16) * 2));
            #pragma unroll
            for (int mt = 0; mt < 4; mt++)
                #pragma unroll
                for (int nt = 0; nt < 4; nt++)
                    MMA_F16(c[mt][nt], a[mt], b[nt]);
        }
    }

    const int g  = lane >> 2;
    const int tg = lane & 3;
    #pragma unroll
    for (int mt = 0; mt < 4; mt++) {
        int row0 = bm + warp_m + mt * 16 + g;
        #pragma unroll
        for (int nt = 0; nt < 4; nt++) {
            int col = bn + warp_n + nt * 8 + tg * 2;
            float2 bb = *(const float2*)&bias[col];
            float2 o0, o1;
            o0.x = c[mt][nt][0] + bb.x;  o0.y = c[mt][nt][1] + bb.y;
            o1.x = c[mt][nt][2] + bb.x;  o1.y = c[mt][nt][3] + bb.y;
            if (RELU) {
                o0.x = fmaxf(o0.x, 0.f); o0.y = fmaxf(o0.y, 0.f);
                o1.x = fmaxf(o1.x, 0.f); o1.y = fmaxf(o1.y, 0.f);
            }
            *(float2*)&C[(size_t)row0 * N + col]       = o0;
            *(float2*)&C[(size_t)(row0 + 8) * N + col] = o1;
            if (C16) {
                __half2 h0 = __floats2half2_rn(o0.x, o0.y);
                __half2 h1 = __floats2half2_rn(o1.x, o1.y);
                *(__half2*)&C16[(size_t)row0 * N + col]       = h0;
                *(__half2*)&C16[(size_t)(row0 + 8) * N + col] = h1;
            }
        }
    }
}

// ================= exact FFMA2 SGEMM (final projection only) =================
template<int BM, int BN, int BK, int TM, int TN>
__global__ __launch_bounds__((BM/TM)*(BN/TN))
void gemm_bias(const float* __restrict__ A, const float* __restrict__ W,
               const float* __restrict__ bias, float* __restrict__ C,
               int M, int N, int K)
{
    constexpr int THREADS = (BM/TM)*(BN/TN);
    __shared__ __align__(16) float As[BK][BM];
    __shared__ __align__(16) float Bs[BK][BN];
    const int tid  = threadIdx.x;
    const int bm   = blockIdx.y * BM;
    const int bn   = blockIdx.x * BN;
    const int tcol = tid % (BN/TN);
    const int trow = tid / (BN/TN);

    ull acc2[TM][TN/2];
    #pragma unroll
    for (int i = 0; i < TM; i++)
        #pragma unroll
        for (int j = 0; j < TN/2; j++) acc2[i][j] = 0ull;

    constexpr int AF4 = BM * (BK/4);
    constexpr int BF4 = BN * (BK/4);

    for (int k0 = 0; k0 < K; k0 += BK) {
        #pragma unroll
        for (int i = tid; i < AF4; i += THREADS) {
            int r  = i / (BK/4);
            int c4 = i % (BK/4);
            float4 v = *(const float4*)&A[(size_t)(bm + r) * K + k0 + c4*4];
            As[c4*4+0][r] = v.x; As[c4*4+1][r] = v.y;
            As[c4*4+2][r] = v.z; As[c4*4+3][r] = v.w;
        }
        #pragma unroll
        for (int i = tid; i < BF4; i += THREADS) {
            int r  = i / (BK/4);
            int c4 = i % (BK/4);
            float4 v = *(const float4*)&W[(size_t)(bn + r) * K + k0 + c4*4];
            Bs[c4*4+0][r] = v.x; Bs[c4*4+1][r] = v.y;
            Bs[c4*4+2][r] = v.z; Bs[c4*4+3][r] = v.w;
        }
        __syncthreads();

        #pragma unroll
        for (int k = 0; k < BK; k++) {
            float ra[TM];
            #pragma unroll
            for (int i = 0; i < TM; i += 4) {
                float4 v = *(const float4*)&As[k][trow*TM + i];
                ra[i] = v.x; ra[i+1] = v.y; ra[i+2] = v.z; ra[i+3] = v.w;
            }
            ull ras[TM];
            #pragma unroll
            for (int i = 0; i < TM; i++) PACK2(ras[i], ra[i], ra[i]);

            ull rb2[TN/2];
            #pragma unroll
            for (int j4 = 0; j4 < TN/4; j4++) {
                ulonglong2 v = *(const ulonglong2*)&Bs[k][tcol*TN + j4*4];
                rb2[2*j4]   = v.x;
                rb2[2*j4+1] = v.y;
            }
            #pragma unroll
            for (int i = 0; i < TM; i++)
                #pragma unroll
                for (int j = 0; j < TN/2; j++)
                    FMA2(acc2[i][j], ras[i], rb2[j], acc2[i][j]);
        }
        __syncthreads();
    }

    #pragma unroll
    for (int i = 0; i < TM; i++) {
        size_t row = (size_t)(bm + trow*TM + i);
        float oc[TN];
        #pragma unroll
        for (int j = 0; j < TN/2; j++) UNPACK2(oc[2*j], oc[2*j+1], acc2[i][j]);
        #pragma unroll
        for (int j = 0; j < TN; j += 4) {
            int col = bn + tcol*TN + j;
            float4 b4 = *(const float4*)&bias[col];
            float4 o;
            o.x = oc[j+0] + b4.x;
            o.y = oc[j+1] + b4.y;
            o.z = oc[j+2] + b4.z;
            o.w = oc[j+3] + b4.w;
            *(float4*)&C[row * N + col] = o;
        }
    }
}

// ---------------- prep: transposes + zero + bias folds in ONE launch ----------------
__global__ __launch_bounds__(256)
void prep_kernel(const float* __restrict__ w_out1, const float* __restrict__ w_out2,
                 const float* __restrict__ w_lin,  const float* __restrict__ b_out1,
                 const float* __restrict__ b_lin,  const float* __restrict__ wkv2,
                 const float* __restrict__ b_out2, const float* __restrict__ bkv2,
                 float* __restrict__ wt, float* __restrict__ wt2, float* __restrict__ zb,
                 float* __restrict__ bcomb, float* __restrict__ bkv)
{
    const int b   = blockIdx.x;
    const int tid = threadIdx.x;

    if (b < 2048) {
        const float* in = (b < 1024) ? w_out1 : w_out2;
        float* out      = (b < 1024) ? wt : wt2;
        const int bb = b & 1023;
        const int bx = bb & 31, by = bb >> 5;
        __shared__ float tile[32][33];
        const int tx = tid & 31, ty = tid >> 5;
        #pragma unroll
        for (int j = 0; j < 32; j += 8)
            tile[ty + j][tx] = in[(size_t)(by*32 + ty + j) * DM + bx*32 + tx];
        __syncthreads();
        #pragma unroll
        for (int j = 0; j < 32; j += 8)
            out[(size_t)(bx*32 + ty + j) * DM + by*32 + tx] = tile[tx][ty + j];
    } else if (b < 2052) {
        zb[(b - 2048) * 256 + tid] = 0.f;
    } else {
        int bb = b - 2052;
        const float *W, *b1, *b2;
        float* out;
        if (bb < 128) { W = w_lin; b1 = b_out1; b2 = b_lin; out = bcomb; }
        else          { bb -= 128; W = wkv2; b1 = b_out2; b2 = bkv2; out = bkv; }
        const int n = bb * 8 + (tid >> 5);
        const int lane = tid & 31;
        float s = 0.f;
        for (int j = lane; j < DM; j += 32) s = fmaf(W[(size_t)n * DM + j], b1[j], s);
        #pragma unroll
        for (int o = 16; o; o >>= 1) s += __shfl_xor_sync(0xffffffffu, s, o);
        if (lane == 0) out[n] = s + b2[n];
    }
}

// f32 -> f16 convert (float4 granularity)
__global__ void f2h_kernel(const float* __restrict__ in, __half* __restrict__ out, int n)
{
    int i = (blockIdx.x * blockDim.x + threadIdx.x) * 4;
    if (i < n) {
        float4 v = *(const float4*)&in[i];
        *(__half2*)&out[i]     = __floats2half2_rn(v.x, v.y);
        *(__half2*)&out[i + 2] = __floats2half2_rn(v.z, v.w);
    }
}

// ---------------- flash-style attention (stage 2; fp16 output) ----------------
constexpr int ATTN_SMEM = (2 * KW * DH + 2 * 256) * (int)sizeof(float); // 133120 B

__global__ __launch_bounds__(256)
void attn_kernel(const float* __restrict__ qbase, long long q_ws, int q_rs,
                 const float* __restrict__ kbase, long long k_ws, int k_rs,
                 const float* __restrict__ vbase, long long v_ws, int v_rs,
                 __half* __restrict__ obase,      long long o_ws, int o_rs,
                 float scale)
{
    extern __shared__ float sm[];
    float* Ks   = sm;
    float* Vs   = sm + KW * DH;
    float* mbuf = sm + 2 * KW * DH;
    float* lbuf = mbuf + 256;

    const int h  = blockIdx.x;
    const int qt = blockIdx.y;
    const int w  = blockIdx.z;
    const int tid = threadIdx.x;

    const float* Kp = kbase + (size_t)w * k_ws + h * DH;
    const float* Vp = vbase + (size_t)w * v_ws + h * DH;

    for (int idx = tid; idx < KW * (DH/4); idx += 256) {
        int r  = idx >> 4;
        int c4 = idx & 15;
        CP_ASYNC16(smaddr(Ks + r * DH + c4*4), Kp + (size_t)r * k_rs + c4*4);
        CP_ASYNC16(smaddr(Vs + r * DH + c4*4), Vp + (size_t)r * v_rs + c4*4);
    }
    CP_COMMIT();

    const int q = tid & 63;
    const int c = tid >> 6;
    const int qrow = qt * 64 + q;

    const float* Qr = qbase + (size_t)w * q_ws + (size_t)qrow * q_rs + h * DH;
    ull qp[DH/2];
    #pragma unroll
    for (int d4 = 0; d4 < 16; d4++) {
        ulonglong2 v = *(const ulonglong2*)(Qr + d4*4);
        qp[2*d4]   = v.x;
        qp[2*d4+1] = v.y;
    }

    CP_WAIT0();
    __syncthreads();

    float m = -1e30f, l = 0.f;
    ull accp[DH/2];
    #pragma unroll
    for (int t = 0; t < DH/2; t++) accp[t] = 0ull;

    const int k0 = c * 64;
    for (int kk = 0; kk < 64; kk++) {
        const float* Krow = Ks + (k0 + kk) * DH;
        ull s0 = 0ull, s1 = 0ull, s2 = 0ull, s3 = 0ull;
        #pragma unroll
        for (int d4 = 0; d4 < 16; d4 += 2) {
            ulonglong2 a = *(const ulonglong2*)(Krow + d4*4);
            ulonglong2 b = *(const ulonglong2*)(Krow + d4*4 + 4);
            FMA2(s0, qp[2*d4+0], a.x, s0);
            FMA2(s1, qp[2*d4+1], a.y, s1);
            FMA2(s2, qp[2*d4+2], b.x, s2);
            FMA2(s3, qp[2*d4+3], b.y, s3);
        }
        float a0,a1,b0,b1,c0,c1,d0,d1;
        UNPACK2(a0,a1,s0); UNPACK2(b0,b1,s1); UNPACK2(c0,c1,s2); UNPACK2(d0,d1,s3);
        float s = ((a0+a1)+(b0+b1)) + ((c0+c1)+(d0+d1));
        s *= scale;

        if (s > m) {
            float corr = __expf(m - s);
            l *= corr;
            ull cp; PACK2(cp, corr, corr);
            #pragma unroll
            for (int t = 0; t < DH/2; t++) MUL2(accp[t], accp[t], cp);
            m = s;
        }
        float p = __expf(s - m);
        l += p;
        ull pp; PACK2(pp, p, p);
        const float* Vrow = Vs + (k0 + kk) * DH;
        #pragma unroll
        for (int d4 = 0; d4 < 16; d4 += 2) {
            ulonglong2 a = *(const ulonglong2*)(Vrow + d4*4);
            ulonglong2 b = *(const ulonglong2*)(Vrow + d4*4 + 4);
            FMA2(accp[2*d4+0], pp, a.x, accp[2*d4+0]);
            FMA2(accp[2*d4+1], pp, a.y, accp[2*d4+1]);
            FMA2(accp[2*d4+2], pp, b.x, accp[2*d4+2]);
            FMA2(accp[2*d4+3], pp, b.y, accp[2*d4+3]);
        }
    }
    __syncthreads();

    float* accbuf = Ks;
    mbuf[tid] = m;
    lbuf[tid] = l;
    #pragma unroll
    for (int d4 = 0; d4 < 16; d4++)
        *(ulonglong2*)(accbuf + (size_t)tid * DH + d4*4) =
            make_ulonglong2(accp[2*d4], accp[2*d4+1]);
    __syncthreads();

    float m0 = mbuf[q], m1 = mbuf[64+q], m2 = mbuf[128+q], m3 = mbuf[192+q];
    float mg = fmaxf(fmaxf(m0, m1), fmaxf(m2, m3));
    float e0 = __expf(m0 - mg), e1 = __expf(m1 - mg);
    float e2 = __expf(m2 - mg), e3 = __expf(m3 - mg);
    float lg = lbuf[q]*e0 + lbuf[64+q]*e1 + lbuf[128+q]*e2 + lbuf[192+q]*e3;
    float inv = 1.f / lg;

    __half* Or = obase + (size_t)w * o_ws + (size_t)qrow * o_rs + h * DH;
    #pragma unroll
    for (int d = c*16; d < c*16 + 16; d += 2) {
        float oa = accbuf[(size_t)(0*64+q)*DH + d] * e0
                 + accbuf[(size_t)(1*64+q)*DH + d] * e1
                 + accbuf[(size_t)(2*64+q)*DH + d] * e2
                 + accbuf[(size_t)(3*64+q)*DH + d] * e3;
        float ob = accbuf[(size_t)(0*64+q)*DH + d+1] * e0
                 + accbuf[(size_t)(1*64+q)*DH + d+1] * e1
                 + accbuf[(size_t)(2*64+q)*DH + d+1] * e2
                 + accbuf[(size_t)(3*64+q)*DH + d+1] * e3;
        *(__half2*)&Or[d] = __floats2half2_rn(oa * inv, ob * inv);
    }
}

// ================= persistent recurrence kernel (fp16 phase A, BK=128 halfs) ======
constexpr int REC_NB   = 128;
constexpr int REC_SMEM = (32768 + 512) * (int)sizeof(float);   // 133120 B
constexpr int RH_BK  = 128;                       // halfs per k-tile
constexpr int RH_LD  = RH_BK + 8;                 // 136 halfs = 272 B (odd*16B -> conflict-free)
constexpr int RH_BUF = (64 + 64) * RH_LD;         // 17408 halfs per stage (34816 B; x3 = 104448 B)

__device__ __forceinline__ void grid_bar(unsigned base, unsigned bar_id)
{
    __syncthreads();
    if (threadIdx.x == 0) {
        __threadfence();
        unsigned a = atomicAdd(&g_bar_arrive, 1u);
        if ((a & (REC_NB - 1u)) == (REC_NB - 1u)) {
            atomicAdd(&g_bar_release, 1u);
        } else {
            while (*(volatile unsigned*)&g_bar_release - base < bar_id) { }
        }
        __threadfence();
    }
    __syncthreads();
}

__global__ __launch_bounds__(256)
void recurrence_kernel(const __half* __restrict__ x16,
                       const float* __restrict__ q2,
                       const __half* __restrict__ wkv2h, const float* __restrict__ bkv2,
                       const __half* __restrict__ wkvh,  const float* __restrict__ bkvF,
                       float* __restrict__ kv, float* __restrict__ st,
                       __half* __restrict__ st16)
{
    extern __shared__ float sm[];
    __half* smh = (__half*)sm;
    const int tid = threadIdx.x;
    const int bid = blockIdx.x;

    __shared__ unsigned s_base;
    if (tid == 0) s_base = *(volatile unsigned*)&g_bar_release;
    __syncthreads();
    const unsigned base = s_base;

    if (bid == 0) {
        if (tid < 32)              g_flagA[tid]      = 0;
        else if (tid < 40)         g_flagB[tid - 32] = 0;
    }
    grid_bar(base, 1);

    const int lane = tid & 31, warp = tid >> 5;
    const int g = lane >> 2, tg = lane & 3;
    const int warp_m = (warp & 1) * 32;
    const int warp_n = (warp >> 1) * 16;
    const int tm = bid >> 5;            // 0..3   A: M-tile
    const int tn = bid & 31;            // 0..31  A: N-stripe of kv

    // ldmatrix b16 address components (units: halfs)
    const int ar  = (lane & 7) + ((lane >> 3) & 1) * 8;
    const int ach = (lane >> 4) * 8;
    const int br  = (lane & 7) + (lane >> 4) * 8;
    const int bch = ((lane >> 3) & 1) * 8;

    const int h  = bid >> 3;            // 0..15  B: head
    const int qt = bid & 7;             // 0..7   B: q row-block
    const int q  = tid & 31;
    const int ck = tid >> 5;

    for (int i = 1; i < NWIN; i++) {
        float*  kvb      = kv   + (size_t)(i & 1) * KW * 2 * ODIM;
        float*  stb      = st   + (size_t)(i & 1) * KW * ODIM;
        __half* st16b    = st16 + (size_t)(i & 1) * KW * ODIM;
        const __half* st16prev = st16 + (size_t)((i - 1) & 1) * KW * ODIM;

        // ===== Phase A: KV projection (fp16 MMA, BK=128 halfs, 8 iters, 3-stage) =====
        {
            if (i > 1 && tid == 0) {
                unsigned tgt = 16u * (unsigned)(i - 1);
                while (flag_acquire(&g_flagB[2*tm])     < tgt) { }
                while (flag_acquire(&g_flagB[2*tm + 1]) < tgt) { }
            }
            __syncthreads();

            const __half* A  = (i == 1) ? x16   : st16prev;
            const __half* W  = (i == 1) ? wkv2h : wkvh;
            const float*  bb = (i == 1) ? bkv2  : bkvF;

            float cacc[2][2][4];
            #pragma unroll
            for (int mt = 0; mt < 2; mt++)
                #pragma unroll
                for (int nt = 0; nt < 2; nt++)
                    #pragma unroll
                    for (int r = 0; r < 4; r++) cacc[mt][nt][r] = 0.f;

            const int crow = tid >> 2;          // 0..63
            const int cch  = (tid & 3) * 4;     // chunk base (of 16 chunks of 8 halfs)

            auto issue = [&](int t) {
                size_t ko = (size_t)t * RH_BK;
                __half* As = smh + (t % 3) * RH_BUF;
                __half* Bs = As + 64 * RH_LD;
                #pragma unroll
                for (int j = 0; j < 4; j++) {
                    int ch = cch + j;
                    CP_ASYNC16(smaddr(&As[crow * RH_LD + ch*8]), &A[(size_t)(tm*64 + crow) * 1024 + ko + ch*8]);
                    CP_ASYNC16(smaddr(&Bs[crow * RH_LD + ch*8]), &W[(size_t)(tn*64 + crow) * 1024 + ko + ch*8]);
                }
                CP_COMMIT();
            };

            issue(0);
            issue(1);
            for (int t = 0; t < 8; t++) {
                if (t == 7) { CP_WAIT0(); } else { CP_WAIT1(); }
                __syncthreads();
                if (t + 2 < 8) issue(t + 2);

                const __half* bufp = smh + (t % 3) * RH_BUF;
                const uint32_t a_base = smaddr(bufp + (warp_m + ar) * RH_LD + ach);
                const uint32_t b_base = smaddr(bufp + 64 * RH_LD + (warp_n + br) * RH_LD + bch);

                #pragma unroll
                for (int ks = 0; ks < 8; ks++) {
                    uint32_t a[2][4], b[2][2];
                    #pragma unroll
                    for (int mt = 0; mt < 2; mt++)
                        LDSM4(a[mt][0], a[mt][1], a[mt][2], a[mt][3],
                              a_base + (uint32_t)((mt * 16 * RH_LD + ks * 16) * 2));
                    LDSM4(b[0][0], b[0][1], b[1][0], b[1][1],
                          b_base + (uint32_t)((ks * 16) * 2));
                    #pragma unroll
                    for (int mt = 0; mt < 2; mt++)
                        #pragma unroll
                        for (int nt = 0; nt < 2; nt++)
                            MMA_F16(cacc[mt][nt], a[mt], b[nt]);
                }
            }

            #pragma unroll
            for (int mt = 0; mt < 2; mt++) {
                int row0 = tm*64 + warp_m + mt*16 + g;
                #pragma unroll
                for (int nt = 0; nt < 2; nt++) {
                    int col = tn*64 + warp_n + nt*8 + tg*2;
                    float2 bb2 = *(const float2*)&bb[col];
                    float2 o0, o1;
                    o0.x = cacc[mt][nt][0] + bb2.x;  o0.y = cacc[mt][nt][1] + bb2.y;
                    o1.x = cacc[mt][nt][2] + bb2.x;  o1.y = cacc[mt][nt][3] + bb2.y;
                    *(float2*)&kvb[(size_t)row0 * 2048 + col]       = o0;
                    *(float2*)&kvb[(size_t)(row0 + 8) * 2048 + col] = o1;
                }
            }
            __syncthreads();
            if (tid == 0) flag_release(&g_flagA[tn]);
        }

        // ================= Phase B: attention (fp32 math) =================
        {
            if (tid == 0) {
                unsigned tgt = 4u * (unsigned)i;
                while (flag_acquire(&g_flagA[h])      < tgt) { }
                while (flag_acquire(&g_flagA[16 + h]) < tgt) { }
            }
            __syncthreads();

            float* Ks   = sm;
            float* Vs   = sm + 16384;
            float* mbuf = sm + 32768;
            float* lbuf = mbuf + 256;

            const float* Kp = kvb + h * DH;
            const float* Vp = kvb + 1024 + h * DH;
            for (int idx = tid; idx < 256 * 16; idx += 256) {
                int r  = idx >> 4;
                int c4 = idx & 15;
                CP_ASYNC16(smaddr(Ks + r*64 + c4*4), Kp + (size_t)r*2048 + c4*4);
                CP_ASYNC16(smaddr(Vs + r*64 + c4*4), Vp + (size_t)r*2048 + c4*4);
            }
            CP_COMMIT();

            const float* Qr = q2 + (size_t)i * KW * ODIM + (size_t)(qt*32 + q) * 1024 + h * DH;
            ull qp[32];
            #pragma unroll
            for (int d4 = 0; d4 < 16; d4++) {
                ulonglong2 v = *(const ulonglong2*)(Qr + d4*4);
                qp[2*d4]   = v.x;
                qp[2*d4+1] = v.y;
            }

            CP_WAIT0();
            __syncthreads();

            float m = -1e30f, l = 0.f;
            ull accp[32];
            #pragma unroll
            for (int t = 0; t < 32; t++) accp[t] = 0ull;

            const int k0 = ck * 32;
            for (int kk = 0; kk < 32; kk++) {
                const float* Krow = Ks + (k0 + kk) * 64;
                ull s0 = 0ull, s1 = 0ull, s2 = 0ull, s3 = 0ull;
                #pragma unroll
                for (int d4 = 0; d4 < 16; d4 += 2) {
                    ulonglong2 a = *(const ulonglong2*)(Krow + d4*4);
                    ulonglong2 b = *(const ulonglong2*)(Krow + d4*4 + 4);
                    FMA2(s0, qp[2*d4+0], a.x, s0);
                    FMA2(s1, qp[2*d4+1], a.y, s1);
                    FMA2(s2, qp[2*d4+2], b.x, s2);
                    FMA2(s3, qp[2*d4+3], b.y, s3);
                }
                float a0,a1,b0,b1,c0,c1,d0,d1;
                UNPACK2(a0,a1,s0); UNPACK2(b0,b1,s1); UNPACK2(c0,c1,s2); UNPACK2(d0,d1,s3);
                float s = ((a0+a1)+(b0+b1)) + ((c0+c1)+(d0+d1));
                s *= 0.125f;

                if (s > m) {
                    float corr = __expf(m - s);
                    l *= corr;
                    ull cp; PACK2(cp, corr, corr);
                    #pragma unroll
                    for (int t = 0; t < 32; t++) MUL2(accp[t], accp[t], cp);
                    m = s;
                }
                float p = __expf(s - m);
                l += p;
                ull pp; PACK2(pp, p, p);
                const float* Vrow = Vs + (k0 + kk) * 64;
                #pragma unroll
                for (int d4 = 0; d4 < 16; d4 += 2) {
                    ulonglong2 a = *(const ulonglong2*)(Vrow + d4*4);
                    ulonglong2 b = *(const ulonglong2*)(Vrow + d4*4 + 4);
                    FMA2(accp[2*d4+0], pp, a.x, accp[2*d4+0]);
                    FMA2(accp[2*d4+1], pp, a.y, accp[2*d4+1]);
                    FMA2(accp[2*d4+2], pp, b.x, accp[2*d4+2]);
                    FMA2(accp[2*d4+3], pp, b.y, accp[2*d4+3]);
                }
            }
            __syncthreads();

            float* accbuf = sm;
            mbuf[tid] = m;
            lbuf[tid] = l;
            #pragma unroll
            for (int t = 0; t < 32; t++) {
                float f0, f1;
                UNPACK2(f0, f1, accp[t]);
                accbuf[tid*65 + 2*t]     = f0;
                accbuf[tid*65 + 2*t + 1] = f1;
            }
            __syncthreads();

            float mv[8], ev[8];
            float mg = -1e30f;
            #pragma unroll
            for (int cc = 0; cc < 8; cc++) { mv[cc] = mbuf[cc*32 + q]; mg = fmaxf(mg, mv[cc]); }
            float lg = 0.f;
            #pragma unroll
            for (int cc = 0; cc < 8; cc++) { ev[cc] = __expf(mv[cc] - mg); lg += lbuf[cc*32 + q] * ev[cc]; }
            float inv = 1.f / lg;

            float*  Orow  = stb   + (size_t)(qt*32 + q) * 1024 + h * DH;
            __half* Orow2 = st16b + (size_t)(qt*32 + q) * 1024 + h * DH;
            #pragma unroll
            for (int j = 0; j < 8; j += 2) {
                int d = ck*8 + j;
                float oa = 0.f, ob = 0.f;
                #pragma unroll
                for (int cc = 0; cc < 8; cc++) {
                    oa += accbuf[(cc*32 + q)*65 + d]     * ev[cc];
                    ob += accbuf[(cc*32 + q)*65 + d + 1] * ev[cc];
                }
                oa *= inv; ob *= inv;
                Orow[d]     = oa;
                Orow[d + 1] = ob;
                *(__half2*)&Orow2[d] = __floats2half2_rn(oa, ob);
            }
            __syncthreads();
            if (tid == 0) flag_release(&g_flagB[qt]);
        }
    }
}

// ---------------- host ----------------
extern "C" void kernel_launch(void* const* d_in, const int* in_sizes, int n_in,
                              void* d_out, int out_size)
{
    const float* path   = (const float*)d_in[0];
    const float* w_in1  = (const float*)d_in[1];
    const float* b_in1  = (const float*)d_in[2];
    const float* w_out1 = (const float*)d_in[3];
    const float* b_out1 = (const float*)d_in[4];
    const float* w_lin  = (const float*)d_in[5];
    const float* b_lin  = (const float*)d_in[6];
    const float* w_in2  = (const float*)d_in[7];
    const float* b_in2  = (const float*)d_in[8];
    const float* w_out2 = (const float*)d_in[9];
    const float* b_out2 = (const float*)d_in[10];

    float *qkv1, *x, *q2, *kv, *st, *wt, *wt2, *wcomb, *bcomb, *wkv, *bkv, *zb;
    __half *attn1h, *x16, *wcomb16, *win2q16, *wkvh, *wkv2h, *st16;
    cudaGetSymbolAddress((void**)&qkv1,    g_qkv1);
    cudaGetSymbolAddress((void**)&attn1h,  g_attn1h);
    cudaGetSymbolAddress((void**)&x,       g_x);
    cudaGetSymbolAddress((void**)&x16,     g_x16);
    cudaGetSymbolAddress((void**)&q2,      g_q2);
    cudaGetSymbolAddress((void**)&kv,      g_kv);
    cudaGetSymbolAddress((void**)&st,      g_st);
    cudaGetSymbolAddress((void**)&st16,    g_st16);
    cudaGetSymbolAddress((void**)&wt,      g_wt);
    cudaGetSymbolAddress((void**)&wt2,     g_wt2);
    cudaGetSymbolAddress((void**)&wcomb,   g_wcomb);
    cudaGetSymbolAddress((void**)&wcomb16, g_wcomb16);
    cudaGetSymbolAddress((void**)&win2q16, g_win2q16);
    cudaGetSymbolAddress((void**)&bcomb,   g_bcomb);
    cudaGetSymbolAddress((void**)&wkv,     g_wkv);
    cudaGetSymbolAddress((void**)&wkvh,    g_wkvh);
    cudaGetSymbolAddress((void**)&wkv2h,   g_wkv2h);
    cudaGetSymbolAddress((void**)&bkv,     g_bkv);
    cudaGetSymbolAddress((void**)&zb,      g_zb);

    cudaFuncSetAttribute(attn_kernel,        cudaFuncAttributeMaxDynamicSharedMemorySize, ATTN_SMEM);
    cudaFuncSetAttribute(gemm_tf32<false>,   cudaFuncAttributeMaxDynamicSharedMemorySize, TF_SMEM);
    cudaFuncSetAttribute(gemm_fp16<false>,   cudaFuncAttributeMaxDynamicSharedMemorySize, H_SMEM);
    cudaFuncSetAttribute(gemm_fp16<true>,    cudaFuncAttributeMaxDynamicSharedMemorySize, H_SMEM);
    cudaFuncSetAttribute(recurrence_kernel,  cudaFuncAttributeMaxDynamicSharedMemorySize, REC_SMEM);
    cudaFuncSetAttribute(gemm_tf32<false>,   cudaFuncAttributePreferredSharedMemoryCarveout, 100);
    cudaFuncSetAttribute(gemm_fp16<false>,   cudaFuncAttributePreferredSharedMemoryCarveout, 100);
    cudaFuncSetAttribute(gemm_fp16<true>,    cudaFuncAttributePreferredSharedMemoryCarveout, 100);

    auto g64  = gemm_bias<64,64,16,4,4>;
    auto t32  = gemm_tf32<false>;
    auto h16  = gemm_fp16<false>;
    auto h16r = gemm_fp16<true>;

    const float* wkv2 = w_in2 + (size_t)ODIM * ODIM;
    const float* bkv2 = b_in2 + ODIM;

    // prologue prep
    prep_kernel<<<2052 + 128 + 256, 256>>>(w_out1, w_out2, w_lin, b_out1, b_lin,
                                           wkv2, b_out2, bkv2, wt, wt2, zb, bcomb, bkv);
    // weight folds (tf32)
    t32<<<dim3(DM/128, DM/128), 256, TF_SMEM>>>(w_lin, wt, zb, wcomb, DM, DM, DM);
    t32<<<dim3(DM/128, 2*ODIM/128), 256, TF_SMEM>>>(wkv2, wt2, zb, wkv, 2*ODIM, DM, DM);

    // fp16 weight shadows
    f2h_kernel<<<DM*DM/1024, 256>>>(wcomb, wcomb16, DM*DM);
    f2h_kernel<<<ODIM*DM/1024, 256>>>(w_in2, win2q16, ODIM*DM);
    f2h_kernel<<<2*ODIM*DM/1024, 256>>>(wkv, wkvh, 2*ODIM*DM);
    f2h_kernel<<<2*ODIM*DM/1024, 256>>>(wkv2, wkv2h, 2*ODIM*DM);

    // stage 1: QKV of every path row (tf32)
    t32<<<dim3(3*DM/128, SEQ/128), 256, TF_SMEM>>>(path, w_in1, b_in1, qkv1, SEQ, 3*DM, DM);

    // stage 2: batched window self-attention (fp32 math, fp16 output)
    attn_kernel<<<dim3(NH, KW/64, NWIN), 256, ATTN_SMEM>>>(
        qkv1,        (long long)STR * 3*DM, 3*DM,
        qkv1 + DM,   (long long)STR * 3*DM, 3*DM,
        qkv1 + 2*DM, (long long)STR * 3*DM, 3*DM,
        attn1h,      (long long)KW * DM,    DM,
        0.125f);

    // stage 3: fused outproj1 + linear + relu (fp16 MMA) -> x fp32 + x16
    h16r<<<dim3(ODIM/128, ROWS/128), 256, H_SMEM>>>(attn1h, wcomb16, bcomb, x, x16, ROWS, ODIM, DM);

    // stage 4a: bulk Q2 projections (fp16 MMA) -> q2 fp32
    h16<<<dim3(ODIM/128, ROWS/128), 256, H_SMEM>>>(x16, win2q16, b_in2, q2, ((__half*)0), ROWS, ODIM, ODIM);

    // stage 4b: persistent recurrence (fp16 phase A)
    recurrence_kernel<<<REC_NB, 256, REC_SMEM>>>(x16, q2, wkv2h, bkv2, wkvh, bkv, kv, st, st16);

    // final out-projection (exact fp32 -> d_out); last step wrote st[(NWIN-1)&1]
    g64<<<dim3(ODIM/64, KW/64), 256>>>(st + (size_t)((NWIN-1)&1) * KW * ODIM,
                                       w_out2, b_out2, (float*)d_out, KW, ODIM, ODIM);
}

// round 14
// speedup vs baseline: 1.7258x; 1.3446x over previous
#include <cuda_runtime.h>
#include <cuda_fp16.h>
#include <math.h>
#include <stdint.h>

// ---------------- problem constants ----------------
constexpr int SEQ  = 4096;
constexpr int DM   = 1024;
constexpr int ODIM = 1024;
constexpr int KW   = 256;
constexpr int STR  = 16;
constexpr int NH   = 16;
constexpr int DH   = 64;
constexpr int NWIN = (SEQ - KW) / STR;   // 240
constexpr int ROWS = NWIN * KW;          // 61440

typedef unsigned long long ull;

// packed fp32x2 helpers
#define PACK2(o, lo, hi)   asm("mov.b64 %0, {%1,%2};" : "=l"(o) : "f"(lo), "f"(hi))
#define UNPACK2(lo, hi, i) asm("mov.b64 {%0,%1}, %2;" : "=f"(lo), "=f"(hi) : "l"(i))
#define FMA2(d, a, b, c)   asm("fma.rn.f32x2 %0, %1, %2, %3;" : "=l"(d) : "l"(a), "l"(b), "l"(c))
#define MUL2(d, a, b)      asm("mul.rn.f32x2 %0, %1, %2;" : "=l"(d) : "l"(a), "l"(b))

__device__ __forceinline__ uint32_t smaddr(const void* p) {
    return (uint32_t)__cvta_generic_to_shared(p);
}
__device__ __forceinline__ uint32_t pkh2(float x, float y) {
    __half2 h = __floats2half2_rn(x, y);
    return *(uint32_t*)&h;
}

#define CP_ASYNC16(sm_u32, gptr) \
    asm volatile("cp.async.cg.shared.global [%0], [%1], 16;" :: "r"(sm_u32), "l"(gptr))
#define CP_COMMIT() asm volatile("cp.async.commit_group;")
#define CP_WAIT0()  asm volatile("cp.async.wait_group 0;")
#define CP_WAIT1()  asm volatile("cp.async.wait_group 1;")

#define LDSM4(r0, r1, r2, r3, addr) \
    asm volatile("ldmatrix.sync.aligned.m8n8.x4.shared.b16 {%0,%1,%2,%3}, [%4];" \
        : "=r"(r0), "=r"(r1), "=r"(r2), "=r"(r3) : "r"(addr))
#define LDSM4T(r0, r1, r2, r3, addr) \
    asm volatile("ldmatrix.sync.aligned.m8n8.x4.trans.shared.b16 {%0,%1,%2,%3}, [%4];" \
        : "=r"(r0), "=r"(r1), "=r"(r2), "=r"(r3) : "r"(addr))

#define MMA_TF32(c, a, b) \
    asm volatile("mma.sync.aligned.m16n8k8.row.col.f32.tf32.tf32.f32 " \
        "{%0,%1,%2,%3},{%4,%5,%6,%7},{%8,%9},{%0,%1,%2,%3};" \
        : "+f"((c)[0]), "+f"((c)[1]), "+f"((c)[2]), "+f"((c)[3]) \
        : "r"((a)[0]), "r"((a)[1]), "r"((a)[2]), "r"((a)[3]), "r"((b)[0]), "r"((b)[1]))

#define MMA_F16(c, a, b) \
    asm volatile("mma.sync.aligned.m16n8k16.row.col.f32.f16.f16.f32 " \
        "{%0,%1,%2,%3},{%4,%5,%6,%7},{%8,%9},{%0,%1,%2,%3};" \
        : "+f"((c)[0]), "+f"((c)[1]), "+f"((c)[2]), "+f"((c)[3]) \
        : "r"((a)[0]), "r"((a)[1]), "r"((a)[2]), "r"((a)[3]), "r"((b)[0]), "r"((b)[1]))

// release/acquire flag ops
__device__ __forceinline__ void flag_release(unsigned* f) {
    unsigned old;
    asm volatile("atom.release.gpu.global.add.u32 %0, [%1], 1;" : "=r"(old) : "l"(f) : "memory");
}
__device__ __forceinline__ unsigned flag_acquire(unsigned* f) {
    unsigned v;
    asm volatile("ld.acquire.gpu.global.u32 %0, [%1];" : "=r"(v) : "l"(f) : "memory");
    return v;
}

// ---------------- scratch ----------------
__device__ float  g_qkv1[SEQ * 3 * DM];      // fp32 (unused output of stage1; scratch)
__device__ __half g_qkv1h[SEQ * 3 * DM];
__device__ __half g_pathh[SEQ * DM];
__device__ __half g_win1h[3 * DM * DM];
__device__ __half g_attn1h[ROWS * DM];
__device__ float  g_x[ROWS * ODIM];
__device__ __half g_x16[ROWS * ODIM];
__device__ float  g_q2[ROWS * ODIM];
__device__ float  g_kv[2 * KW * 2 * ODIM];
__device__ float  g_st[2 * KW * ODIM];
__device__ __half g_st16[2 * KW * ODIM];
__device__ float  g_wt[DM * DM];
__device__ float  g_wt2[DM * DM];
__device__ float  g_wcomb[DM * DM];
__device__ __half g_wcomb16[DM * DM];
__device__ __half g_win2q16[ODIM * DM];
__device__ float  g_bcomb[DM];
__device__ float  g_wkv[2 * ODIM * DM];
__device__ __half g_wkvh[2 * ODIM * DM];
__device__ __half g_wkv2h[2 * ODIM * DM];
__device__ float  g_bkv[2 * ODIM];
__device__ float  g_zb[DM];

// persistent-kernel sync state (monotonic; replay-safe)
__device__ unsigned g_bar_arrive  = 0;
__device__ unsigned g_bar_release = 0;
__device__ unsigned g_flagA[32];
__device__ unsigned g_flagB[8];

// ================= TF32 tensor-core GEMM (weight folds) =================
constexpr int TF_BK = 32;
constexpr int TF_LD = TF_BK + 4;
constexpr int TF_BUF = (128 + 128) * TF_LD;
constexpr int TF_SMEM = 3 * TF_BUF * (int)sizeof(float);

template<bool RELU>
__global__ __launch_bounds__(256, 2)
void gemm_tf32(const float* __restrict__ A, const float* __restrict__ W,
               const float* __restrict__ bias, float* __restrict__ C,
               int M, int N, int K)
{
    extern __shared__ float smem[];
    const int tid    = threadIdx.x;
    const int lane   = tid & 31;
    const int warp   = tid >> 5;
    const int warp_m = (warp & 1) * 64;
    const int warp_n = (warp >> 1) * 32;
    const int bm     = blockIdx.y * 128;
    const int bn     = blockIdx.x * 128;

    const int ar = (lane & 7) + ((lane >> 3) & 1) * 8;
    const int ac = (lane >> 4) * 4;
    const int br = (lane & 7) + (lane >> 4) * 8;
    const int bc = ((lane >> 3) & 1) * 4;

    float c[4][4][4];
    #pragma unroll
    for (int i = 0; i < 4; i++)
        #pragma unroll
        for (int j = 0; j < 4; j++)
            #pragma unroll
            for (int r = 0; r < 4; r++) c[i][j][r] = 0.f;

    const int lr = tid >> 3;
    const int lc = tid & 7;

    auto issue = [&](int t) {
        const size_t ko = (size_t)t * TF_BK + lc * 4;
        float* As = smem + (t % 3) * TF_BUF;
        float* Bs = As + 128 * TF_LD;
        #pragma unroll
        for (int i = 0; i < 4; i++) {
            int r = lr + i * 32;
            CP_ASYNC16(smaddr(&As[r * TF_LD + lc * 4]), &A[(size_t)(bm + r) * K + ko]);
            CP_ASYNC16(smaddr(&Bs[r * TF_LD + lc * 4]), &W[(size_t)(bn + r) * K + ko]);
        }
        CP_COMMIT();
    };

    const int nk = K / TF_BK;
    issue(0);
    if (nk > 1) issue(1);

    for (int t = 0; t < nk; t++) {
        if (t == nk - 1) { CP_WAIT0(); } else { CP_WAIT1(); }
        __syncthreads();
        if (t + 2 < nk) issue(t + 2);

        const float* bufp = smem + (t % 3) * TF_BUF;
        const uint32_t a_base = smaddr(bufp + (warp_m + ar) * TF_LD + ac);
        const uint32_t b_base = smaddr(bufp + 128 * TF_LD + (warp_n + br) * TF_LD + bc);

        #pragma unroll
        for (int ks = 0; ks < 4; ks++) {
            uint32_t a[4][4], b[4][2];
            #pragma unroll
            for (int mt = 0; mt < 4; mt++)
                LDSM4(a[mt][0], a[mt][1], a[mt][2], a[mt][3],
                      a_base + (uint32_t)((mt * 16 * TF_LD + ks * 8) * 4));
            #pragma unroll
            for (int np = 0; np < 2; np++)
                LDSM4(b[2*np][0], b[2*np][1], b[2*np+1][0], b[2*np+1][1],
                      b_base + (uint32_t)((np * 16 * TF_LD + ks * 8) * 4));
            #pragma unroll
            for (int mt = 0; mt < 4; mt++)
                #pragma unroll
                for (int nt = 0; nt < 4; nt++)
                    MMA_TF32(c[mt][nt], a[mt], b[nt]);
        }
    }

    const int g  = lane >> 2;
    const int tg = lane & 3;
    #pragma unroll
    for (int mt = 0; mt < 4; mt++) {
        int row0 = bm + warp_m + mt * 16 + g;
        #pragma unroll
        for (int nt = 0; nt < 4; nt++) {
            int col = bn + warp_n + nt * 8 + tg * 2;
            float2 bb = *(const float2*)&bias[col];
            float2 o0, o1;
            o0.x = c[mt][nt][0] + bb.x;  o0.y = c[mt][nt][1] + bb.y;
            o1.x = c[mt][nt][2] + bb.x;  o1.y = c[mt][nt][3] + bb.y;
            if (RELU) {
                o0.x = fmaxf(o0.x, 0.f); o0.y = fmaxf(o0.y, 0.f);
                o1.x = fmaxf(o1.x, 0.f); o1.y = fmaxf(o1.y, 0.f);
            }
            *(float2*)&C[(size_t)row0 * N + col]       = o0;
            *(float2*)&C[(size_t)(row0 + 8) * N + col] = o1;
        }
    }
}

// ================= FP16 tensor-core GEMM, 128x128 tiles =================
constexpr int H_BK  = 32;
constexpr int H_LD  = H_BK + 8;
constexpr int H_BUF = (128 + 128) * H_LD;
constexpr int H_SMEM = 3 * H_BUF * 2;

template<bool RELU>
__global__ __launch_bounds__(256, 2)
void gemm_fp16(const __half* __restrict__ A, const __half* __restrict__ W,
               const float* __restrict__ bias, float* __restrict__ C,
               __half* __restrict__ C16, int M, int N, int K)
{
    extern __shared__ __half smh[];
    const int tid    = threadIdx.x;
    const int lane   = tid & 31;
    const int warp   = tid >> 5;
    const int warp_m = (warp & 1) * 64;
    const int warp_n = (warp >> 1) * 32;
    const int bm     = blockIdx.y * 128;
    const int bn     = blockIdx.x * 128;

    const int ar = (lane & 7) + ((lane >> 3) & 1) * 8;
    const int ac = (lane >> 4) * 8;
    const int br = (lane & 7) + (lane >> 4) * 8;
    const int bc = ((lane >> 3) & 1) * 8;

    float c[4][4][4];
    #pragma unroll
    for (int i = 0; i < 4; i++)
        #pragma unroll
        for (int j = 0; j < 4; j++)
            #pragma unroll
            for (int r = 0; r < 4; r++) c[i][j][r] = 0.f;

    const int cr = tid >> 1;
    const int cc = (tid & 1) * 2;

    auto issue = [&](int t) {
        const size_t ko = (size_t)t * H_BK;
        __half* As = smh + (t % 3) * H_BUF;
        __half* Bs = As + 128 * H_LD;
        #pragma unroll
        for (int j = 0; j < 2; j++) {
            int ch = cc + j;
            CP_ASYNC16(smaddr(&As[cr * H_LD + ch * 8]), &A[(size_t)(bm + cr) * K + ko + ch * 8]);
            CP_ASYNC16(smaddr(&Bs[cr * H_LD + ch * 8]), &W[(size_t)(bn + cr) * K + ko + ch * 8]);
        }
        CP_COMMIT();
    };

    const int nk = K / H_BK;
    issue(0);
    if (nk > 1) issue(1);

    for (int t = 0; t < nk; t++) {
        if (t == nk - 1) { CP_WAIT0(); } else { CP_WAIT1(); }
        __syncthreads();
        if (t + 2 < nk) issue(t + 2);

        const __half* bufp = smh + (t % 3) * H_BUF;
        const uint32_t a_base = smaddr(bufp + (warp_m + ar) * H_LD + ac);
        const uint32_t b_base = smaddr(bufp + 128 * H_LD + (warp_n + br) * H_LD + bc);

        #pragma unroll
        for (int ks = 0; ks < 2; ks++) {
            uint32_t a[4][4], b[4][2];
            #pragma unroll
            for (int mt = 0; mt < 4; mt++)
                LDSM4(a[mt][0], a[mt][1], a[mt][2], a[mt][3],
                      a_base + (uint32_t)((mt * 16 * H_LD + ks * 16) * 2));
            #pragma unroll
            for (int np = 0; np < 2; np++)
                LDSM4(b[2*np][0], b[2*np][1], b[2*np+1][0], b[2*np+1][1],
                      b_base + (uint32_t)((np * 16 * H_LD + ks * 16) * 2));
            #pragma unroll
            for (int mt = 0; mt < 4; mt++)
                #pragma unroll
                for (int nt = 0; nt < 4; nt++)
                    MMA_F16(c[mt][nt], a[mt], b[nt]);
        }
    }

    const int g  = lane >> 2;
    const int tg = lane & 3;
    #pragma unroll
    for (int mt = 0; mt < 4; mt++) {
        int row0 = bm + warp_m + mt * 16 + g;
        #pragma unroll
        for (int nt = 0; nt < 4; nt++) {
            int col = bn + warp_n + nt * 8 + tg * 2;
            float2 bb = *(const float2*)&bias[col];
            float2 o0, o1;
            o0.x = c[mt][nt][0] + bb.x;  o0.y = c[mt][nt][1] + bb.y;
            o1.x = c[mt][nt][2] + bb.x;  o1.y = c[mt][nt][3] + bb.y;
            if (RELU) {
                o0.x = fmaxf(o0.x, 0.f); o0.y = fmaxf(o0.y, 0.f);
                o1.x = fmaxf(o1.x, 0.f); o1.y = fmaxf(o1.y, 0.f);
            }
            *(float2*)&C[(size_t)row0 * N + col]       = o0;
            *(float2*)&C[(size_t)(row0 + 8) * N + col] = o1;
            if (C16) {
                *(__half2*)&C16[(size_t)row0 * N + col]       = __floats2half2_rn(o0.x, o0.y);
                *(__half2*)&C16[(size_t)(row0 + 8) * N + col] = __floats2half2_rn(o1.x, o1.y);
            }
        }
    }
}

// ================= exact FFMA2 SGEMM (final projection only) =================
template<int BM, int BN, int BK, int TM, int TN>
__global__ __launch_bounds__((BM/TM)*(BN/TN))
void gemm_bias(const float* __restrict__ A, const float* __restrict__ W,
               const float* __restrict__ bias, float* __restrict__ C,
               int M, int N, int K)
{
    constexpr int THREADS = (BM/TM)*(BN/TN);
    __shared__ __align__(16) float As[BK][BM];
    __shared__ __align__(16) float Bs[BK][BN];
    const int tid  = threadIdx.x;
    const int bm   = blockIdx.y * BM;
    const int bn   = blockIdx.x * BN;
    const int tcol = tid % (BN/TN);
    const int trow = tid / (BN/TN);

    ull acc2[TM][TN/2];
    #pragma unroll
    for (int i = 0; i < TM; i++)
        #pragma unroll
        for (int j = 0; j < TN/2; j++) acc2[i][j] = 0ull;

    constexpr int AF4 = BM * (BK/4);
    constexpr int BF4 = BN * (BK/4);

    for (int k0 = 0; k0 < K; k0 += BK) {
        #pragma unroll
        for (int i = tid; i < AF4; i += THREADS) {
            int r  = i / (BK/4);
            int c4 = i % (BK/4);
            float4 v = *(const float4*)&A[(size_t)(bm + r) * K + k0 + c4*4];
            As[c4*4+0][r] = v.x; As[c4*4+1][r] = v.y;
            As[c4*4+2][r] = v.z; As[c4*4+3][r] = v.w;
        }
        #pragma unroll
        for (int i = tid; i < BF4; i += THREADS) {
            int r  = i / (BK/4);
            int c4 = i % (BK/4);
            float4 v = *(const float4*)&W[(size_t)(bn + r) * K + k0 + c4*4];
            Bs[c4*4+0][r] = v.x; Bs[c4*4+1][r] = v.y;
            Bs[c4*4+2][r] = v.z; Bs[c4*4+3][r] = v.w;
        }
        __syncthreads();

        #pragma unroll
        for (int k = 0; k < BK; k++) {
            float ra[TM];
            #pragma unroll
            for (int i = 0; i < TM; i += 4) {
                float4 v = *(const float4*)&As[k][trow*TM + i];
                ra[i] = v.x; ra[i+1] = v.y; ra[i+2] = v.z; ra[i+3] = v.w;
            }
            ull ras[TM];
            #pragma unroll
            for (int i = 0; i < TM; i++) PACK2(ras[i], ra[i], ra[i]);

            ull rb2[TN/2];
            #pragma unroll
            for (int j4 = 0; j4 < TN/4; j4++) {
                ulonglong2 v = *(const ulonglong2*)&Bs[k][tcol*TN + j4*4];
                rb2[2*j4]   = v.x;
                rb2[2*j4+1] = v.y;
            }
            #pragma unroll
            for (int i = 0; i < TM; i++)
                #pragma unroll
                for (int j = 0; j < TN/2; j++)
                    FMA2(acc2[i][j], ras[i], rb2[j], acc2[i][j]);
        }
        __syncthreads();
    }

    #pragma unroll
    for (int i = 0; i < TM; i++) {
        size_t row = (size_t)(bm + trow*TM + i);
        float oc[TN];
        #pragma unroll
        for (int j = 0; j < TN/2; j++) UNPACK2(oc[2*j], oc[2*j+1], acc2[i][j]);
        #pragma unroll
        for (int j = 0; j < TN; j += 4) {
            int col = bn + tcol*TN + j;
            float4 b4 = *(const float4*)&bias[col];
            float4 o;
            o.x = oc[j+0] + b4.x;
            o.y = oc[j+1] + b4.y;
            o.z = oc[j+2] + b4.z;
            o.w = oc[j+3] + b4.w;
            *(float4*)&C[row * N + col] = o;
        }
    }
}

// ---------------- prep: transposes + zero + bias folds ----------------
__global__ __launch_bounds__(256)
void prep_kernel(const float* __restrict__ w_out1, const float* __restrict__ w_out2,
                 const float* __restrict__ w_lin,  const float* __restrict__ b_out1,
                 const float* __restrict__ b_lin,  const float* __restrict__ wkv2,
                 const float* __restrict__ b_out2, const float* __restrict__ bkv2,
                 float* __restrict__ wt, float* __restrict__ wt2, float* __restrict__ zb,
                 float* __restrict__ bcomb, float* __restrict__ bkv)
{
    const int b   = blockIdx.x;
    const int tid = threadIdx.x;

    if (b < 2048) {
        const float* in = (b < 1024) ? w_out1 : w_out2;
        float* out      = (b < 1024) ? wt : wt2;
        const int bb = b & 1023;
        const int bx = bb & 31, by = bb >> 5;
        __shared__ float tile[32][33];
        const int tx = tid & 31, ty = tid >> 5;
        #pragma unroll
        for (int j = 0; j < 32; j += 8)
            tile[ty + j][tx] = in[(size_t)(by*32 + ty + j) * DM + bx*32 + tx];
        __syncthreads();
        #pragma unroll
        for (int j = 0; j < 32; j += 8)
            out[(size_t)(bx*32 + ty + j) * DM + by*32 + tx] = tile[tx][ty + j];
    } else if (b < 2052) {
        zb[(b - 2048) * 256 + tid] = 0.f;
    } else {
        int bb = b - 2052;
        const float *W, *b1, *b2;
        float* out;
        if (bb < 128) { W = w_lin; b1 = b_out1; b2 = b_lin; out = bcomb; }
        else          { bb -= 128; W = wkv2; b1 = b_out2; b2 = bkv2; out = bkv; }
        const int n = bb * 8 + (tid >> 5);
        const int lane = tid & 31;
        float s = 0.f;
        for (int j = lane; j < DM; j += 32) s = fmaf(W[(size_t)n * DM + j], b1[j], s);
        #pragma unroll
        for (int o = 16; o; o >>= 1) s += __shfl_xor_sync(0xffffffffu, s, o);
        if (lane == 0) out[n] = s + b2[n];
    }
}

// all f32->f16 converts in ONE launch (1024 elems per block)
__global__ __launch_bounds__(256)
void cvt_all(const float* __restrict__ path, const float* __restrict__ w_in1,
             const float* __restrict__ wcomb, const float* __restrict__ w_in2,
             const float* __restrict__ wkv,   const float* __restrict__ wkv2,
             __half* __restrict__ pathh, __half* __restrict__ win1h,
             __half* __restrict__ wcomb16, __half* __restrict__ win2q16,
             __half* __restrict__ wkvh, __half* __restrict__ wkv2h)
{
    int b = blockIdx.x;
    const float* src; __half* dst; int off;
    if      (b < 4096)  { src = path;  dst = pathh;   off = b; }
    else if (b < 7168)  { src = w_in1; dst = win1h;   off = b - 4096; }
    else if (b < 8192)  { src = wcomb; dst = wcomb16; off = b - 7168; }
    else if (b < 9216)  { src = w_in2; dst = win2q16; off = b - 8192; }
    else if (b < 11264) { src = wkv;   dst = wkvh;    off = b - 9216; }
    else                { src = wkv2;  dst = wkv2h;   off = b - 11264; }
    size_t i = (size_t)off * 1024 + threadIdx.x * 4;
    float4 v = *(const float4*)&src[i];
    *(__half2*)&dst[i]     = __floats2half2_rn(v.x, v.y);
    *(__half2*)&dst[i + 2] = __floats2half2_rn(v.z, v.w);
}

// ================= stage-2 attention via fp16 MMA =================
// grid (NH, 4, NWIN), 128 threads = 4 warps x 16 queries. Full 256-key window.
constexpr int AT_LD   = 72;                                     // halfs per smem row
constexpr int AT_SMEM = (256 + 256 + 64) * AT_LD * 2;           // 82944 B

__global__ __launch_bounds__(128, 2)
void attn2_kernel(const __half* __restrict__ qkv, __half* __restrict__ obase, float scale)
{
    extern __shared__ __half smh[];
    __half* Kh = smh;                  // 256 x 72
    __half* Vh = smh + 256 * AT_LD;    // 256 x 72
    __half* Qh = smh + 512 * AT_LD;    // 64 x 72

    const int h   = blockIdx.x;
    const int qt  = blockIdx.y;
    const int w   = blockIdx.z;
    const int tid = threadIdx.x;
    const int lane = tid & 31;
    const int wq  = tid >> 5;          // warp 0..3 -> queries wq*16
    const int g   = lane >> 2;
    const int tg  = lane & 3;

    const __half* Kp = qkv + (size_t)w * STR * 3*DM + DM   + h * DH;
    const __half* Vp = qkv + (size_t)w * STR * 3*DM + 2*DM + h * DH;
    const __half* Qp = qkv + (size_t)(w * STR + qt * 64) * 3*DM + h * DH;

    for (int idx = tid; idx < 256 * 8; idx += 128) {
        int r = idx >> 3, c = idx & 7;
        CP_ASYNC16(smaddr(Kh + r * AT_LD + c*8), Kp + (size_t)r * 3*DM + c*8);
        CP_ASYNC16(smaddr(Vh + r * AT_LD + c*8), Vp + (size_t)r * 3*DM + c*8);
    }
    for (int idx = tid; idx < 64 * 8; idx += 128) {
        int r = idx >> 3, c = idx & 7;
        CP_ASYNC16(smaddr(Qh + r * AT_LD + c*8), Qp + (size_t)r * 3*DM + c*8);
    }
    CP_COMMIT();
    CP_WAIT0();
    __syncthreads();

    // ---- S = Q K^T  (16 q x 256 k, 32 n-tiles) ----
    float S[32][4];
    #pragma unroll
    for (int j = 0; j < 32; j++)
        #pragma unroll
        for (int r = 0; r < 4; r++) S[j][r] = 0.f;

    const int ar  = (lane & 7) + ((lane >> 3) & 1) * 8;
    const int ach = (lane >> 4) * 8;
    const int br  = (lane & 7) + (lane >> 4) * 8;
    const int bch = ((lane >> 3) & 1) * 8;
    const uint32_t qa = smaddr(Qh + (wq*16 + ar) * AT_LD + ach);
    const uint32_t kb = smaddr(Kh + br * AT_LD + bch);

    #pragma unroll
    for (int kd = 0; kd < 4; kd++) {
        uint32_t a[4];
        LDSM4(a[0], a[1], a[2], a[3], qa + (uint32_t)(kd * 16 * 2));
        #pragma unroll
        for (int nt2 = 0; nt2 < 16; nt2++) {
            uint32_t b[2][2];
            LDSM4(b[0][0], b[0][1], b[1][0], b[1][1],
                  kb + (uint32_t)((nt2 * 16 * AT_LD + kd * 16) * 2));
            MMA_F16(S[2*nt2],     a, b[0]);
            MMA_F16(S[2*nt2 + 1], a, b[1]);
        }
    }

    // ---- softmax over 256 keys (rows g and g+8; quad = lanes sharing g) ----
    float mx0 = -1e30f, mx1 = -1e30f;
    #pragma unroll
    for (int j = 0; j < 32; j++) {
        mx0 = fmaxf(mx0, fmaxf(S[j][0], S[j][1]));
        mx1 = fmaxf(mx1, fmaxf(S[j][2], S[j][3]));
    }
    mx0 = fmaxf(mx0, __shfl_xor_sync(0xffffffffu, mx0, 1));
    mx0 = fmaxf(mx0, __shfl_xor_sync(0xffffffffu, mx0, 2));
    mx1 = fmaxf(mx1, __shfl_xor_sync(0xffffffffu, mx1, 1));
    mx1 = fmaxf(mx1, __shfl_xor_sync(0xffffffffu, mx1, 2));

    float l0 = 0.f, l1 = 0.f;
    #pragma unroll
    for (int j = 0; j < 32; j++) {
        float p0 = __expf((S[j][0] - mx0) * scale);
        float p1 = __expf((S[j][1] - mx0) * scale);
        float p2 = __expf((S[j][2] - mx1) * scale);
        float p3 = __expf((S[j][3] - mx1) * scale);
        S[j][0] = p0; S[j][1] = p1; S[j][2] = p2; S[j][3] = p3;
        l0 += p0 + p1;
        l1 += p2 + p3;
    }
    l0 += __shfl_xor_sync(0xffffffffu, l0, 1);
    l0 += __shfl_xor_sync(0xffffffffu, l0, 2);
    l1 += __shfl_xor_sync(0xffffffffu, l1, 1);
    l1 += __shfl_xor_sync(0xffffffffu, l1, 2);
    const float inv0 = 1.f / l0;
    const float inv1 = 1.f / l1;

    // ---- O = P V  (16 q x 64 d, 8 n-tiles, 16 k-chunks) ----
    float O[8][4];
    #pragma unroll
    for (int n = 0; n < 8; n++)
        #pragma unroll
        for (int r = 0; r < 4; r++) O[n][r] = 0.f;

    const int vr = (lane & 7) + ((lane >> 3) & 1) * 8;   // key row within 16-chunk
    const int vc = (lane >> 4) * 8;                      // dim offset within nt-pair
    const uint32_t vb = smaddr(Vh + vr * AT_LD + vc);

    #pragma unroll
    for (int j = 0; j < 16; j++) {
        uint32_t a[4];
        a[0] = pkh2(S[2*j][0],     S[2*j][1]);
        a[1] = pkh2(S[2*j][2],     S[2*j][3]);
        a[2] = pkh2(S[2*j + 1][0], S[2*j + 1][1]);
        a[3] = pkh2(S[2*j + 1][2], S[2*j + 1][3]);
        #pragma unroll
        for (int ntp = 0; ntp < 4; ntp++) {
            uint32_t b[2][2];
            LDSM4T(b[0][0], b[0][1], b[1][0], b[1][1],
                   vb + (uint32_t)((j * 16 * AT_LD + ntp * 16) * 2));
            MMA_F16(O[2*ntp],     a, b[0]);
            MMA_F16(O[2*ntp + 1], a, b[1]);
        }
    }

    // ---- epilogue: rows g, g+8 of this warp's 16 queries ----
    const int qrow0 = qt * 64 + wq * 16 + g;
    __half* Ob0 = obase + (size_t)(w * KW + qrow0) * DM + h * DH;
    __half* Ob1 = Ob0 + (size_t)8 * DM;
    #pragma unroll
    for (int nt = 0; nt < 8; nt++) {
        int d = nt * 8 + tg * 2;
        *(__half2*)&Ob0[d] = __floats2half2_rn(O[nt][0] * inv0, O[nt][1] * inv0);
        *(__half2*)&Ob1[d] = __floats2half2_rn(O[nt][2] * inv1, O[nt][3] * inv1);
    }
}

// ================= persistent recurrence kernel (unchanged from R13) ======
constexpr int REC_NB   = 128;
constexpr int REC_SMEM = (32768 + 512) * (int)sizeof(float);
constexpr int RH_BK  = 128;
constexpr int RH_LD  = RH_BK + 8;
constexpr int RH_BUF = (64 + 64) * RH_LD;

__device__ __forceinline__ void grid_bar(unsigned base, unsigned bar_id)
{
    __syncthreads();
    if (threadIdx.x == 0) {
        __threadfence();
        unsigned a = atomicAdd(&g_bar_arrive, 1u);
        if ((a & (REC_NB - 1u)) == (REC_NB - 1u)) {
            atomicAdd(&g_bar_release, 1u);
        } else {
            while (*(volatile unsigned*)&g_bar_release - base < bar_id) { }
        }
        __threadfence();
    }
    __syncthreads();
}

__global__ __launch_bounds__(256)
void recurrence_kernel(const __half* __restrict__ x16,
                       const float* __restrict__ q2,
                       const __half* __restrict__ wkv2h, const float* __restrict__ bkv2,
                       const __half* __restrict__ wkvh,  const float* __restrict__ bkvF,
                       float* __restrict__ kv, float* __restrict__ st,
                       __half* __restrict__ st16)
{
    extern __shared__ float sm[];
    __half* smh = (__half*)sm;
    const int tid = threadIdx.x;
    const int bid = blockIdx.x;

    __shared__ unsigned s_base;
    if (tid == 0) s_base = *(volatile unsigned*)&g_bar_release;
    __syncthreads();
    const unsigned base = s_base;

    if (bid == 0) {
        if (tid < 32)              g_flagA[tid]      = 0;
        else if (tid < 40)         g_flagB[tid - 32] = 0;
    }
    grid_bar(base, 1);

    const int lane = tid & 31, warp = tid >> 5;
    const int g = lane >> 2, tg = lane & 3;
    const int warp_m = (warp & 1) * 32;
    const int warp_n = (warp >> 1) * 16;
    const int tm = bid >> 5;
    const int tn = bid & 31;

    const int ar  = (lane & 7) + ((lane >> 3) & 1) * 8;
    const int ach = (lane >> 4) * 8;
    const int br  = (lane & 7) + (lane >> 4) * 8;
    const int bch = ((lane >> 3) & 1) * 8;

    const int h  = bid >> 3;
    const int qt = bid & 7;
    const int q  = tid & 31;
    const int ck = tid >> 5;

    for (int i = 1; i < NWIN; i++) {
        float*  kvb      = kv   + (size_t)(i & 1) * KW * 2 * ODIM;
        float*  stb      = st   + (size_t)(i & 1) * KW * ODIM;
        __half* st16b    = st16 + (size_t)(i & 1) * KW * ODIM;
        const __half* st16prev = st16 + (size_t)((i - 1) & 1) * KW * ODIM;

        // ===== Phase A: KV projection (fp16 MMA, BK=128 halfs) =====
        {
            if (i > 1 && tid == 0) {
                unsigned tgt = 16u * (unsigned)(i - 1);
                while (flag_acquire(&g_flagB[2*tm])     < tgt) { }
                while (flag_acquire(&g_flagB[2*tm + 1]) < tgt) { }
            }
            __syncthreads();

            const __half* A  = (i == 1) ? x16   : st16prev;
            const __half* W  = (i == 1) ? wkv2h : wkvh;
            const float*  bb = (i == 1) ? bkv2  : bkvF;

            float cacc[2][2][4];
            #pragma unroll
            for (int mt = 0; mt < 2; mt++)
                #pragma unroll
                for (int nt = 0; nt < 2; nt++)
                    #pragma unroll
                    for (int r = 0; r < 4; r++) cacc[mt][nt][r] = 0.f;

            const int crow = tid >> 2;
            const int cch  = (tid & 3) * 4;

            auto issue = [&](int t) {
                size_t ko = (size_t)t * RH_BK;
                __half* As = smh + (t % 3) * RH_BUF;
                __half* Bs = As + 64 * RH_LD;
                #pragma unroll
                for (int j = 0; j < 4; j++) {
                    int ch = cch + j;
                    CP_ASYNC16(smaddr(&As[crow * RH_LD + ch*8]), &A[(size_t)(tm*64 + crow) * 1024 + ko + ch*8]);
                    CP_ASYNC16(smaddr(&Bs[crow * RH_LD + ch*8]), &W[(size_t)(tn*64 + crow) * 1024 + ko + ch*8]);
                }
                CP_COMMIT();
            };

            issue(0);
            issue(1);
            for (int t = 0; t < 8; t++) {
                if (t == 7) { CP_WAIT0(); } else { CP_WAIT1(); }
                __syncthreads();
                if (t + 2 < 8) issue(t + 2);

                const __half* bufp = smh + (t % 3) * RH_BUF;
                const uint32_t a_base = smaddr(bufp + (warp_m + ar) * RH_LD + ach);
                const uint32_t b_base = smaddr(bufp + 64 * RH_LD + (warp_n + br) * RH_LD + bch);

                #pragma unroll
                for (int ks = 0; ks < 8; ks++) {
                    uint32_t a[2][4], b[2][2];
                    #pragma unroll
                    for (int mt = 0; mt < 2; mt++)
                        LDSM4(a[mt][0], a[mt][1], a[mt][2], a[mt][3],
                              a_base + (uint32_t)((mt * 16 * RH_LD + ks * 16) * 2));
                    LDSM4(b[0][0], b[0][1], b[1][0], b[1][1],
                          b_base + (uint32_t)((ks * 16) * 2));
                    #pragma unroll
                    for (int mt = 0; mt < 2; mt++)
                        #pragma unroll
                        for (int nt = 0; nt < 2; nt++)
                            MMA_F16(cacc[mt][nt], a[mt], b[nt]);
                }
            }

            #pragma unroll
            for (int mt = 0; mt < 2; mt++) {
                int row0 = tm*64 + warp_m + mt*16 + g;
                #pragma unroll
                for (int nt = 0; nt < 2; nt++) {
                    int col = tn*64 + warp_n + nt*8 + tg*2;
                    float2 bb2 = *(const float2*)&bb[col];
                    float2 o0, o1;
                    o0.x = cacc[mt][nt][0] + bb2.x;  o0.y = cacc[mt][nt][1] + bb2.y;
                    o1.x = cacc[mt][nt][2] + bb2.x;  o1.y = cacc[mt][nt][3] + bb2.y;
                    *(float2*)&kvb[(size_t)row0 * 2048 + col]       = o0;
                    *(float2*)&kvb[(size_t)(row0 + 8) * 2048 + col] = o1;
                }
            }
            __syncthreads();
            if (tid == 0) flag_release(&g_flagA[tn]);
        }

        // ===== Phase B: attention (fp32 math) =====
        {
            if (tid == 0) {
                unsigned tgt = 4u * (unsigned)i;
                while (flag_acquire(&g_flagA[h])      < tgt) { }
                while (flag_acquire(&g_flagA[16 + h]) < tgt) { }
            }
            __syncthreads();

            float* Ks   = sm;
            float* Vs   = sm + 16384;
            float* mbuf = sm + 32768;
            float* lbuf = mbuf + 256;

            const float* Kp = kvb + h * DH;
            const float* Vp = kvb + 1024 + h * DH;
            for (int idx = tid; idx < 256 * 16; idx += 256) {
                int r  = idx >> 4;
                int c4 = idx & 15;
                CP_ASYNC16(smaddr(Ks + r*64 + c4*4), Kp + (size_t)r*2048 + c4*4);
                CP_ASYNC16(smaddr(Vs + r*64 + c4*4), Vp + (size_t)r*2048 + c4*4);
            }
            CP_COMMIT();

            const float* Qr = q2 + (size_t)i * KW * ODIM + (size_t)(qt*32 + q) * 1024 + h * DH;
            ull qp[32];
            #pragma unroll
            for (int d4 = 0; d4 < 16; d4++) {
                ulonglong2 v = *(const ulonglong2*)(Qr + d4*4);
                qp[2*d4]   = v.x;
                qp[2*d4+1] = v.y;
            }

            CP_WAIT0();
            __syncthreads();

            float m = -1e30f, l = 0.f;
            ull accp[32];
            #pragma unroll
            for (int t = 0; t < 32; t++) accp[t] = 0ull;

            const int k0 = ck * 32;
            for (int kk = 0; kk < 32; kk++) {
                const float* Krow = Ks + (k0 + kk) * 64;
                ull s0 = 0ull, s1 = 0ull, s2 = 0ull, s3 = 0ull;
                #pragma unroll
                for (int d4 = 0; d4 < 16; d4 += 2) {
                    ulonglong2 a = *(const ulonglong2*)(Krow + d4*4);
                    ulonglong2 b = *(const ulonglong2*)(Krow + d4*4 + 4);
                    FMA2(s0, qp[2*d4+0], a.x, s0);
                    FMA2(s1, qp[2*d4+1], a.y, s1);
                    FMA2(s2, qp[2*d4+2], b.x, s2);
                    FMA2(s3, qp[2*d4+3], b.y, s3);
                }
                float a0,a1,b0,b1,c0,c1,d0,d1;
                UNPACK2(a0,a1,s0); UNPACK2(b0,b1,s1); UNPACK2(c0,c1,s2); UNPACK2(d0,d1,s3);
                float s = ((a0+a1)+(b0+b1)) + ((c0+c1)+(d0+d1));
                s *= 0.125f;

                if (s > m) {
                    float corr = __expf(m - s);
                    l *= corr;
                    ull cp; PACK2(cp, corr, corr);
                    #pragma unroll
                    for (int t = 0; t < 32; t++) MUL2(accp[t], accp[t], cp);
                    m = s;
                }
                float p = __expf(s - m);
                l += p;
                ull pp; PACK2(pp, p, p);
                const float* Vrow = Vs + (k0 + kk) * 64;
                #pragma unroll
                for (int d4 = 0; d4 < 16; d4 += 2) {
                    ulonglong2 a = *(const ulonglong2*)(Vrow + d4*4);
                    ulonglong2 b = *(const ulonglong2*)(Vrow + d4*4 + 4);
                    FMA2(accp[2*d4+0], pp, a.x, accp[2*d4+0]);
                    FMA2(accp[2*d4+1], pp, a.y, accp[2*d4+1]);
                    FMA2(accp[2*d4+2], pp, b.x, accp[2*d4+2]);
                    FMA2(accp[2*d4+3], pp, b.y, accp[2*d4+3]);
                }
            }
            __syncthreads();

            float* accbuf = sm;
            mbuf[tid] = m;
            lbuf[tid] = l;
            #pragma unroll
            for (int t = 0; t < 32; t++) {
                float f0, f1;
                UNPACK2(f0, f1, accp[t]);
                accbuf[tid*65 + 2*t]     = f0;
                accbuf[tid*65 + 2*t + 1] = f1;
            }
            __syncthreads();

            float mv[8], ev[8];
            float mg = -1e30f;
            #pragma unroll
            for (int cc = 0; cc < 8; cc++) { mv[cc] = mbuf[cc*32 + q]; mg = fmaxf(mg, mv[cc]); }
            float lg = 0.f;
            #pragma unroll
            for (int cc = 0; cc < 8; cc++) { ev[cc] = __expf(mv[cc] - mg); lg += lbuf[cc*32 + q] * ev[cc]; }
            float inv = 1.f / lg;

            float*  Orow  = stb   + (size_t)(qt*32 + q) * 1024 + h * DH;
            __half* Orow2 = st16b + (size_t)(qt*32 + q) * 1024 + h * DH;
            #pragma unroll
            for (int j = 0; j < 8; j += 2) {
                int d = ck*8 + j;
                float oa = 0.f, ob = 0.f;
                #pragma unroll
                for (int cc = 0; cc < 8; cc++) {
                    oa += accbuf[(cc*32 + q)*65 + d]     * ev[cc];
                    ob += accbuf[(cc*32 + q)*65 + d + 1] * ev[cc];
                }
                oa *= inv; ob *= inv;
                Orow[d]     = oa;
                Orow[d + 1] = ob;
                *(__half2*)&Orow2[d] = __floats2half2_rn(oa, ob);
            }
            __syncthreads();
            if (tid == 0) flag_release(&g_flagB[qt]);
        }
    }
}

// ---------------- host ----------------
extern "C" void kernel_launch(void* const* d_in, const int* in_sizes, int n_in,
                              void* d_out, int out_size)
{
    const float* path   = (const float*)d_in[0];
    const float* w_in1  = (const float*)d_in[1];
    const float* b_in1  = (const float*)d_in[2];
    const float* w_out1 = (const float*)d_in[3];
    const float* b_out1 = (const float*)d_in[4];
    const float* w_lin  = (const float*)d_in[5];
    const float* b_lin  = (const float*)d_in[6];
    const float* w_in2  = (const float*)d_in[7];
    const float* b_in2  = (const float*)d_in[8];
    const float* w_out2 = (const float*)d_in[9];
    const float* b_out2 = (const float*)d_in[10];

    float *qkv1, *x, *q2, *kv, *st, *wt, *wt2, *wcomb, *bcomb, *wkv, *bkv, *zb;
    __half *qkv1h, *pathh, *win1h, *attn1h, *x16, *wcomb16, *win2q16, *wkvh, *wkv2h, *st16;
    cudaGetSymbolAddress((void**)&qkv1,    g_qkv1);
    cudaGetSymbolAddress((void**)&qkv1h,   g_qkv1h);
    cudaGetSymbolAddress((void**)&pathh,   g_pathh);
    cudaGetSymbolAddress((void**)&win1h,   g_win1h);
    cudaGetSymbolAddress((void**)&attn1h,  g_attn1h);
    cudaGetSymbolAddress((void**)&x,       g_x);
    cudaGetSymbolAddress((void**)&x16,     g_x16);
    cudaGetSymbolAddress((void**)&q2,      g_q2);
    cudaGetSymbolAddress((void**)&kv,      g_kv);
    cudaGetSymbolAddress((void**)&st,      g_st);
    cudaGetSymbolAddress((void**)&st16,    g_st16);
    cudaGetSymbolAddress((void**)&wt,      g_wt);
    cudaGetSymbolAddress((void**)&wt2,     g_wt2);
    cudaGetSymbolAddress((void**)&wcomb,   g_wcomb);
    cudaGetSymbolAddress((void**)&wcomb16, g_wcomb16);
    cudaGetSymbolAddress((void**)&win2q16, g_win2q16);
    cudaGetSymbolAddress((void**)&bcomb,   g_bcomb);
    cudaGetSymbolAddress((void**)&wkv,     g_wkv);
    cudaGetSymbolAddress((void**)&wkvh,    g_wkvh);
    cudaGetSymbolAddress((void**)&wkv2h,   g_wkv2h);
    cudaGetSymbolAddress((void**)&bkv,     g_bkv);
    cudaGetSymbolAddress((void**)&zb,      g_zb);

    cudaFuncSetAttribute(attn2_kernel,       cudaFuncAttributeMaxDynamicSharedMemorySize, AT_SMEM);
    cudaFuncSetAttribute(gemm_tf32<false>,   cudaFuncAttributeMaxDynamicSharedMemorySize, TF_SMEM);
    cudaFuncSetAttribute(gemm_fp16<false>,   cudaFuncAttributeMaxDynamicSharedMemorySize, H_SMEM);
    cudaFuncSetAttribute(gemm_fp16<true>,    cudaFuncAttributeMaxDynamicSharedMemorySize, H_SMEM);
    cudaFuncSetAttribute(recurrence_kernel,  cudaFuncAttributeMaxDynamicSharedMemorySize, REC_SMEM);
    cudaFuncSetAttribute(attn2_kernel,       cudaFuncAttributePreferredSharedMemoryCarveout, 100);
    cudaFuncSetAttribute(gemm_tf32<false>,   cudaFuncAttributePreferredSharedMemoryCarveout, 100);
    cudaFuncSetAttribute(gemm_fp16<false>,   cudaFuncAttributePreferredSharedMemoryCarveout, 100);
    cudaFuncSetAttribute(gemm_fp16<true>,    cudaFuncAttributePreferredSharedMemoryCarveout, 100);

    auto g64  = gemm_bias<64,64,16,4,4>;
    auto t32  = gemm_tf32<false>;
    auto h16  = gemm_fp16<false>;
    auto h16r = gemm_fp16<true>;

    const float* wkv2 = w_in2 + (size_t)ODIM * ODIM;
    const float* bkv2 = b_in2 + ODIM;

    // 0: prologue prep
    prep_kernel<<<2052 + 128 + 256, 256>>>(w_out1, w_out2, w_lin, b_out1, b_lin,
                                           wkv2, b_out2, bkv2, wt, wt2, zb, bcomb, bkv);
    // 1-2: weight folds (tf32)
    t32<<<dim3(DM/128, DM/128), 256, TF_SMEM>>>(w_lin, wt, zb, wcomb, DM, DM, DM);
    t32<<<dim3(DM/128, 2*ODIM/128), 256, TF_SMEM>>>(wkv2, wt2, zb, wkv, 2*ODIM, DM, DM);

    // 3: all f32->f16 converts in one launch
    cvt_all<<<13312, 256>>>(path, w_in1, wcomb, w_in2, wkv, wkv2,
                            pathh, win1h, wcomb16, win2q16, wkvh, wkv2h);

    // 4: stage 1 QKV (fp16 MMA) -> qkv1 fp32 (scratch) + qkv1h
    h16<<<dim3(3*DM/128, SEQ/128), 256, H_SMEM>>>(pathh, win1h, b_in1, qkv1, qkv1h, SEQ, 3*DM, DM);

    // 5: stage 2 window self-attention (fp16 MMA)   <-- ncu -s 5 target
    attn2_kernel<<<dim3(NH, KW/64, NWIN), 128, AT_SMEM>>>(qkv1h, attn1h, 0.125f);

    // 6: stage 3 fused outproj1 + linear + relu (fp16 MMA) -> x fp32 + x16
    h16r<<<dim3(ODIM/128, ROWS/128), 256, H_SMEM>>>(attn1h, wcomb16, bcomb, x, x16, ROWS, ODIM, DM);

    // 7: stage 4a bulk Q2 projections (fp16 MMA) -> q2 fp32
    h16<<<dim3(ODIM/128, ROWS/128), 256, H_SMEM>>>(x16, win2q16, b_in2, q2, ((__half*)0), ROWS, ODIM, ODIM);

    // 8: persistent recurrence (fp16 phase A)
    recurrence_kernel<<<REC_NB, 256, REC_SMEM>>>(x16, q2, wkv2h, bkv2, wkvh, bkv, kv, st, st16);

    // 9: final out-projection (exact fp32 -> d_out)
    g64<<<dim3(ODIM/64, KW/64), 256>>>(st + (size_t)((NWIN-1)&1) * KW * ODIM,
                                       w_out2, b_out2, (float*)d_out, KW, ODIM, ODIM);
}

// round 15
// speedup vs baseline: 2.5714x; 1.4899x over previous
#include <cuda_runtime.h>
#include <cuda_fp16.h>
#include <math.h>
#include <stdint.h>

// ---------------- problem constants ----------------
constexpr int SEQ  = 4096;
constexpr int DM   = 1024;
constexpr int ODIM = 1024;
constexpr int KW   = 256;
constexpr int STR  = 16;
constexpr int NH   = 16;
constexpr int DH   = 64;
constexpr int NWIN = (SEQ - KW) / STR;   // 240
constexpr int ROWS = NWIN * KW;          // 61440

typedef unsigned long long ull;

// packed fp32x2 helpers
#define PACK2(o, lo, hi)   asm("mov.b64 %0, {%1,%2};" : "=l"(o) : "f"(lo), "f"(hi))
#define UNPACK2(lo, hi, i) asm("mov.b64 {%0,%1}, %2;" : "=f"(lo), "=f"(hi) : "l"(i))
#define FMA2(d, a, b, c)   asm("fma.rn.f32x2 %0, %1, %2, %3;" : "=l"(d) : "l"(a), "l"(b), "l"(c))
#define MUL2(d, a, b)      asm("mul.rn.f32x2 %0, %1, %2;" : "=l"(d) : "l"(a), "l"(b))

__device__ __forceinline__ uint32_t smaddr(const void* p) {
    return (uint32_t)__cvta_generic_to_shared(p);
}
__device__ __forceinline__ uint32_t pkh2(float x, float y) {
    __half2 h = __floats2half2_rn(x, y);
    return *(uint32_t*)&h;
}

#define CP_ASYNC16(sm_u32, gptr) \
    asm volatile("cp.async.cg.shared.global [%0], [%1], 16;" :: "r"(sm_u32), "l"(gptr))
#define CP_COMMIT() asm volatile("cp.async.commit_group;")
#define CP_WAIT0()  asm volatile("cp.async.wait_group 0;")
#define CP_WAIT1()  asm volatile("cp.async.wait_group 1;")

#define LDSM4(r0, r1, r2, r3, addr) \
    asm volatile("ldmatrix.sync.aligned.m8n8.x4.shared.b16 {%0,%1,%2,%3}, [%4];" \
        : "=r"(r0), "=r"(r1), "=r"(r2), "=r"(r3) : "r"(addr))
#define LDSM4T(r0, r1, r2, r3, addr) \
    asm volatile("ldmatrix.sync.aligned.m8n8.x4.trans.shared.b16 {%0,%1,%2,%3}, [%4];" \
        : "=r"(r0), "=r"(r1), "=r"(r2), "=r"(r3) : "r"(addr))

#define MMA_TF32(c, a, b) \
    asm volatile("mma.sync.aligned.m16n8k8.row.col.f32.tf32.tf32.f32 " \
        "{%0,%1,%2,%3},{%4,%5,%6,%7},{%8,%9},{%0,%1,%2,%3};" \
        : "+f"((c)[0]), "+f"((c)[1]), "+f"((c)[2]), "+f"((c)[3]) \
        : "r"((a)[0]), "r"((a)[1]), "r"((a)[2]), "r"((a)[3]), "r"((b)[0]), "r"((b)[1]))

#define MMA_F16(c, a, b) \
    asm volatile("mma.sync.aligned.m16n8k16.row.col.f32.f16.f16.f32 " \
        "{%0,%1,%2,%3},{%4,%5,%6,%7},{%8,%9},{%0,%1,%2,%3};" \
        : "+f"((c)[0]), "+f"((c)[1]), "+f"((c)[2]), "+f"((c)[3]) \
        : "r"((a)[0]), "r"((a)[1]), "r"((a)[2]), "r"((a)[3]), "r"((b)[0]), "r"((b)[1]))

// release/acquire flag ops
__device__ __forceinline__ void flag_release(unsigned* f) {
    unsigned old;
    asm volatile("atom.release.gpu.global.add.u32 %0, [%1], 1;" : "=r"(old) : "l"(f) : "memory");
}
__device__ __forceinline__ unsigned flag_acquire(unsigned* f) {
    unsigned v;
    asm volatile("ld.acquire.gpu.global.u32 %0, [%1];" : "=r"(v) : "l"(f) : "memory");
    return v;
}

// ---------------- scratch ----------------
__device__ float  g_qkv1[SEQ * 3 * DM];      // fp32 scratch C for stage1
__device__ __half g_qkv1h[SEQ * 3 * DM];
__device__ __half g_pathh[SEQ * DM];
__device__ __half g_win1h[3 * DM * DM];
__device__ __half g_attn1h[ROWS * DM];
__device__ float  g_x[ROWS * ODIM];
__device__ __half g_x16[ROWS * ODIM];
__device__ float  g_q2[ROWS * ODIM];         // fp32 scratch C for stage4a
__device__ __half g_q2h[ROWS * ODIM];
__device__ __half g_kvh[2 * KW * 2 * ODIM];  // fp16 KV, double-buffered by parity
__device__ float  g_st[2 * KW * ODIM];       // fp32 state (final projection)
__device__ __half g_st16[2 * KW * ODIM];     // fp16 shadow (phase A input)
__device__ float  g_wt[DM * DM];
__device__ float  g_wt2[DM * DM];
__device__ float  g_wcomb[DM * DM];
__device__ __half g_wcomb16[DM * DM];
__device__ __half g_win2q16[ODIM * DM];
__device__ float  g_bcomb[DM];
__device__ float  g_wkv[2 * ODIM * DM];
__device__ __half g_wkvh[2 * ODIM * DM];
__device__ __half g_wkv2h[2 * ODIM * DM];
__device__ float  g_bkv[2 * ODIM];
__device__ float  g_zb[DM];

// persistent-kernel sync state (monotonic; replay-safe)
__device__ unsigned g_bar_arrive  = 0;
__device__ unsigned g_bar_release = 0;
__device__ unsigned g_flagA[32];
__device__ unsigned g_flagB[8];

// ================= TF32 tensor-core GEMM (weight folds) =================
constexpr int TF_BK = 32;
constexpr int TF_LD = TF_BK + 4;
constexpr int TF_BUF = (128 + 128) * TF_LD;
constexpr int TF_SMEM = 3 * TF_BUF * (int)sizeof(float);

template<bool RELU>
__global__ __launch_bounds__(256, 2)
void gemm_tf32(const float* __restrict__ A, const float* __restrict__ W,
               const float* __restrict__ bias, float* __restrict__ C,
               int M, int N, int K)
{
    extern __shared__ float smem[];
    const int tid    = threadIdx.x;
    const int lane   = tid & 31;
    const int warp   = tid >> 5;
    const int warp_m = (warp & 1) * 64;
    const int warp_n = (warp >> 1) * 32;
    const int bm     = blockIdx.y * 128;
    const int bn     = blockIdx.x * 128;

    const int ar = (lane & 7) + ((lane >> 3) & 1) * 8;
    const int ac = (lane >> 4) * 4;
    const int br = (lane & 7) + (lane >> 4) * 8;
    const int bc = ((lane >> 3) & 1) * 4;

    float c[4][4][4];
    #pragma unroll
    for (int i = 0; i < 4; i++)
        #pragma unroll
        for (int j = 0; j < 4; j++)
            #pragma unroll
            for (int r = 0; r < 4; r++) c[i][j][r] = 0.f;

    const int lr = tid >> 3;
    const int lc = tid & 7;

    auto issue = [&](int t) {
        const size_t ko = (size_t)t * TF_BK + lc * 4;
        float* As = smem + (t % 3) * TF_BUF;
        float* Bs = As + 128 * TF_LD;
        #pragma unroll
        for (int i = 0; i < 4; i++) {
            int r = lr + i * 32;
            CP_ASYNC16(smaddr(&As[r * TF_LD + lc * 4]), &A[(size_t)(bm + r) * K + ko]);
            CP_ASYNC16(smaddr(&Bs[r * TF_LD + lc * 4]), &W[(size_t)(bn + r) * K + ko]);
        }
        CP_COMMIT();
    };

    const int nk = K / TF_BK;
    issue(0);
    if (nk > 1) issue(1);

    for (int t = 0; t < nk; t++) {
        if (t == nk - 1) { CP_WAIT0(); } else { CP_WAIT1(); }
        __syncthreads();
        if (t + 2 < nk) issue(t + 2);

        const float* bufp = smem + (t % 3) * TF_BUF;
        const uint32_t a_base = smaddr(bufp + (warp_m + ar) * TF_LD + ac);
        const uint32_t b_base = smaddr(bufp + 128 * TF_LD + (warp_n + br) * TF_LD + bc);

        #pragma unroll
        for (int ks = 0; ks < 4; ks++) {
            uint32_t a[4][4], b[4][2];
            #pragma unroll
            for (int mt = 0; mt < 4; mt++)
                LDSM4(a[mt][0], a[mt][1], a[mt][2], a[mt][3],
                      a_base + (uint32_t)((mt * 16 * TF_LD + ks * 8) * 4));
            #pragma unroll
            for (int np = 0; np < 2; np++)
                LDSM4(b[2*np][0], b[2*np][1], b[2*np+1][0], b[2*np+1][1],
                      b_base + (uint32_t)((np * 16 * TF_LD + ks * 8) * 4));
            #pragma unroll
            for (int mt = 0; mt < 4; mt++)
                #pragma unroll
                for (int nt = 0; nt < 4; nt++)
                    MMA_TF32(c[mt][nt], a[mt], b[nt]);
        }
    }

    const int g  = lane >> 2;
    const int tg = lane & 3;
    #pragma unroll
    for (int mt = 0; mt < 4; mt++) {
        int row0 = bm + warp_m + mt * 16 + g;
        #pragma unroll
        for (int nt = 0; nt < 4; nt++) {
            int col = bn + warp_n + nt * 8 + tg * 2;
            float2 bb = *(const float2*)&bias[col];
            float2 o0, o1;
            o0.x = c[mt][nt][0] + bb.x;  o0.y = c[mt][nt][1] + bb.y;
            o1.x = c[mt][nt][2] + bb.x;  o1.y = c[mt][nt][3] + bb.y;
            if (RELU) {
                o0.x = fmaxf(o0.x, 0.f); o0.y = fmaxf(o0.y, 0.f);
                o1.x = fmaxf(o1.x, 0.f); o1.y = fmaxf(o1.y, 0.f);
            }
            *(float2*)&C[(size_t)row0 * N + col]       = o0;
            *(float2*)&C[(size_t)(row0 + 8) * N + col] = o1;
        }
    }
}

// ================= FP16 tensor-core GEMM, 128x128 tiles =================
constexpr int H_BK  = 32;
constexpr int H_LD  = H_BK + 8;
constexpr int H_BUF = (128 + 128) * H_LD;
constexpr int H_SMEM = 3 * H_BUF * 2;

template<bool RELU>
__global__ __launch_bounds__(256, 2)
void gemm_fp16(const __half* __restrict__ A, const __half* __restrict__ W,
               const float* __restrict__ bias, float* __restrict__ C,
               __half* __restrict__ C16, int M, int N, int K)
{
    extern __shared__ __half smh[];
    const int tid    = threadIdx.x;
    const int lane   = tid & 31;
    const int warp   = tid >> 5;
    const int warp_m = (warp & 1) * 64;
    const int warp_n = (warp >> 1) * 32;
    const int bm     = blockIdx.y * 128;
    const int bn     = blockIdx.x * 128;

    const int ar = (lane & 7) + ((lane >> 3) & 1) * 8;
    const int ac = (lane >> 4) * 8;
    const int br = (lane & 7) + (lane >> 4) * 8;
    const int bc = ((lane >> 3) & 1) * 8;

    float c[4][4][4];
    #pragma unroll
    for (int i = 0; i < 4; i++)
        #pragma unroll
        for (int j = 0; j < 4; j++)
            #pragma unroll
            for (int r = 0; r < 4; r++) c[i][j][r] = 0.f;

    const int cr = tid >> 1;
    const int cc = (tid & 1) * 2;

    auto issue = [&](int t) {
        const size_t ko = (size_t)t * H_BK;
        __half* As = smh + (t % 3) * H_BUF;
        __half* Bs = As + 128 * H_LD;
        #pragma unroll
        for (int j = 0; j < 2; j++) {
            int ch = cc + j;
            CP_ASYNC16(smaddr(&As[cr * H_LD + ch * 8]), &A[(size_t)(bm + cr) * K + ko + ch * 8]);
            CP_ASYNC16(smaddr(&Bs[cr * H_LD + ch * 8]), &W[(size_t)(bn + cr) * K + ko + ch * 8]);
        }
        CP_COMMIT();
    };

    const int nk = K / H_BK;
    issue(0);
    if (nk > 1) issue(1);

    for (int t = 0; t < nk; t++) {
        if (t == nk - 1) { CP_WAIT0(); } else { CP_WAIT1(); }
        __syncthreads();
        if (t + 2 < nk) issue(t + 2);

        const __half* bufp = smh + (t % 3) * H_BUF;
        const uint32_t a_base = smaddr(bufp + (warp_m + ar) * H_LD + ac);
        const uint32_t b_base = smaddr(bufp + 128 * H_LD + (warp_n + br) * H_LD + bc);

        #pragma unroll
        for (int ks = 0; ks < 2; ks++) {
            uint32_t a[4][4], b[4][2];
            #pragma unroll
            for (int mt = 0; mt < 4; mt++)
                LDSM4(a[mt][0], a[mt][1], a[mt][2], a[mt][3],
                      a_base + (uint32_t)((mt * 16 * H_LD + ks * 16) * 2));
            #pragma unroll
            for (int np = 0; np < 2; np++)
                LDSM4(b[2*np][0], b[2*np][1], b[2*np+1][0], b[2*np+1][1],
                      b_base + (uint32_t)((np * 16 * H_LD + ks * 16) * 2));
            #pragma unroll
            for (int mt = 0; mt < 4; mt++)
                #pragma unroll
                for (int nt = 0; nt < 4; nt++)
                    MMA_F16(c[mt][nt], a[mt], b[nt]);
        }
    }

    const int g  = lane >> 2;
    const int tg = lane & 3;
    #pragma unroll
    for (int mt = 0; mt < 4; mt++) {
        int row0 = bm + warp_m + mt * 16 + g;
        #pragma unroll
        for (int nt = 0; nt < 4; nt++) {
            int col = bn + warp_n + nt * 8 + tg * 2;
            float2 bb = *(const float2*)&bias[col];
            float2 o0, o1;
            o0.x = c[mt][nt][0] + bb.x;  o0.y = c[mt][nt][1] + bb.y;
            o1.x = c[mt][nt][2] + bb.x;  o1.y = c[mt][nt][3] + bb.y;
            if (RELU) {
                o0.x = fmaxf(o0.x, 0.f); o0.y = fmaxf(o0.y, 0.f);
                o1.x = fmaxf(o1.x, 0.f); o1.y = fmaxf(o1.y, 0.f);
            }
            *(float2*)&C[(size_t)row0 * N + col]       = o0;
            *(float2*)&C[(size_t)(row0 + 8) * N + col] = o1;
            if (C16) {
                *(__half2*)&C16[(size_t)row0 * N + col]       = __floats2half2_rn(o0.x, o0.y);
                *(__half2*)&C16[(size_t)(row0 + 8) * N + col] = __floats2half2_rn(o1.x, o1.y);
            }
        }
    }
}

// ================= exact FFMA2 SGEMM (final projection only) =================
template<int BM, int BN, int BK, int TM, int TN>
__global__ __launch_bounds__((BM/TM)*(BN/TN))
void gemm_bias(const float* __restrict__ A, const float* __restrict__ W,
               const float* __restrict__ bias, float* __restrict__ C,
               int M, int N, int K)
{
    constexpr int THREADS = (BM/TM)*(BN/TN);
    __shared__ __align__(16) float As[BK][BM];
    __shared__ __align__(16) float Bs[BK][BN];
    const int tid  = threadIdx.x;
    const int bm   = blockIdx.y * BM;
    const int bn   = blockIdx.x * BN;
    const int tcol = tid % (BN/TN);
    const int trow = tid / (BN/TN);

    ull acc2[TM][TN/2];
    #pragma unroll
    for (int i = 0; i < TM; i++)
        #pragma unroll
        for (int j = 0; j < TN/2; j++) acc2[i][j] = 0ull;

    constexpr int AF4 = BM * (BK/4);
    constexpr int BF4 = BN * (BK/4);

    for (int k0 = 0; k0 < K; k0 += BK) {
        #pragma unroll
        for (int i = tid; i < AF4; i += THREADS) {
            int r  = i / (BK/4);
            int c4 = i % (BK/4);
            float4 v = *(const float4*)&A[(size_t)(bm + r) * K + k0 + c4*4];
            As[c4*4+0][r] = v.x; As[c4*4+1][r] = v.y;
            As[c4*4+2][r] = v.z; As[c4*4+3][r] = v.w;
        }
        #pragma unroll
        for (int i = tid; i < BF4; i += THREADS) {
            int r  = i / (BK/4);
            int c4 = i % (BK/4);
            float4 v = *(const float4*)&W[(size_t)(bn + r) * K + k0 + c4*4];
            Bs[c4*4+0][r] = v.x; Bs[c4*4+1][r] = v.y;
            Bs[c4*4+2][r] = v.z; Bs[c4*4+3][r] = v.w;
        }
        __syncthreads();

        #pragma unroll
        for (int k = 0; k < BK; k++) {
            float ra[TM];
            #pragma unroll
            for (int i = 0; i < TM; i += 4) {
                float4 v = *(const float4*)&As[k][trow*TM + i];
                ra[i] = v.x; ra[i+1] = v.y; ra[i+2] = v.z; ra[i+3] = v.w;
            }
            ull ras[TM];
            #pragma unroll
            for (int i = 0; i < TM; i++) PACK2(ras[i], ra[i], ra[i]);

            ull rb2[TN/2];
            #pragma unroll
            for (int j4 = 0; j4 < TN/4; j4++) {
                ulonglong2 v = *(const ulonglong2*)&Bs[k][tcol*TN + j4*4];
                rb2[2*j4]   = v.x;
                rb2[2*j4+1] = v.y;
            }
            #pragma unroll
            for (int i = 0; i < TM; i++)
                #pragma unroll
                for (int j = 0; j < TN/2; j++)
                    FMA2(acc2[i][j], ras[i], rb2[j], acc2[i][j]);
        }
        __syncthreads();
    }

    #pragma unroll
    for (int i = 0; i < TM; i++) {
        size_t row = (size_t)(bm + trow*TM + i);
        float oc[TN];
        #pragma unroll
        for (int j = 0; j < TN/2; j++) UNPACK2(oc[2*j], oc[2*j+1], acc2[i][j]);
        #pragma unroll
        for (int j = 0; j < TN; j += 4) {
            int col = bn + tcol*TN + j;
            float4 b4 = *(const float4*)&bias[col];
            float4 o;
            o.x = oc[j+0] + b4.x;
            o.y = oc[j+1] + b4.y;
            o.z = oc[j+2] + b4.z;
            o.w = oc[j+3] + b4.w;
            *(float4*)&C[row * N + col] = o;
        }
    }
}

// ---------------- prep: transposes + zero + bias folds ----------------
__global__ __launch_bounds__(256)
void prep_kernel(const float* __restrict__ w_out1, const float* __restrict__ w_out2,
                 const float* __restrict__ w_lin,  const float* __restrict__ b_out1,
                 const float* __restrict__ b_lin,  const float* __restrict__ wkv2,
                 const float* __restrict__ b_out2, const float* __restrict__ bkv2,
                 float* __restrict__ wt, float* __restrict__ wt2, float* __restrict__ zb,
                 float* __restrict__ bcomb, float* __restrict__ bkv)
{
    const int b   = blockIdx.x;
    const int tid = threadIdx.x;

    if (b < 2048) {
        const float* in = (b < 1024) ? w_out1 : w_out2;
        float* out      = (b < 1024) ? wt : wt2;
        const int bb = b & 1023;
        const int bx = bb & 31, by = bb >> 5;
        __shared__ float tile[32][33];
        const int tx = tid & 31, ty = tid >> 5;
        #pragma unroll
        for (int j = 0; j < 32; j += 8)
            tile[ty + j][tx] = in[(size_t)(by*32 + ty + j) * DM + bx*32 + tx];
        __syncthreads();
        #pragma unroll
        for (int j = 0; j < 32; j += 8)
            out[(size_t)(bx*32 + ty + j) * DM + by*32 + tx] = tile[tx][ty + j];
    } else if (b < 2052) {
        zb[(b - 2048) * 256 + tid] = 0.f;
    } else {
        int bb = b - 2052;
        const float *W, *b1, *b2;
        float* out;
        if (bb < 128) { W = w_lin; b1 = b_out1; b2 = b_lin; out = bcomb; }
        else          { bb -= 128; W = wkv2; b1 = b_out2; b2 = bkv2; out = bkv; }
        const int n = bb * 8 + (tid >> 5);
        const int lane = tid & 31;
        float s = 0.f;
        for (int j = lane; j < DM; j += 32) s = fmaf(W[(size_t)n * DM + j], b1[j], s);
        #pragma unroll
        for (int o = 16; o; o >>= 1) s += __shfl_xor_sync(0xffffffffu, s, o);
        if (lane == 0) out[n] = s + b2[n];
    }
}

// all f32->f16 converts in ONE launch
__global__ __launch_bounds__(256)
void cvt_all(const float* __restrict__ path, const float* __restrict__ w_in1,
             const float* __restrict__ wcomb, const float* __restrict__ w_in2,
             const float* __restrict__ wkv,   const float* __restrict__ wkv2,
             __half* __restrict__ pathh, __half* __restrict__ win1h,
             __half* __restrict__ wcomb16, __half* __restrict__ win2q16,
             __half* __restrict__ wkvh, __half* __restrict__ wkv2h)
{
    int b = blockIdx.x;
    const float* src; __half* dst; int off;
    if      (b < 4096)  { src = path;  dst = pathh;   off = b; }
    else if (b < 7168)  { src = w_in1; dst = win1h;   off = b - 4096; }
    else if (b < 8192)  { src = wcomb; dst = wcomb16; off = b - 7168; }
    else if (b < 9216)  { src = w_in2; dst = win2q16; off = b - 8192; }
    else if (b < 11264) { src = wkv;   dst = wkvh;    off = b - 9216; }
    else                { src = wkv2;  dst = wkv2h;   off = b - 11264; }
    size_t i = (size_t)off * 1024 + threadIdx.x * 4;
    float4 v = *(const float4*)&src[i];
    *(__half2*)&dst[i]     = __floats2half2_rn(v.x, v.y);
    *(__half2*)&dst[i + 2] = __floats2half2_rn(v.z, v.w);
}

// ================= stage-2 attention via fp16 MMA =================
constexpr int AT_LD   = 72;
constexpr int AT_SMEM = (256 + 256 + 64) * AT_LD * 2;           // 82944 B

__global__ __launch_bounds__(128, 2)
void attn2_kernel(const __half* __restrict__ qkv, __half* __restrict__ obase, float scale)
{
    extern __shared__ __half smh[];
    __half* Kh = smh;
    __half* Vh = smh + 256 * AT_LD;
    __half* Qh = smh + 512 * AT_LD;

    const int h   = blockIdx.x;
    const int qt  = blockIdx.y;
    const int w   = blockIdx.z;
    const int tid = threadIdx.x;
    const int lane = tid & 31;
    const int wq  = tid >> 5;
    const int g   = lane >> 2;
    const int tg  = lane & 3;

    const __half* Kp = qkv + (size_t)w * STR * 3*DM + DM   + h * DH;
    const __half* Vp = qkv + (size_t)w * STR * 3*DM + 2*DM + h * DH;
    const __half* Qp = qkv + (size_t)(w * STR + qt * 64) * 3*DM + h * DH;

    for (int idx = tid; idx < 256 * 8; idx += 128) {
        int r = idx >> 3, c = idx & 7;
        CP_ASYNC16(smaddr(Kh + r * AT_LD + c*8), Kp + (size_t)r * 3*DM + c*8);
        CP_ASYNC16(smaddr(Vh + r * AT_LD + c*8), Vp + (size_t)r * 3*DM + c*8);
    }
    for (int idx = tid; idx < 64 * 8; idx += 128) {
        int r = idx >> 3, c = idx & 7;
        CP_ASYNC16(smaddr(Qh + r * AT_LD + c*8), Qp + (size_t)r * 3*DM + c*8);
    }
    CP_COMMIT();
    CP_WAIT0();
    __syncthreads();

    float S[32][4];
    #pragma unroll
    for (int j = 0; j < 32; j++)
        #pragma unroll
        for (int r = 0; r < 4; r++) S[j][r] = 0.f;

    const int ar  = (lane & 7) + ((lane >> 3) & 1) * 8;
    const int ach = (lane >> 4) * 8;
    const int br  = (lane & 7) + (lane >> 4) * 8;
    const int bch = ((lane >> 3) & 1) * 8;
    const uint32_t qa = smaddr(Qh + (wq*16 + ar) * AT_LD + ach);
    const uint32_t kb = smaddr(Kh + br * AT_LD + bch);

    #pragma unroll
    for (int kd = 0; kd < 4; kd++) {
        uint32_t a[4];
        LDSM4(a[0], a[1], a[2], a[3], qa + (uint32_t)(kd * 16 * 2));
        #pragma unroll
        for (int nt2 = 0; nt2 < 16; nt2++) {
            uint32_t b[2][2];
            LDSM4(b[0][0], b[0][1], b[1][0], b[1][1],
                  kb + (uint32_t)((nt2 * 16 * AT_LD + kd * 16) * 2));
            MMA_F16(S[2*nt2],     a, b[0]);
            MMA_F16(S[2*nt2 + 1], a, b[1]);
        }
    }

    float mx0 = -1e30f, mx1 = -1e30f;
    #pragma unroll
    for (int j = 0; j < 32; j++) {
        mx0 = fmaxf(mx0, fmaxf(S[j][0], S[j][1]));
        mx1 = fmaxf(mx1, fmaxf(S[j][2], S[j][3]));
    }
    mx0 = fmaxf(mx0, __shfl_xor_sync(0xffffffffu, mx0, 1));
    mx0 = fmaxf(mx0, __shfl_xor_sync(0xffffffffu, mx0, 2));
    mx1 = fmaxf(mx1, __shfl_xor_sync(0xffffffffu, mx1, 1));
    mx1 = fmaxf(mx1, __shfl_xor_sync(0xffffffffu, mx1, 2));

    float l0 = 0.f, l1 = 0.f;
    #pragma unroll
    for (int j = 0; j < 32; j++) {
        float p0 = __expf((S[j][0] - mx0) * scale);
        float p1 = __expf((S[j][1] - mx0) * scale);
        float p2 = __expf((S[j][2] - mx1) * scale);
        float p3 = __expf((S[j][3] - mx1) * scale);
        S[j][0] = p0; S[j][1] = p1; S[j][2] = p2; S[j][3] = p3;
        l0 += p0 + p1;
        l1 += p2 + p3;
    }
    l0 += __shfl_xor_sync(0xffffffffu, l0, 1);
    l0 += __shfl_xor_sync(0xffffffffu, l0, 2);
    l1 += __shfl_xor_sync(0xffffffffu, l1, 1);
    l1 += __shfl_xor_sync(0xffffffffu, l1, 2);
    const float inv0 = 1.f / l0;
    const float inv1 = 1.f / l1;

    float O[8][4];
    #pragma unroll
    for (int n = 0; n < 8; n++)
        #pragma unroll
        for (int r = 0; r < 4; r++) O[n][r] = 0.f;

    const int vr = (lane & 7) + ((lane >> 3) & 1) * 8;
    const int vc = (lane >> 4) * 8;
    const uint32_t vb = smaddr(Vh + vr * AT_LD + vc);

    #pragma unroll
    for (int j = 0; j < 16; j++) {
        uint32_t a[4];
        a[0] = pkh2(S[2*j][0],     S[2*j][1]);
        a[1] = pkh2(S[2*j][2],     S[2*j][3]);
        a[2] = pkh2(S[2*j + 1][0], S[2*j + 1][1]);
        a[3] = pkh2(S[2*j + 1][2], S[2*j + 1][3]);
        #pragma unroll
        for (int ntp = 0; ntp < 4; ntp++) {
            uint32_t b[2][2];
            LDSM4T(b[0][0], b[0][1], b[1][0], b[1][1],
                   vb + (uint32_t)((j * 16 * AT_LD + ntp * 16) * 2));
            MMA_F16(O[2*ntp],     a, b[0]);
            MMA_F16(O[2*ntp + 1], a, b[1]);
        }
    }

    const int qrow0 = qt * 64 + wq * 16 + g;
    __half* Ob0 = obase + (size_t)(w * KW + qrow0) * DM + h * DH;
    __half* Ob1 = Ob0 + (size_t)8 * DM;
    #pragma unroll
    for (int nt = 0; nt < 8; nt++) {
        int d = nt * 8 + tg * 2;
        *(__half2*)&Ob0[d] = __floats2half2_rn(O[nt][0] * inv0, O[nt][1] * inv0);
        *(__half2*)&Ob1[d] = __floats2half2_rn(O[nt][2] * inv1, O[nt][3] * inv1);
    }
}

// ================= persistent recurrence (fp16 MMA both phases) ======
constexpr int REC_NB   = 128;
constexpr int REC_SMEM = (32768 + 512) * (int)sizeof(float);   // 133120 B
constexpr int RH_BK  = 128;
constexpr int RH_LD  = RH_BK + 8;
constexpr int RH_BUF = (64 + 64) * RH_LD;

__device__ __forceinline__ void grid_bar(unsigned base, unsigned bar_id)
{
    __syncthreads();
    if (threadIdx.x == 0) {
        __threadfence();
        unsigned a = atomicAdd(&g_bar_arrive, 1u);
        if ((a & (REC_NB - 1u)) == (REC_NB - 1u)) {
            atomicAdd(&g_bar_release, 1u);
        } else {
            while (*(volatile unsigned*)&g_bar_release - base < bar_id) { }
        }
        __threadfence();
    }
    __syncthreads();
}

__global__ __launch_bounds__(256)
void recurrence_kernel(const __half* __restrict__ x16,
                       const __half* __restrict__ q2h,
                       const __half* __restrict__ wkv2h, const float* __restrict__ bkv2,
                       const __half* __restrict__ wkvh,  const float* __restrict__ bkvF,
                       __half* __restrict__ kvh, float* __restrict__ st,
                       __half* __restrict__ st16)
{
    extern __shared__ float sm[];
    __half* smh = (__half*)sm;
    const int tid = threadIdx.x;
    const int bid = blockIdx.x;

    __shared__ unsigned s_base;
    if (tid == 0) s_base = *(volatile unsigned*)&g_bar_release;
    __syncthreads();
    const unsigned base = s_base;

    if (bid == 0) {
        if (tid < 32)              g_flagA[tid]      = 0;
        else if (tid < 40)         g_flagB[tid - 32] = 0;
    }
    grid_bar(base, 1);

    const int lane = tid & 31, warp = tid >> 5;
    const int g = lane >> 2, tg = lane & 3;
    const int warp_m = (warp & 1) * 32;
    const int warp_n = (warp >> 1) * 16;
    const int tm = bid >> 5;
    const int tn = bid & 31;

    const int ar  = (lane & 7) + ((lane >> 3) & 1) * 8;
    const int ach = (lane >> 4) * 8;
    const int br  = (lane & 7) + (lane >> 4) * 8;
    const int bch = ((lane >> 3) & 1) * 8;

    const int h  = bid >> 3;
    const int qt = bid & 7;

    for (int i = 1; i < NWIN; i++) {
        __half* kvb      = kvh  + (size_t)(i & 1) * KW * 2 * ODIM;
        float*  stb      = st   + (size_t)(i & 1) * KW * ODIM;
        __half* st16b    = st16 + (size_t)(i & 1) * KW * ODIM;
        const __half* st16prev = st16 + (size_t)((i - 1) & 1) * KW * ODIM;

        // ===== Phase A: KV projection (fp16 MMA, BK=128 halfs) =====
        {
            if (i > 1 && tid == 0) {
                unsigned tgt = 16u * (unsigned)(i - 1);
                while (flag_acquire(&g_flagB[2*tm])     < tgt) { }
                while (flag_acquire(&g_flagB[2*tm + 1]) < tgt) { }
            }
            __syncthreads();

            const __half* A  = (i == 1) ? x16   : st16prev;
            const __half* W  = (i == 1) ? wkv2h : wkvh;
            const float*  bb = (i == 1) ? bkv2  : bkvF;

            float cacc[2][2][4];
            #pragma unroll
            for (int mt = 0; mt < 2; mt++)
                #pragma unroll
                for (int nt = 0; nt < 2; nt++)
                    #pragma unroll
                    for (int r = 0; r < 4; r++) cacc[mt][nt][r] = 0.f;

            const int crow = tid >> 2;
            const int cch  = (tid & 3) * 4;

            auto issue = [&](int t) {
                size_t ko = (size_t)t * RH_BK;
                __half* As = smh + (t % 3) * RH_BUF;
                __half* Bs = As + 64 * RH_LD;
                #pragma unroll
                for (int j = 0; j < 4; j++) {
                    int ch = cch + j;
                    CP_ASYNC16(smaddr(&As[crow * RH_LD + ch*8]), &A[(size_t)(tm*64 + crow) * 1024 + ko + ch*8]);
                    CP_ASYNC16(smaddr(&Bs[crow * RH_LD + ch*8]), &W[(size_t)(tn*64 + crow) * 1024 + ko + ch*8]);
                }
                CP_COMMIT();
            };

            issue(0);
            issue(1);
            for (int t = 0; t < 8; t++) {
                if (t == 7) { CP_WAIT0(); } else { CP_WAIT1(); }
                __syncthreads();
                if (t + 2 < 8) issue(t + 2);

                const __half* bufp = smh + (t % 3) * RH_BUF;
                const uint32_t a_base = smaddr(bufp + (warp_m + ar) * RH_LD + ach);
                const uint32_t b_base = smaddr(bufp + 64 * RH_LD + (warp_n + br) * RH_LD + bch);

                #pragma unroll
                for (int ks = 0; ks < 8; ks++) {
                    uint32_t a[2][4], b[2][2];
                    #pragma unroll
                    for (int mt = 0; mt < 2; mt++)
                        LDSM4(a[mt][0], a[mt][1], a[mt][2], a[mt][3],
                              a_base + (uint32_t)((mt * 16 * RH_LD + ks * 16) * 2));
                    LDSM4(b[0][0], b[0][1], b[1][0], b[1][1],
                          b_base + (uint32_t)((ks * 16) * 2));
                    #pragma unroll
                    for (int mt = 0; mt < 2; mt++)
                        #pragma unroll
                        for (int nt = 0; nt < 2; nt++)
                            MMA_F16(cacc[mt][nt], a[mt], b[nt]);
                }
            }

            #pragma unroll
            for (int mt = 0; mt < 2; mt++) {
                int row0 = tm*64 + warp_m + mt*16 + g;
                #pragma unroll
                for (int nt = 0; nt < 2; nt++) {
                    int col = tn*64 + warp_n + nt*8 + tg*2;
                    float2 bb2 = *(const float2*)&bb[col];
                    *(__half2*)&kvb[(size_t)row0 * 2048 + col] =
                        __floats2half2_rn(cacc[mt][nt][0] + bb2.x, cacc[mt][nt][1] + bb2.y);
                    *(__half2*)&kvb[(size_t)(row0 + 8) * 2048 + col] =
                        __floats2half2_rn(cacc[mt][nt][2] + bb2.x, cacc[mt][nt][3] + bb2.y);
                }
            }
            __syncthreads();
            if (tid == 0) flag_release(&g_flagA[tn]);
        }

        // ===== Phase B: attention (fp16 MMA, attn2 pattern, warps 0-1) =====
        {
            if (tid == 0) {
                unsigned tgt = 4u * (unsigned)i;
                while (flag_acquire(&g_flagA[h])      < tgt) { }
                while (flag_acquire(&g_flagA[16 + h]) < tgt) { }
            }
            __syncthreads();

            __half* Kh = smh;                  // 256 x 72
            __half* Vh = smh + 256 * AT_LD;    // 256 x 72
            __half* Qh = smh + 512 * AT_LD;    // 32 x 72

            const __half* Kp = kvb + h * DH;
            const __half* Vp = kvb + 1024 + h * DH;
            for (int idx = tid; idx < 256 * 8; idx += 256) {
                int r = idx >> 3, c = idx & 7;
                CP_ASYNC16(smaddr(Kh + r * AT_LD + c*8), Kp + (size_t)r * 2048 + c*8);
                CP_ASYNC16(smaddr(Vh + r * AT_LD + c*8), Vp + (size_t)r * 2048 + c*8);
            }
            const __half* Qp = q2h + (size_t)i * KW * ODIM + (size_t)(qt*32) * 1024 + h * DH;
            for (int idx = tid; idx < 32 * 8; idx += 256) {
                int r = idx >> 3, c = idx & 7;
                CP_ASYNC16(smaddr(Qh + r * AT_LD + c*8), Qp + (size_t)r * 1024 + c*8);
            }
            CP_COMMIT();
            CP_WAIT0();
            __syncthreads();

            if (warp < 2) {
                const int wq = warp;           // 16 queries each

                float S[32][4];
                #pragma unroll
                for (int j = 0; j < 32; j++)
                    #pragma unroll
                    for (int r = 0; r < 4; r++) S[j][r] = 0.f;

                const uint32_t qa = smaddr(Qh + (wq*16 + ar) * AT_LD + ach);
                const uint32_t kb = smaddr(Kh + br * AT_LD + bch);

                #pragma unroll
                for (int kd = 0; kd < 4; kd++) {
                    uint32_t a[4];
                    LDSM4(a[0], a[1], a[2], a[3], qa + (uint32_t)(kd * 16 * 2));
                    #pragma unroll
                    for (int nt2 = 0; nt2 < 16; nt2++) {
                        uint32_t b[2][2];
                        LDSM4(b[0][0], b[0][1], b[1][0], b[1][1],
                              kb + (uint32_t)((nt2 * 16 * AT_LD + kd * 16) * 2));
                        MMA_F16(S[2*nt2],     a, b[0]);
                        MMA_F16(S[2*nt2 + 1], a, b[1]);
                    }
                }

                float mx0 = -1e30f, mx1 = -1e30f;
                #pragma unroll
                for (int j = 0; j < 32; j++) {
                    mx0 = fmaxf(mx0, fmaxf(S[j][0], S[j][1]));
                    mx1 = fmaxf(mx1, fmaxf(S[j][2], S[j][3]));
                }
                mx0 = fmaxf(mx0, __shfl_xor_sync(0xffffffffu, mx0, 1));
                mx0 = fmaxf(mx0, __shfl_xor_sync(0xffffffffu, mx0, 2));
                mx1 = fmaxf(mx1, __shfl_xor_sync(0xffffffffu, mx1, 1));
                mx1 = fmaxf(mx1, __shfl_xor_sync(0xffffffffu, mx1, 2));

                float l0 = 0.f, l1 = 0.f;
                #pragma unroll
                for (int j = 0; j < 32; j++) {
                    float p0 = __expf((S[j][0] - mx0) * 0.125f);
                    float p1 = __expf((S[j][1] - mx0) * 0.125f);
                    float p2 = __expf((S[j][2] - mx1) * 0.125f);
                    float p3 = __expf((S[j][3] - mx1) * 0.125f);
                    S[j][0] = p0; S[j][1] = p1; S[j][2] = p2; S[j][3] = p3;
                    l0 += p0 + p1;
                    l1 += p2 + p3;
                }
                l0 += __shfl_xor_sync(0xffffffffu, l0, 1);
                l0 += __shfl_xor_sync(0xffffffffu, l0, 2);
                l1 += __shfl_xor_sync(0xffffffffu, l1, 1);
                l1 += __shfl_xor_sync(0xffffffffu, l1, 2);
                const float inv0 = 1.f / l0;
                const float inv1 = 1.f / l1;

                float O[8][4];
                #pragma unroll
                for (int n = 0; n < 8; n++)
                    #pragma unroll
                    for (int r = 0; r < 4; r++) O[n][r] = 0.f;

                const int vr = (lane & 7) + ((lane >> 3) & 1) * 8;
                const int vc = (lane >> 4) * 8;
                const uint32_t vb = smaddr(Vh + vr * AT_LD + vc);

                #pragma unroll
                for (int j = 0; j < 16; j++) {
                    uint32_t a[4];
                    a[0] = pkh2(S[2*j][0],     S[2*j][1]);
                    a[1] = pkh2(S[2*j][2],     S[2*j][3]);
                    a[2] = pkh2(S[2*j + 1][0], S[2*j + 1][1]);
                    a[3] = pkh2(S[2*j + 1][2], S[2*j + 1][3]);
                    #pragma unroll
                    for (int ntp = 0; ntp < 4; ntp++) {
                        uint32_t b[2][2];
                        LDSM4T(b[0][0], b[0][1], b[1][0], b[1][1],
                               vb + (uint32_t)((j * 16 * AT_LD + ntp * 16) * 2));
                        MMA_F16(O[2*ntp],     a, b[0]);
                        MMA_F16(O[2*ntp + 1], a, b[1]);
                    }
                }

                const int qrow0 = qt * 32 + wq * 16 + g;
                float*  S0 = stb   + (size_t)qrow0 * 1024 + h * DH;
                float*  S1 = S0 + (size_t)8 * 1024;
                __half* H0 = st16b + (size_t)qrow0 * 1024 + h * DH;
                __half* H1 = H0 + (size_t)8 * 1024;
                #pragma unroll
                for (int nt = 0; nt < 8; nt++) {
                    int d = nt * 8 + tg * 2;
                    float o00 = O[nt][0] * inv0, o01 = O[nt][1] * inv0;
                    float o10 = O[nt][2] * inv1, o11 = O[nt][3] * inv1;
                    *(float2*)&S0[d] = make_float2(o00, o01);
                    *(float2*)&S1[d] = make_float2(o10, o11);
                    *(__half2*)&H0[d] = __floats2half2_rn(o00, o01);
                    *(__half2*)&H1[d] = __floats2half2_rn(o10, o11);
                }
            }
            __syncthreads();
            if (tid == 0) flag_release(&g_flagB[qt]);
        }
    }
}

// ---------------- host ----------------
extern "C" void kernel_launch(void* const* d_in, const int* in_sizes, int n_in,
                              void* d_out, int out_size)
{
    const float* path   = (const float*)d_in[0];
    const float* w_in1  = (const float*)d_in[1];
    const float* b_in1  = (const float*)d_in[2];
    const float* w_out1 = (const float*)d_in[3];
    const float* b_out1 = (const float*)d_in[4];
    const float* w_lin  = (const float*)d_in[5];
    const float* b_lin  = (const float*)d_in[6];
    const float* w_in2  = (const float*)d_in[7];
    const float* b_in2  = (const float*)d_in[8];
    const float* w_out2 = (const float*)d_in[9];
    const float* b_out2 = (const float*)d_in[10];

    float *qkv1, *x, *q2, *st, *wt, *wt2, *wcomb, *bcomb, *wkv, *bkv, *zb;
    __half *qkv1h, *pathh, *win1h, *attn1h, *x16, *q2h, *kvh, *wcomb16, *win2q16, *wkvh, *wkv2h, *st16;
    cudaGetSymbolAddress((void**)&qkv1,    g_qkv1);
    cudaGetSymbolAddress((void**)&qkv1h,   g_qkv1h);
    cudaGetSymbolAddress((void**)&pathh,   g_pathh);
    cudaGetSymbolAddress((void**)&win1h,   g_win1h);
    cudaGetSymbolAddress((void**)&attn1h,  g_attn1h);
    cudaGetSymbolAddress((void**)&x,       g_x);
    cudaGetSymbolAddress((void**)&x16,     g_x16);
    cudaGetSymbolAddress((void**)&q2,      g_q2);
    cudaGetSymbolAddress((void**)&q2h,     g_q2h);
    cudaGetSymbolAddress((void**)&kvh,     g_kvh);
    cudaGetSymbolAddress((void**)&st,      g_st);
    cudaGetSymbolAddress((void**)&st16,    g_st16);
    cudaGetSymbolAddress((void**)&wt,      g_wt);
    cudaGetSymbolAddress((void**)&wt2,     g_wt2);
    cudaGetSymbolAddress((void**)&wcomb,   g_wcomb);
    cudaGetSymbolAddress((void**)&wcomb16, g_wcomb16);
    cudaGetSymbolAddress((void**)&win2q16, g_win2q16);
    cudaGetSymbolAddress((void**)&bcomb,   g_bcomb);
    cudaGetSymbolAddress((void**)&wkv,     g_wkv);
    cudaGetSymbolAddress((void**)&wkvh,    g_wkvh);
    cudaGetSymbolAddress((void**)&wkv2h,   g_wkv2h);
    cudaGetSymbolAddress((void**)&bkv,     g_bkv);
    cudaGetSymbolAddress((void**)&zb,      g_zb);

    cudaFuncSetAttribute(attn2_kernel,       cudaFuncAttributeMaxDynamicSharedMemorySize, AT_SMEM);
    cudaFuncSetAttribute(gemm_tf32<false>,   cudaFuncAttributeMaxDynamicSharedMemorySize, TF_SMEM);
    cudaFuncSetAttribute(gemm_fp16<false>,   cudaFuncAttributeMaxDynamicSharedMemorySize, H_SMEM);
    cudaFuncSetAttribute(gemm_fp16<true>,    cudaFuncAttributeMaxDynamicSharedMemorySize, H_SMEM);
    cudaFuncSetAttribute(recurrence_kernel,  cudaFuncAttributeMaxDynamicSharedMemorySize, REC_SMEM);
    cudaFuncSetAttribute(attn2_kernel,       cudaFuncAttributePreferredSharedMemoryCarveout, 100);
    cudaFuncSetAttribute(gemm_tf32<false>,   cudaFuncAttributePreferredSharedMemoryCarveout, 100);
    cudaFuncSetAttribute(gemm_fp16<false>,   cudaFuncAttributePreferredSharedMemoryCarveout, 100);
    cudaFuncSetAttribute(gemm_fp16<true>,    cudaFuncAttributePreferredSharedMemoryCarveout, 100);

    auto g64  = gemm_bias<64,64,16,4,4>;
    auto t32  = gemm_tf32<false>;
    auto h16  = gemm_fp16<false>;
    auto h16r = gemm_fp16<true>;

    const float* wkv2 = w_in2 + (size_t)ODIM * ODIM;
    const float* bkv2 = b_in2 + ODIM;

    // 0: prologue prep
    prep_kernel<<<2052 + 128 + 256, 256>>>(w_out1, w_out2, w_lin, b_out1, b_lin,
                                           wkv2, b_out2, bkv2, wt, wt2, zb, bcomb, bkv);
    // 1-2: weight folds (tf32)
    t32<<<dim3(DM/128, DM/128), 256, TF_SMEM>>>(w_lin, wt, zb, wcomb, DM, DM, DM);
    t32<<<dim3(DM/128, 2*ODIM/128), 256, TF_SMEM>>>(wkv2, wt2, zb, wkv, 2*ODIM, DM, DM);

    // 3: all f32->f16 converts
    cvt_all<<<13312, 256>>>(path, w_in1, wcomb, w_in2, wkv, wkv2,
                            pathh, win1h, wcomb16, win2q16, wkvh, wkv2h);

    // 4: stage 1 QKV (fp16 MMA)
    h16<<<dim3(3*DM/128, SEQ/128), 256, H_SMEM>>>(pathh, win1h, b_in1, qkv1, qkv1h, SEQ, 3*DM, DM);

    // 5: stage 2 window self-attention (fp16 MMA)
    attn2_kernel<<<dim3(NH, KW/64, NWIN), 128, AT_SMEM>>>(qkv1h, attn1h, 0.125f);

    // 6: stage 3 fused outproj1 + linear + relu (fp16 MMA)
    h16r<<<dim3(ODIM/128, ROWS/128), 256, H_SMEM>>>(attn1h, wcomb16, bcomb, x, x16, ROWS, ODIM, DM);

    // 7: stage 4a bulk Q2 projections (fp16 MMA) -> q2 fp32 scratch + q2h
    h16<<<dim3(ODIM/128, ROWS/128), 256, H_SMEM>>>(x16, win2q16, b_in2, q2, q2h, ROWS, ODIM, ODIM);

    // 8: persistent recurrence (fp16 MMA phases A and B)
    recurrence_kernel<<<REC_NB, 256, REC_SMEM>>>(x16, q2h, wkv2h, bkv2, wkvh, bkv, kvh, st, st16);

    // 9: final out-projection (exact fp32 -> d_out)
    g64<<<dim3(ODIM/64, KW/64), 256>>>(st + (size_t)((NWIN-1)&1) * KW * ODIM,
                                       w_out2, b_out2, (float*)d_out, KW, ODIM, ODIM);
}

// round 16
// speedup vs baseline: 2.6425x; 1.0277x over previous
#include <cuda_runtime.h>
#include <cuda_fp16.h>
#include <math.h>
#include <stdint.h>

// ---------------- problem constants ----------------
constexpr int SEQ  = 4096;
constexpr int DM   = 1024;
constexpr int ODIM = 1024;
constexpr int KW   = 256;
constexpr int STR  = 16;
constexpr int NH   = 16;
constexpr int DH   = 64;
constexpr int NWIN = (SEQ - KW) / STR;   // 240
constexpr int ROWS = NWIN * KW;          // 61440

typedef unsigned long long ull;

// packed fp32x2 helpers
#define PACK2(o, lo, hi)   asm("mov.b64 %0, {%1,%2};" : "=l"(o) : "f"(lo), "f"(hi))
#define UNPACK2(lo, hi, i) asm("mov.b64 {%0,%1}, %2;" : "=f"(lo), "=f"(hi) : "l"(i))
#define FMA2(d, a, b, c)   asm("fma.rn.f32x2 %0, %1, %2, %3;" : "=l"(d) : "l"(a), "l"(b), "l"(c))

__device__ __forceinline__ uint32_t smaddr(const void* p) {
    return (uint32_t)__cvta_generic_to_shared(p);
}
__device__ __forceinline__ uint32_t pkh2(float x, float y) {
    __half2 h = __floats2half2_rn(x, y);
    return *(uint32_t*)&h;
}

#define CP_ASYNC16(sm_u32, gptr) \
    asm volatile("cp.async.cg.shared.global [%0], [%1], 16;" :: "r"(sm_u32), "l"(gptr))
#define CP_COMMIT() asm volatile("cp.async.commit_group;")
#define CP_WAIT0()  asm volatile("cp.async.wait_group 0;")
#define CP_WAIT1()  asm volatile("cp.async.wait_group 1;")

#define LDSM4(r0, r1, r2, r3, addr) \
    asm volatile("ldmatrix.sync.aligned.m8n8.x4.shared.b16 {%0,%1,%2,%3}, [%4];" \
        : "=r"(r0), "=r"(r1), "=r"(r2), "=r"(r3) : "r"(addr))
#define LDSM4T(r0, r1, r2, r3, addr) \
    asm volatile("ldmatrix.sync.aligned.m8n8.x4.trans.shared.b16 {%0,%1,%2,%3}, [%4];" \
        : "=r"(r0), "=r"(r1), "=r"(r2), "=r"(r3) : "r"(addr))

#define MMA_F16(c, a, b) \
    asm volatile("mma.sync.aligned.m16n8k16.row.col.f32.f16.f16.f32 " \
        "{%0,%1,%2,%3},{%4,%5,%6,%7},{%8,%9},{%0,%1,%2,%3};" \
        : "+f"((c)[0]), "+f"((c)[1]), "+f"((c)[2]), "+f"((c)[3]) \
        : "r"((a)[0]), "r"((a)[1]), "r"((a)[2]), "r"((a)[3]), "r"((b)[0]), "r"((b)[1]))

// release/acquire flag ops
__device__ __forceinline__ void flag_release(unsigned* f) {
    unsigned old;
    asm volatile("atom.release.gpu.global.add.u32 %0, [%1], 1;" : "=r"(old) : "l"(f) : "memory");
}
__device__ __forceinline__ unsigned flag_acquire(unsigned* f) {
    unsigned v;
    asm volatile("ld.acquire.gpu.global.u32 %0, [%1];" : "=r"(v) : "l"(f) : "memory");
    return v;
}

// ---------------- scratch ----------------
__device__ __half g_qkv1h[SEQ * 3 * DM];
__device__ __half g_pathh[SEQ * DM];
__device__ __half g_win1h[3 * DM * DM];
__device__ __half g_attn1h[ROWS * DM];
__device__ __half g_x16[ROWS * ODIM];
__device__ __half g_q2h[ROWS * ODIM];
__device__ __half g_kvh[2 * KW * 2 * ODIM];  // fp16 KV, double-buffered by parity
__device__ float  g_st[2 * KW * ODIM];       // fp32 state (final projection)
__device__ __half g_st16[2 * KW * ODIM];     // fp16 shadow (phase A input)
__device__ __half g_wt16[DM * DM];           // w_out1^T fp16
__device__ __half g_wt2h[DM * DM];           // w_out2^T fp16
__device__ __half g_wlinh[DM * DM];
__device__ __half g_wcomb16[DM * DM];
__device__ __half g_win2q16[ODIM * DM];
__device__ float  g_bcomb[DM];
__device__ __half g_wkvh[2 * ODIM * DM];     // folded KV weights, fp16 (from fold gemm)
__device__ __half g_wkv2h[2 * ODIM * DM];
__device__ float  g_bkv[2 * ODIM];
__device__ float  g_zb[DM];

// persistent-kernel sync state (monotonic; replay-safe)
__device__ unsigned g_bar_arrive  = 0;
__device__ unsigned g_bar_release = 0;
__device__ unsigned g_flagA[32];
__device__ unsigned g_flagB[8];

// ================= FP16 tensor-core GEMM, 128x128 tiles =================
constexpr int H_BK  = 32;
constexpr int H_LD  = H_BK + 8;
constexpr int H_BUF = (128 + 128) * H_LD;
constexpr int H_SMEM = 3 * H_BUF * 2;

template<bool RELU>
__global__ __launch_bounds__(256, 2)
void gemm_fp16(const __half* __restrict__ A, const __half* __restrict__ W,
               const float* __restrict__ bias, float* __restrict__ C,
               __half* __restrict__ C16, int M, int N, int K)
{
    extern __shared__ __half smh[];
    const int tid    = threadIdx.x;
    const int lane   = tid & 31;
    const int warp   = tid >> 5;
    const int warp_m = (warp & 1) * 64;
    const int warp_n = (warp >> 1) * 32;
    const int bm     = blockIdx.y * 128;
    const int bn     = blockIdx.x * 128;

    const int ar = (lane & 7) + ((lane >> 3) & 1) * 8;
    const int ac = (lane >> 4) * 8;
    const int br = (lane & 7) + (lane >> 4) * 8;
    const int bc = ((lane >> 3) & 1) * 8;

    float c[4][4][4];
    #pragma unroll
    for (int i = 0; i < 4; i++)
        #pragma unroll
        for (int j = 0; j < 4; j++)
            #pragma unroll
            for (int r = 0; r < 4; r++) c[i][j][r] = 0.f;

    const int cr = tid >> 1;
    const int cc = (tid & 1) * 2;

    auto issue = [&](int t) {
        const size_t ko = (size_t)t * H_BK;
        __half* As = smh + (t % 3) * H_BUF;
        __half* Bs = As + 128 * H_LD;
        #pragma unroll
        for (int j = 0; j < 2; j++) {
            int ch = cc + j;
            CP_ASYNC16(smaddr(&As[cr * H_LD + ch * 8]), &A[(size_t)(bm + cr) * K + ko + ch * 8]);
            CP_ASYNC16(smaddr(&Bs[cr * H_LD + ch * 8]), &W[(size_t)(bn + cr) * K + ko + ch * 8]);
        }
        CP_COMMIT();
    };

    const int nk = K / H_BK;
    issue(0);
    if (nk > 1) issue(1);

    for (int t = 0; t < nk; t++) {
        if (t == nk - 1) { CP_WAIT0(); } else { CP_WAIT1(); }
        __syncthreads();
        if (t + 2 < nk) issue(t + 2);

        const __half* bufp = smh + (t % 3) * H_BUF;
        const uint32_t a_base = smaddr(bufp + (warp_m + ar) * H_LD + ac);
        const uint32_t b_base = smaddr(bufp + 128 * H_LD + (warp_n + br) * H_LD + bc);

        #pragma unroll
        for (int ks = 0; ks < 2; ks++) {
            uint32_t a[4][4], b[4][2];
            #pragma unroll
            for (int mt = 0; mt < 4; mt++)
                LDSM4(a[mt][0], a[mt][1], a[mt][2], a[mt][3],
                      a_base + (uint32_t)((mt * 16 * H_LD + ks * 16) * 2));
            #pragma unroll
            for (int np = 0; np < 2; np++)
                LDSM4(b[2*np][0], b[2*np][1], b[2*np+1][0], b[2*np+1][1],
                      b_base + (uint32_t)((np * 16 * H_LD + ks * 16) * 2));
            #pragma unroll
            for (int mt = 0; mt < 4; mt++)
                #pragma unroll
                for (int nt = 0; nt < 4; nt++)
                    MMA_F16(c[mt][nt], a[mt], b[nt]);
        }
    }

    const int g  = lane >> 2;
    const int tg = lane & 3;
    #pragma unroll
    for (int mt = 0; mt < 4; mt++) {
        int row0 = bm + warp_m + mt * 16 + g;
        #pragma unroll
        for (int nt = 0; nt < 4; nt++) {
            int col = bn + warp_n + nt * 8 + tg * 2;
            float2 bb = *(const float2*)&bias[col];
            float2 o0, o1;
            o0.x = c[mt][nt][0] + bb.x;  o0.y = c[mt][nt][1] + bb.y;
            o1.x = c[mt][nt][2] + bb.x;  o1.y = c[mt][nt][3] + bb.y;
            if (RELU) {
                o0.x = fmaxf(o0.x, 0.f); o0.y = fmaxf(o0.y, 0.f);
                o1.x = fmaxf(o1.x, 0.f); o1.y = fmaxf(o1.y, 0.f);
            }
            if (C) {
                *(float2*)&C[(size_t)row0 * N + col]       = o0;
                *(float2*)&C[(size_t)(row0 + 8) * N + col] = o1;
            }
            if (C16) {
                *(__half2*)&C16[(size_t)row0 * N + col]       = __floats2half2_rn(o0.x, o0.y);
                *(__half2*)&C16[(size_t)(row0 + 8) * N + col] = __floats2half2_rn(o1.x, o1.y);
            }
        }
    }
}

// ================= exact FFMA2 SGEMM (final projection only) =================
template<int BM, int BN, int BK, int TM, int TN>
__global__ __launch_bounds__((BM/TM)*(BN/TN))
void gemm_bias(const float* __restrict__ A, const float* __restrict__ W,
               const float* __restrict__ bias, float* __restrict__ C,
               int M, int N, int K)
{
    constexpr int THREADS = (BM/TM)*(BN/TN);
    __shared__ __align__(16) float As[BK][BM];
    __shared__ __align__(16) float Bs[BK][BN];
    const int tid  = threadIdx.x;
    const int bm   = blockIdx.y * BM;
    const int bn   = blockIdx.x * BN;
    const int tcol = tid % (BN/TN);
    const int trow = tid / (BN/TN);

    ull acc2[TM][TN/2];
    #pragma unroll
    for (int i = 0; i < TM; i++)
        #pragma unroll
        for (int j = 0; j < TN/2; j++) acc2[i][j] = 0ull;

    constexpr int AF4 = BM * (BK/4);
    constexpr int BF4 = BN * (BK/4);

    for (int k0 = 0; k0 < K; k0 += BK) {
        #pragma unroll
        for (int i = tid; i < AF4; i += THREADS) {
            int r  = i / (BK/4);
            int c4 = i % (BK/4);
            float4 v = *(const float4*)&A[(size_t)(bm + r) * K + k0 + c4*4];
            As[c4*4+0][r] = v.x; As[c4*4+1][r] = v.y;
            As[c4*4+2][r] = v.z; As[c4*4+3][r] = v.w;
        }
        #pragma unroll
        for (int i = tid; i < BF4; i += THREADS) {
            int r  = i / (BK/4);
            int c4 = i % (BK/4);
            float4 v = *(const float4*)&W[(size_t)(bn + r) * K + k0 + c4*4];
            Bs[c4*4+0][r] = v.x; Bs[c4*4+1][r] = v.y;
            Bs[c4*4+2][r] = v.z; Bs[c4*4+3][r] = v.w;
        }
        __syncthreads();

        #pragma unroll
        for (int k = 0; k < BK; k++) {
            float ra[TM];
            #pragma unroll
            for (int i = 0; i < TM; i += 4) {
                float4 v = *(const float4*)&As[k][trow*TM + i];
                ra[i] = v.x; ra[i+1] = v.y; ra[i+2] = v.z; ra[i+3] = v.w;
            }
            ull ras[TM];
            #pragma unroll
            for (int i = 0; i < TM; i++) PACK2(ras[i], ra[i], ra[i]);

            ull rb2[TN/2];
            #pragma unroll
            for (int j4 = 0; j4 < TN/4; j4++) {
                ulonglong2 v = *(const ulonglong2*)&Bs[k][tcol*TN + j4*4];
                rb2[2*j4]   = v.x;
                rb2[2*j4+1] = v.y;
            }
            #pragma unroll
            for (int i = 0; i < TM; i++)
                #pragma unroll
                for (int j = 0; j < TN/2; j++)
                    FMA2(acc2[i][j], ras[i], rb2[j], acc2[i][j]);
        }
        __syncthreads();
    }

    #pragma unroll
    for (int i = 0; i < TM; i++) {
        size_t row = (size_t)(bm + trow*TM + i);
        float oc[TN];
        #pragma unroll
        for (int j = 0; j < TN/2; j++) UNPACK2(oc[2*j], oc[2*j+1], acc2[i][j]);
        #pragma unroll
        for (int j = 0; j < TN; j += 4) {
            int col = bn + tcol*TN + j;
            float4 b4 = *(const float4*)&bias[col];
            float4 o;
            o.x = oc[j+0] + b4.x;
            o.y = oc[j+1] + b4.y;
            o.z = oc[j+2] + b4.z;
            o.w = oc[j+3] + b4.w;
            *(float4*)&C[row * N + col] = o;
        }
    }
}

// ---------------- prep: fp16 transposes + zero + bias folds ----------------
__global__ __launch_bounds__(256)
void prep_kernel(const float* __restrict__ w_out1, const float* __restrict__ w_out2,
                 const float* __restrict__ w_lin,  const float* __restrict__ b_out1,
                 const float* __restrict__ b_lin,  const float* __restrict__ wkv2,
                 const float* __restrict__ b_out2, const float* __restrict__ bkv2,
                 __half* __restrict__ wt16, __half* __restrict__ wt2h,
                 float* __restrict__ zb,
                 float* __restrict__ bcomb, float* __restrict__ bkv)
{
    const int b   = blockIdx.x;
    const int tid = threadIdx.x;

    if (b < 2048) {  // two 1024x1024 transposes -> fp16
        const float* in = (b < 1024) ? w_out1 : w_out2;
        __half* out     = (b < 1024) ? wt16 : wt2h;
        const int bb = b & 1023;
        const int bx = bb & 31, by = bb >> 5;
        __shared__ float tile[32][33];
        const int tx = tid & 31, ty = tid >> 5;
        #pragma unroll
        for (int j = 0; j < 32; j += 8)
            tile[ty + j][tx] = in[(size_t)(by*32 + ty + j) * DM + bx*32 + tx];
        __syncthreads();
        #pragma unroll
        for (int j = 0; j < 32; j += 8)
            out[(size_t)(bx*32 + ty + j) * DM + by*32 + tx] = __float2half_rn(tile[tx][ty + j]);
    } else if (b < 2052) {
        zb[(b - 2048) * 256 + tid] = 0.f;
    } else {
        int bb = b - 2052;
        const float *W, *b1, *b2;
        float* out;
        if (bb < 128) { W = w_lin; b1 = b_out1; b2 = b_lin; out = bcomb; }
        else          { bb -= 128; W = wkv2; b1 = b_out2; b2 = bkv2; out = bkv; }
        const int n = bb * 8 + (tid >> 5);
        const int lane = tid & 31;
        float s = 0.f;
        for (int j = lane; j < DM; j += 32) s = fmaf(W[(size_t)n * DM + j], b1[j], s);
        #pragma unroll
        for (int o = 16; o; o >>= 1) s += __shfl_xor_sync(0xffffffffu, s, o);
        if (lane == 0) out[n] = s + b2[n];
    }
}

// f32->f16 converts in ONE launch: pathh, win1h, win2q16, wkv2h, wlinh
__global__ __launch_bounds__(256)
void cvt_all(const float* __restrict__ path, const float* __restrict__ w_in1,
             const float* __restrict__ w_in2, const float* __restrict__ wkv2,
             const float* __restrict__ w_lin,
             __half* __restrict__ pathh, __half* __restrict__ win1h,
             __half* __restrict__ win2q16, __half* __restrict__ wkv2h,
             __half* __restrict__ wlinh)
{
    int b = blockIdx.x;
    const float* src; __half* dst; int off;
    if      (b < 4096)  { src = path;  dst = pathh;   off = b; }
    else if (b < 7168)  { src = w_in1; dst = win1h;   off = b - 4096; }
    else if (b < 8192)  { src = w_in2; dst = win2q16; off = b - 7168; }
    else if (b < 10240) { src = wkv2;  dst = wkv2h;   off = b - 8192; }
    else                { src = w_lin; dst = wlinh;   off = b - 10240; }
    size_t i = (size_t)off * 1024 + threadIdx.x * 4;
    float4 v = *(const float4*)&src[i];
    *(__half2*)&dst[i]     = __floats2half2_rn(v.x, v.y);
    *(__half2*)&dst[i + 2] = __floats2half2_rn(v.z, v.w);
}

// ================= stage-2 attention via fp16 MMA =================
constexpr int AT_LD   = 72;
constexpr int AT_SMEM = (256 + 256 + 64) * AT_LD * 2;           // 82944 B

__global__ __launch_bounds__(128, 2)
void attn2_kernel(const __half* __restrict__ qkv, __half* __restrict__ obase, float scale)
{
    extern __shared__ __half smh[];
    __half* Kh = smh;
    __half* Vh = smh + 256 * AT_LD;
    __half* Qh = smh + 512 * AT_LD;

    const int h   = blockIdx.x;
    const int qt  = blockIdx.y;
    const int w   = blockIdx.z;
    const int tid = threadIdx.x;
    const int lane = tid & 31;
    const int wq  = tid >> 5;
    const int g   = lane >> 2;
    const int tg  = lane & 3;

    const __half* Kp = qkv + (size_t)w * STR * 3*DM + DM   + h * DH;
    const __half* Vp = qkv + (size_t)w * STR * 3*DM + 2*DM + h * DH;
    const __half* Qp = qkv + (size_t)(w * STR + qt * 64) * 3*DM + h * DH;

    for (int idx = tid; idx < 256 * 8; idx += 128) {
        int r = idx >> 3, c = idx & 7;
        CP_ASYNC16(smaddr(Kh + r * AT_LD + c*8), Kp + (size_t)r * 3*DM + c*8);
        CP_ASYNC16(smaddr(Vh + r * AT_LD + c*8), Vp + (size_t)r * 3*DM + c*8);
    }
    for (int idx = tid; idx < 64 * 8; idx += 128) {
        int r = idx >> 3, c = idx & 7;
        CP_ASYNC16(smaddr(Qh + r * AT_LD + c*8), Qp + (size_t)r * 3*DM + c*8);
    }
    CP_COMMIT();
    CP_WAIT0();
    __syncthreads();

    float S[32][4];
    #pragma unroll
    for (int j = 0; j < 32; j++)
        #pragma unroll
        for (int r = 0; r < 4; r++) S[j][r] = 0.f;

    const int ar  = (lane & 7) + ((lane >> 3) & 1) * 8;
    const int ach = (lane >> 4) * 8;
    const int br  = (lane & 7) + (lane >> 4) * 8;
    const int bch = ((lane >> 3) & 1) * 8;
    const uint32_t qa = smaddr(Qh + (wq*16 + ar) * AT_LD + ach);
    const uint32_t kb = smaddr(Kh + br * AT_LD + bch);

    #pragma unroll
    for (int kd = 0; kd < 4; kd++) {
        uint32_t a[4];
        LDSM4(a[0], a[1], a[2], a[3], qa + (uint32_t)(kd * 16 * 2));
        #pragma unroll
        for (int nt2 = 0; nt2 < 16; nt2++) {
            uint32_t b[2][2];
            LDSM4(b[0][0], b[0][1], b[1][0], b[1][1],
                  kb + (uint32_t)((nt2 * 16 * AT_LD + kd * 16) * 2));
            MMA_F16(S[2*nt2],     a, b[0]);
            MMA_F16(S[2*nt2 + 1], a, b[1]);
        }
    }

    float mx0 = -1e30f, mx1 = -1e30f;
    #pragma unroll
    for (int j = 0; j < 32; j++) {
        mx0 = fmaxf(mx0, fmaxf(S[j][0], S[j][1]));
        mx1 = fmaxf(mx1, fmaxf(S[j][2], S[j][3]));
    }
    mx0 = fmaxf(mx0, __shfl_xor_sync(0xffffffffu, mx0, 1));
    mx0 = fmaxf(mx0, __shfl_xor_sync(0xffffffffu, mx0, 2));
    mx1 = fmaxf(mx1, __shfl_xor_sync(0xffffffffu, mx1, 1));
    mx1 = fmaxf(mx1, __shfl_xor_sync(0xffffffffu, mx1, 2));

    float l0 = 0.f, l1 = 0.f;
    #pragma unroll
    for (int j = 0; j < 32; j++) {
        float p0 = __expf((S[j][0] - mx0) * scale);
        float p1 = __expf((S[j][1] - mx0) * scale);
        float p2 = __expf((S[j][2] - mx1) * scale);
        float p3 = __expf((S[j][3] - mx1) * scale);
        S[j][0] = p0; S[j][1] = p1; S[j][2] = p2; S[j][3] = p3;
        l0 += p0 + p1;
        l1 += p2 + p3;
    }
    l0 += __shfl_xor_sync(0xffffffffu, l0, 1);
    l0 += __shfl_xor_sync(0xffffffffu, l0, 2);
    l1 += __shfl_xor_sync(0xffffffffu, l1, 1);
    l1 += __shfl_xor_sync(0xffffffffu, l1, 2);
    const float inv0 = 1.f / l0;
    const float inv1 = 1.f / l1;

    float O[8][4];
    #pragma unroll
    for (int n = 0; n < 8; n++)
        #pragma unroll
        for (int r = 0; r < 4; r++) O[n][r] = 0.f;

    const int vr = (lane & 7) + ((lane >> 3) & 1) * 8;
    const int vc = (lane >> 4) * 8;
    const uint32_t vb = smaddr(Vh + vr * AT_LD + vc);

    #pragma unroll
    for (int j = 0; j < 16; j++) {
        uint32_t a[4];
        a[0] = pkh2(S[2*j][0],     S[2*j][1]);
        a[1] = pkh2(S[2*j][2],     S[2*j][3]);
        a[2] = pkh2(S[2*j + 1][0], S[2*j + 1][1]);
        a[3] = pkh2(S[2*j + 1][2], S[2*j + 1][3]);
        #pragma unroll
        for (int ntp = 0; ntp < 4; ntp++) {
            uint32_t b[2][2];
            LDSM4T(b[0][0], b[0][1], b[1][0], b[1][1],
                   vb + (uint32_t)((j * 16 * AT_LD + ntp * 16) * 2));
            MMA_F16(O[2*ntp],     a, b[0]);
            MMA_F16(O[2*ntp + 1], a, b[1]);
        }
    }

    const int qrow0 = qt * 64 + wq * 16 + g;
    __half* Ob0 = obase + (size_t)(w * KW + qrow0) * DM + h * DH;
    __half* Ob1 = Ob0 + (size_t)8 * DM;
    #pragma unroll
    for (int nt = 0; nt < 8; nt++) {
        int d = nt * 8 + tg * 2;
        *(__half2*)&Ob0[d] = __floats2half2_rn(O[nt][0] * inv0, O[nt][1] * inv0);
        *(__half2*)&Ob1[d] = __floats2half2_rn(O[nt][2] * inv1, O[nt][3] * inv1);
    }
}

// ================= persistent recurrence (fp16 MMA both phases) ======
constexpr int REC_NB   = 128;
constexpr int REC_SMEM = (32768 + 512) * (int)sizeof(float);   // 133120 B
constexpr int RH_BK  = 128;
constexpr int RH_LD  = RH_BK + 8;
constexpr int RH_BUF = (64 + 64) * RH_LD;

__device__ __forceinline__ void grid_bar(unsigned base, unsigned bar_id)
{
    __syncthreads();
    if (threadIdx.x == 0) {
        __threadfence();
        unsigned a = atomicAdd(&g_bar_arrive, 1u);
        if ((a & (REC_NB - 1u)) == (REC_NB - 1u)) {
            atomicAdd(&g_bar_release, 1u);
        } else {
            while (*(volatile unsigned*)&g_bar_release - base < bar_id) { }
        }
        __threadfence();
    }
    __syncthreads();
}

__global__ __launch_bounds__(256)
void recurrence_kernel(const __half* __restrict__ x16,
                       const __half* __restrict__ q2h,
                       const __half* __restrict__ wkv2h, const float* __restrict__ bkv2,
                       const __half* __restrict__ wkvh,  const float* __restrict__ bkvF,
                       __half* __restrict__ kvh, float* __restrict__ st,
                       __half* __restrict__ st16)
{
    extern __shared__ float sm[];
    __half* smh = (__half*)sm;
    const int tid = threadIdx.x;
    const int bid = blockIdx.x;

    __shared__ unsigned s_base;
    if (tid == 0) s_base = *(volatile unsigned*)&g_bar_release;
    __syncthreads();
    const unsigned base = s_base;

    if (bid == 0) {
        if (tid < 32)              g_flagA[tid]      = 0;
        else if (tid < 40)         g_flagB[tid - 32] = 0;
    }
    grid_bar(base, 1);

    const int lane = tid & 31, warp = tid >> 5;
    const int g = lane >> 2, tg = lane & 3;
    const int warp_m = (warp & 1) * 32;
    const int warp_n = (warp >> 1) * 16;
    const int tm = bid >> 5;
    const int tn = bid & 31;

    const int ar  = (lane & 7) + ((lane >> 3) & 1) * 8;
    const int ach = (lane >> 4) * 8;
    const int br  = (lane & 7) + (lane >> 4) * 8;
    const int bch = ((lane >> 3) & 1) * 8;

    const int h  = bid >> 3;
    const int qt = bid & 7;

    for (int i = 1; i < NWIN; i++) {
        __half* kvb      = kvh  + (size_t)(i & 1) * KW * 2 * ODIM;
        float*  stb      = st   + (size_t)(i & 1) * KW * ODIM;
        __half* st16b    = st16 + (size_t)(i & 1) * KW * ODIM;
        const __half* st16prev = st16 + (size_t)((i - 1) & 1) * KW * ODIM;

        // ===== Phase A: KV projection (fp16 MMA, BK=128 halfs) =====
        {
            if (i > 1 && tid == 0) {
                unsigned tgt = 16u * (unsigned)(i - 1);
                while (flag_acquire(&g_flagB[2*tm])     < tgt) { }
                while (flag_acquire(&g_flagB[2*tm + 1]) < tgt) { }
            }
            __syncthreads();

            const __half* A  = (i == 1) ? x16   : st16prev;
            const __half* W  = (i == 1) ? wkv2h : wkvh;
            const float*  bb = (i == 1) ? bkv2  : bkvF;

            float cacc[2][2][4];
            #pragma unroll
            for (int mt = 0; mt < 2; mt++)
                #pragma unroll
                for (int nt = 0; nt < 2; nt++)
                    #pragma unroll
                    for (int r = 0; r < 4; r++) cacc[mt][nt][r] = 0.f;

            const int crow = tid >> 2;
            const int cch  = (tid & 3) * 4;

            auto issue = [&](int t) {
                size_t ko = (size_t)t * RH_BK;
                __half* As = smh + (t % 3) * RH_BUF;
                __half* Bs = As + 64 * RH_LD;
                #pragma unroll
                for (int j = 0; j < 4; j++) {
                    int ch = cch + j;
                    CP_ASYNC16(smaddr(&As[crow * RH_LD + ch*8]), &A[(size_t)(tm*64 + crow) * 1024 + ko + ch*8]);
                    CP_ASYNC16(smaddr(&Bs[crow * RH_LD + ch*8]), &W[(size_t)(tn*64 + crow) * 1024 + ko + ch*8]);
                }
                CP_COMMIT();
            };

            issue(0);
            issue(1);
            for (int t = 0; t < 8; t++) {
                if (t == 7) { CP_WAIT0(); } else { CP_WAIT1(); }
                __syncthreads();
                if (t + 2 < 8) issue(t + 2);

                const __half* bufp = smh + (t % 3) * RH_BUF;
                const uint32_t a_base = smaddr(bufp + (warp_m + ar) * RH_LD + ach);
                const uint32_t b_base = smaddr(bufp + 64 * RH_LD + (warp_n + br) * RH_LD + bch);

                #pragma unroll
                for (int ks = 0; ks < 8; ks++) {
                    uint32_t a[2][4], b[2][2];
                    #pragma unroll
                    for (int mt = 0; mt < 2; mt++)
                        LDSM4(a[mt][0], a[mt][1], a[mt][2], a[mt][3],
                              a_base + (uint32_t)((mt * 16 * RH_LD + ks * 16) * 2));
                    LDSM4(b[0][0], b[0][1], b[1][0], b[1][1],
                          b_base + (uint32_t)((ks * 16) * 2));
                    #pragma unroll
                    for (int mt = 0; mt < 2; mt++)
                        #pragma unroll
                        for (int nt = 0; nt < 2; nt++)
                            MMA_F16(cacc[mt][nt], a[mt], b[nt]);
                }
            }

            #pragma unroll
            for (int mt = 0; mt < 2; mt++) {
                int row0 = tm*64 + warp_m + mt*16 + g;
                #pragma unroll
                for (int nt = 0; nt < 2; nt++) {
                    int col = tn*64 + warp_n + nt*8 + tg*2;
                    float2 bb2 = *(const float2*)&bb[col];
                    *(__half2*)&kvb[(size_t)row0 * 2048 + col] =
                        __floats2half2_rn(cacc[mt][nt][0] + bb2.x, cacc[mt][nt][1] + bb2.y);
                    *(__half2*)&kvb[(size_t)(row0 + 8) * 2048 + col] =
                        __floats2half2_rn(cacc[mt][nt][2] + bb2.x, cacc[mt][nt][3] + bb2.y);
                }
            }
            __syncthreads();
            if (tid == 0) flag_release(&g_flagA[tn]);
        }

        // ===== Phase B: attention (fp16 MMA, warps 0-1) =====
        {
            if (tid == 0) {
                unsigned tgt = 4u * (unsigned)i;
                while (flag_acquire(&g_flagA[h])      < tgt) { }
                while (flag_acquire(&g_flagA[16 + h]) < tgt) { }
            }
            __syncthreads();

            __half* Kh = smh;                  // 256 x 72
            __half* Vh = smh + 256 * AT_LD;    // 256 x 72
            __half* Qh = smh + 512 * AT_LD;    // 32 x 72

            const __half* Kp = kvb + h * DH;
            const __half* Vp = kvb + 1024 + h * DH;
            for (int idx = tid; idx < 256 * 8; idx += 256) {
                int r = idx >> 3, c = idx & 7;
                CP_ASYNC16(smaddr(Kh + r * AT_LD + c*8), Kp + (size_t)r * 2048 + c*8);
                CP_ASYNC16(smaddr(Vh + r * AT_LD + c*8), Vp + (size_t)r * 2048 + c*8);
            }
            const __half* Qp = q2h + (size_t)i * KW * ODIM + (size_t)(qt*32) * 1024 + h * DH;
            for (int idx = tid; idx < 32 * 8; idx += 256) {
                int r = idx >> 3, c = idx & 7;
                CP_ASYNC16(smaddr(Qh + r * AT_LD + c*8), Qp + (size_t)r * 1024 + c*8);
            }
            CP_COMMIT();
            CP_WAIT0();
            __syncthreads();

            if (warp < 2) {
                const int wq = warp;

                float S[32][4];
                #pragma unroll
                for (int j = 0; j < 32; j++)
                    #pragma unroll
                    for (int r = 0; r < 4; r++) S[j][r] = 0.f;

                const uint32_t qa = smaddr(Qh + (wq*16 + ar) * AT_LD + ach);
                const uint32_t kb = smaddr(Kh + br * AT_LD + bch);

                #pragma unroll
                for (int kd = 0; kd < 4; kd++) {
                    uint32_t a[4];
                    LDSM4(a[0], a[1], a[2], a[3], qa + (uint32_t)(kd * 16 * 2));
                    #pragma unroll
                    for (int nt2 = 0; nt2 < 16; nt2++) {
                        uint32_t b[2][2];
                        LDSM4(b[0][0], b[0][1], b[1][0], b[1][1],
                              kb + (uint32_t)((nt2 * 16 * AT_LD + kd * 16) * 2));
                        MMA_F16(S[2*nt2],     a, b[0]);
                        MMA_F16(S[2*nt2 + 1], a, b[1]);
                    }
                }

                float mx0 = -1e30f, mx1 = -1e30f;
                #pragma unroll
                for (int j = 0; j < 32; j++) {
                    mx0 = fmaxf(mx0, fmaxf(S[j][0], S[j][1]));
                    mx1 = fmaxf(mx1, fmaxf(S[j][2], S[j][3]));
                }
                mx0 = fmaxf(mx0, __shfl_xor_sync(0xffffffffu, mx0, 1));
                mx0 = fmaxf(mx0, __shfl_xor_sync(0xffffffffu, mx0, 2));
                mx1 = fmaxf(mx1, __shfl_xor_sync(0xffffffffu, mx1, 1));
                mx1 = fmaxf(mx1, __shfl_xor_sync(0xffffffffu, mx1, 2));

                float l0 = 0.f, l1 = 0.f;
                #pragma unroll
                for (int j = 0; j < 32; j++) {
                    float p0 = __expf((S[j][0] - mx0) * 0.125f);
                    float p1 = __expf((S[j][1] - mx0) * 0.125f);
                    float p2 = __expf((S[j][2] - mx1) * 0.125f);
                    float p3 = __expf((S[j][3] - mx1) * 0.125f);
                    S[j][0] = p0; S[j][1] = p1; S[j][2] = p2; S[j][3] = p3;
                    l0 += p0 + p1;
                    l1 += p2 + p3;
                }
                l0 += __shfl_xor_sync(0xffffffffu, l0, 1);
                l0 += __shfl_xor_sync(0xffffffffu, l0, 2);
                l1 += __shfl_xor_sync(0xffffffffu, l1, 1);
                l1 += __shfl_xor_sync(0xffffffffu, l1, 2);
                const float inv0 = 1.f / l0;
                const float inv1 = 1.f / l1;

                float O[8][4];
                #pragma unroll
                for (int n = 0; n < 8; n++)
                    #pragma unroll
                    for (int r = 0; r < 4; r++) O[n][r] = 0.f;

                const int vr = (lane & 7) + ((lane >> 3) & 1) * 8;
                const int vc = (lane >> 4) * 8;
                const uint32_t vb = smaddr(Vh + vr * AT_LD + vc);

                #pragma unroll
                for (int j = 0; j < 16; j++) {
                    uint32_t a[4];
                    a[0] = pkh2(S[2*j][0],     S[2*j][1]);
                    a[1] = pkh2(S[2*j][2],     S[2*j][3]);
                    a[2] = pkh2(S[2*j + 1][0], S[2*j + 1][1]);
                    a[3] = pkh2(S[2*j + 1][2], S[2*j + 1][3]);
                    #pragma unroll
                    for (int ntp = 0; ntp < 4; ntp++) {
                        uint32_t b[2][2];
                        LDSM4T(b[0][0], b[0][1], b[1][0], b[1][1],
                               vb + (uint32_t)((j * 16 * AT_LD + ntp * 16) * 2));
                        MMA_F16(O[2*ntp],     a, b[0]);
                        MMA_F16(O[2*ntp + 1], a, b[1]);
                    }
                }

                const int qrow0 = qt * 32 + wq * 16 + g;
                float*  S0 = stb   + (size_t)qrow0 * 1024 + h * DH;
                float*  S1 = S0 + (size_t)8 * 1024;
                __half* H0 = st16b + (size_t)qrow0 * 1024 + h * DH;
                __half* H1 = H0 + (size_t)8 * 1024;
                #pragma unroll
                for (int nt = 0; nt < 8; nt++) {
                    int d = nt * 8 + tg * 2;
                    float o00 = O[nt][0] * inv0, o01 = O[nt][1] * inv0;
                    float o10 = O[nt][2] * inv1, o11 = O[nt][3] * inv1;
                    *(float2*)&S0[d] = make_float2(o00, o01);
                    *(float2*)&S1[d] = make_float2(o10, o11);
                    *(__half2*)&H0[d] = __floats2half2_rn(o00, o01);
                    *(__half2*)&H1[d] = __floats2half2_rn(o10, o11);
                }
            }
            __syncthreads();
            if (tid == 0) flag_release(&g_flagB[qt]);
        }
    }
}

// ---------------- host ----------------
extern "C" void kernel_launch(void* const* d_in, const int* in_sizes, int n_in,
                              void* d_out, int out_size)
{
    const float* path   = (const float*)d_in[0];
    const float* w_in1  = (const float*)d_in[1];
    const float* b_in1  = (const float*)d_in[2];
    const float* w_out1 = (const float*)d_in[3];
    const float* b_out1 = (const float*)d_in[4];
    const float* w_lin  = (const float*)d_in[5];
    const float* b_lin  = (const float*)d_in[6];
    const float* w_in2  = (const float*)d_in[7];
    const float* b_in2  = (const float*)d_in[8];
    const float* w_out2 = (const float*)d_in[9];
    const float* b_out2 = (const float*)d_in[10];

    float *st, *bcomb, *bkv, *zb;
    __half *qkv1h, *pathh, *win1h, *attn1h, *x16, *q2h, *kvh, *wcomb16, *win2q16,
           *wkvh, *wkv2h, *st16, *wt16, *wt2h, *wlinh;
    cudaGetSymbolAddress((void**)&qkv1h,   g_qkv1h);
    cudaGetSymbolAddress((void**)&pathh,   g_pathh);
    cudaGetSymbolAddress((void**)&win1h,   g_win1h);
    cudaGetSymbolAddress((void**)&attn1h,  g_attn1h);
    cudaGetSymbolAddress((void**)&x16,     g_x16);
    cudaGetSymbolAddress((void**)&q2h,     g_q2h);
    cudaGetSymbolAddress((void**)&kvh,     g_kvh);
    cudaGetSymbolAddress((void**)&st,      g_st);
    cudaGetSymbolAddress((void**)&st16,    g_st16);
    cudaGetSymbolAddress((void**)&wt16,    g_wt16);
    cudaGetSymbolAddress((void**)&wt2h,    g_wt2h);
    cudaGetSymbolAddress((void**)&wlinh,   g_wlinh);
    cudaGetSymbolAddress((void**)&wcomb16, g_wcomb16);
    cudaGetSymbolAddress((void**)&win2q16, g_win2q16);
    cudaGetSymbolAddress((void**)&bcomb,   g_bcomb);
    cudaGetSymbolAddress((void**)&wkvh,    g_wkvh);
    cudaGetSymbolAddress((void**)&wkv2h,   g_wkv2h);
    cudaGetSymbolAddress((void**)&bkv,     g_bkv);
    cudaGetSymbolAddress((void**)&zb,      g_zb);

    cudaFuncSetAttribute(attn2_kernel,       cudaFuncAttributeMaxDynamicSharedMemorySize, AT_SMEM);
    cudaFuncSetAttribute(gemm_fp16<false>,   cudaFuncAttributeMaxDynamicSharedMemorySize, H_SMEM);
    cudaFuncSetAttribute(gemm_fp16<true>,    cudaFuncAttributeMaxDynamicSharedMemorySize, H_SMEM);
    cudaFuncSetAttribute(recurrence_kernel,  cudaFuncAttributeMaxDynamicSharedMemorySize, REC_SMEM);
    cudaFuncSetAttribute(attn2_kernel,       cudaFuncAttributePreferredSharedMemoryCarveout, 100);
    cudaFuncSetAttribute(gemm_fp16<false>,   cudaFuncAttributePreferredSharedMemoryCarveout, 100);
    cudaFuncSetAttribute(gemm_fp16<true>,    cudaFuncAttributePreferredSharedMemoryCarveout, 100);

    auto g64  = gemm_bias<64,64,16,4,4>;
    auto h16  = gemm_fp16<false>;
    auto h16r = gemm_fp16<true>;

    const float* wkv2 = w_in2 + (size_t)ODIM * ODIM;
    const float* bkv2 = b_in2 + ODIM;

    // 0: prologue prep (fp16 transposes + zb + bias folds)
    prep_kernel<<<2052 + 128 + 256, 256>>>(w_out1, w_out2, w_lin, b_out1, b_lin,
                                           wkv2, b_out2, bkv2, wt16, wt2h, zb, bcomb, bkv);
    // 1: f32->f16 converts (pathh, win1h, win2q16, wkv2h, wlinh)
    cvt_all<<<11264, 256>>>(path, w_in1, w_in2, wkv2, w_lin,
                            pathh, win1h, win2q16, wkv2h, wlinh);

    // 2-3: weight folds (fp16 MMA, fp16 out; fp32 C skipped)
    h16<<<dim3(DM/128, DM/128), 256, H_SMEM>>>(wlinh, wt16, zb, ((float*)0), wcomb16, DM, DM, DM);
    h16<<<dim3(DM/128, 2*ODIM/128), 256, H_SMEM>>>(wkv2h, wt2h, zb, ((float*)0), wkvh, 2*ODIM, DM, DM);

    // 4: stage 1 QKV (fp16 MMA; fp32 C skipped)
    h16<<<dim3(3*DM/128, SEQ/128), 256, H_SMEM>>>(pathh, win1h, b_in1, ((float*)0), qkv1h, SEQ, 3*DM, DM);

    // 5: stage 2 window self-attention (fp16 MMA)
    attn2_kernel<<<dim3(NH, KW/64, NWIN), 128, AT_SMEM>>>(qkv1h, attn1h, 0.125f);

    // 6: stage 3 fused outproj1 + linear + relu (fp16 MMA; fp32 C skipped)
    h16r<<<dim3(ODIM/128, ROWS/128), 256, H_SMEM>>>(attn1h, wcomb16, bcomb, ((float*)0), x16, ROWS, ODIM, DM);

    // 7: stage 4a bulk Q2 projections (fp16 MMA; fp32 C skipped)
    h16<<<dim3(ODIM/128, ROWS/128), 256, H_SMEM>>>(x16, win2q16, b_in2, ((float*)0), q2h, ROWS, ODIM, ODIM);

    // 8: persistent recurrence (fp16 MMA phases A and B)
    recurrence_kernel<<<REC_NB, 256, REC_SMEM>>>(x16, q2h, wkv2h, bkv2, wkvh, bkv, kvh, st, st16);

    // 9: final out-projection (exact fp32 -> d_out)
    g64<<<dim3(ODIM/64, KW/64), 256>>>(st + (size_t)((NWIN-1)&1) * KW * ODIM,
                                       w_out2, b_out2, (float*)d_out, KW, ODIM, ODIM);
}